// round 4
// baseline (speedup 1.0000x reference)
#include <cuda_runtime.h>
#include <cstdint>
#include <math.h>

#define S 2048
#define H 2048
#define NH 16
#define D 128
#define NE 8
#define TOPK 4
#define IE 1408
#define IS 5632

// ---------------- scratch ----------------
static __device__ float g_h1[S * H];
static __device__ float g_q[S * H];
static __device__ float g_k[S * H];
static __device__ float g_v[S * H];
static __device__ float g_sc[(long long)NH * S * S];
static __device__ float g_at[S * H];
static __device__ float g_x2[S * H];
static __device__ float g_h2[S * H];
static __device__ float g_w[NE * S];
static __device__ float g_gb[(long long)NE * S * IE];
static __device__ float g_ub[(long long)NE * S * IE];
static __device__ float g_eo[(long long)NE * S * H];
static __device__ float g_sgb[(long long)S * IS];
static __device__ float g_sub[(long long)S * IS];
static __device__ float g_sm[S * H];
static __device__ float g_sgl[S];
static __device__ float g_rl[S * NE];

// ---------------- helpers ----------------
__device__ __forceinline__ uint32_t smem_u32(const void* p) {
    uint32_t a;
    asm("{ .reg .u64 t; cvta.to.shared.u64 t, %1; cvt.u32.u64 %0, t; }" : "=r"(a) : "l"(p));
    return a;
}
__device__ __forceinline__ uint32_t rna_tf32_u(float x) {
    uint32_t u;
    asm("cvt.rna.tf32.f32 %0, %1;" : "=r"(u) : "f"(x));
    return u;
}
__device__ __forceinline__ float rna_tf32_f(float x) {
    return __uint_as_float(rna_tf32_u(x));
}
__device__ __forceinline__ void cp16(uint32_t dst, const void* src) {
    asm volatile("cp.async.cg.shared.global [%0], [%1], 16;" :: "r"(dst), "l"(src));
}
#define CP_COMMIT() asm volatile("cp.async.commit_group;" ::: "memory")
#define CP_WAIT2() asm volatile("cp.async.wait_group 2;" ::: "memory")
#define CP_WAIT0() asm volatile("cp.async.wait_group 0;" ::: "memory")

__device__ __forceinline__ void mma_tf32(float* d, const uint32_t* a, const uint32_t* b) {
    asm volatile(
        "mma.sync.aligned.m16n8k8.row.col.f32.tf32.tf32.f32 "
        "{%0,%1,%2,%3}, {%4,%5,%6,%7}, {%8,%9}, {%0,%1,%2,%3};"
        : "+f"(d[0]), "+f"(d[1]), "+f"(d[2]), "+f"(d[3])
        : "r"(a[0]), "r"(a[1]), "r"(a[2]), "r"(a[3]), "r"(b[0]), "r"(b[1]));
}

// ---------------- tf32 mma.sync GEMM, CTA tile 256x128, 8 warps of 64x64 ----------------
// C[M,N] = A[M,K] @ B (+ epilogue). A rows = tokens (M multiple of 256).
// TB=false: B is [K][N] (ldb). TB=true: B is [N][K] (ldb), computes A@B^T.
// EPI: 0 none, 1 +bias[col], 2 +resid[row][col]. RNA: round outputs to tf32.
// CMODE: 0 none, 1 causal tile skip (scores), 2 causal K-trim (PV).
// A fragments are used raw (producers pre-round to tf32); B fragments cvt in-loop.
#define ASTG 5120          // 256*20 floats per A stage
#define BSTG_NT 2560       // 128*20
#define BSTG_NN 2176       // 16*136
#define PADA 20
#define PADB 136

template <bool TB, int EPI, int CMODE, bool RNA>
__global__ void __launch_bounds__(256, 1)
mma_gemm(const float* __restrict__ A, const float* __restrict__ B,
         float* __restrict__ C, const float* __restrict__ X,
         int K, int lda, int ldb, int ldc,
         long long sA, long long sB, long long sC) {
    if (CMODE == 1 && (int)blockIdx.x > 2 * (int)blockIdx.y + 1) return;
    extern __shared__ float smem[];
    constexpr int BSTG = TB ? BSTG_NT : BSTG_NN;
    float* const AS = smem;                 // 3 stages
    float* const BS = smem + 3 * ASTG;      // 3 stages

    int tid = threadIdx.x, lane = tid & 31, wid = tid >> 5;
    int row0 = blockIdx.y * 256, col0 = blockIdx.x * 128;

    A += (long long)blockIdx.z * sA + (long long)row0 * lda;
    B += (long long)blockIdx.z * sB + (TB ? (long long)col0 * ldb : (long long)col0);
    C += (long long)blockIdx.z * sC;

    int nstg = K >> 4;
    if (CMODE == 2) { int lim = (blockIdx.y + 1) * 16; if (lim < nstg) nstg = lim; }

    // fill mappings
    int ar = tid >> 2, ac = (tid & 3) * 4;      // A: 1024 16B chunks, 4/thread
    int nr = tid >> 5, nc = (tid & 31) * 4;     // B-NN: 512 chunks, 2/thread

    auto fillA = [&](int s, int k0) {
        float* dst = AS + s * ASTG;
#pragma unroll
        for (int i = 0; i < 4; i++) {
            int r = ar + i * 64;
            cp16(smem_u32(dst + r * PADA + ac), A + (long long)r * lda + k0 + ac);
        }
    };
    auto fillB = [&](int s, int k0) {
        float* dst = BS + s * BSTG;
        if (TB) {
#pragma unroll
            for (int i = 0; i < 2; i++) {
                int r = ar + i * 64;
                cp16(smem_u32(dst + r * PADA + ac), B + (long long)r * ldb + k0 + ac);
            }
        } else {
#pragma unroll
            for (int i = 0; i < 2; i++) {
                int r = nr + i * 8;
                cp16(smem_u32(dst + r * PADB + nc), B + (long long)(k0 + r) * ldb + nc);
            }
        }
    };

    float acc[4][8][4];
#pragma unroll
    for (int i = 0; i < 4; i++)
#pragma unroll
        for (int j = 0; j < 8; j++)
#pragma unroll
            for (int u = 0; u < 4; u++) acc[i][j][u] = 0.f;

    int wm = (wid >> 1) * 64, wn = (wid & 1) * 64;
    int fr = lane >> 2, fc = lane & 3;

    fillA(0, 0); fillB(0, 0); CP_COMMIT();
    fillA(1, 16); fillB(1, 16); CP_COMMIT();

    for (int t = 0; t < nstg; t++) {
        if (t + 2 < nstg) {
            int s = (t + 2) % 3;
            fillA(s, (t + 2) * 16); fillB(s, (t + 2) * 16); CP_COMMIT();
            CP_WAIT2();
        } else {
            CP_WAIT0();
        }
        __syncthreads();
        int buf = t % 3;
        const float* as = AS + buf * ASTG;
        const float* bs = BS + buf * BSTG;
#pragma unroll
        for (int kk = 0; kk < 16; kk += 8) {
            uint32_t af[4][4];
#pragma unroll
            for (int mt = 0; mt < 4; mt++) {
                const uint32_t* ap =
                    (const uint32_t*)(as + (wm + mt * 16 + fr) * PADA + kk + fc);
                af[mt][0] = ap[0];
                af[mt][1] = ap[8 * PADA];
                af[mt][2] = ap[4];
                af[mt][3] = ap[8 * PADA + 4];
            }
            uint32_t bf[8][2];
#pragma unroll
            for (int nt = 0; nt < 8; nt++) {
                if (TB) {
                    const float* bp = bs + (wn + nt * 8 + fr) * PADA + kk + fc;
                    bf[nt][0] = rna_tf32_u(bp[0]);
                    bf[nt][1] = rna_tf32_u(bp[4]);
                } else {
                    const float* bp = bs + (kk + fc) * PADB + wn + nt * 8 + fr;
                    bf[nt][0] = rna_tf32_u(bp[0]);
                    bf[nt][1] = rna_tf32_u(bp[4 * PADB]);
                }
            }
#pragma unroll
            for (int mt = 0; mt < 4; mt++)
#pragma unroll
                for (int nt = 0; nt < 8; nt++) mma_tf32(acc[mt][nt], af[mt], bf[nt]);
        }
        __syncthreads();
    }

    // epilogue
#pragma unroll
    for (int mt = 0; mt < 4; mt++) {
        int m = row0 + wm + mt * 16 + fr;
#pragma unroll
        for (int nt = 0; nt < 8; nt++) {
            int n = col0 + wn + nt * 8 + fc * 2;
            float2 v0 = make_float2(acc[mt][nt][0], acc[mt][nt][1]);
            float2 v1 = make_float2(acc[mt][nt][2], acc[mt][nt][3]);
            if (EPI == 1) {
                v0.x += X[n]; v0.y += X[n + 1];
                v1.x += X[n]; v1.y += X[n + 1];
            }
            if (EPI == 2) {
                const float2 r0 = *(const float2*)&X[(long long)m * ldc + n];
                const float2 r1 = *(const float2*)&X[(long long)(m + 8) * ldc + n];
                v0.x += r0.x; v0.y += r0.y;
                v1.x += r1.x; v1.y += r1.y;
            }
            if (RNA) {
                v0.x = rna_tf32_f(v0.x); v0.y = rna_tf32_f(v0.y);
                v1.x = rna_tf32_f(v1.x); v1.y = rna_tf32_f(v1.y);
            }
            *(float2*)&C[(long long)m * ldc + n] = v0;
            *(float2*)&C[(long long)(m + 8) * ldc + n] = v1;
        }
    }
}

#define SMEM_NT ((3 * ASTG + 3 * BSTG_NT) * 4)
#define SMEM_NN ((3 * ASTG + 3 * BSTG_NN) * 4)

// ---------------- RMSNorm (tf32-rounded output) ----------------
__global__ void rmsnorm_kernel(const float* __restrict__ x, const float* __restrict__ w,
                               float* __restrict__ o) {
    int s = blockIdx.x;
    const float* xr = x + (long long)s * H;
    float* orow = o + (long long)s * H;
    int tid = threadIdx.x;
    float ss = 0.f;
    for (int i = tid; i < H; i += 256) { float v = xr[i]; ss += v * v; }
    __shared__ float sh[8];
#pragma unroll
    for (int off = 16; off; off >>= 1) ss += __shfl_xor_sync(0xffffffffu, ss, off);
    if ((tid & 31) == 0) sh[tid >> 5] = ss;
    __syncthreads();
    ss = sh[tid & 7];
#pragma unroll
    for (int off = 4; off; off >>= 1) ss += __shfl_xor_sync(0xffffffffu, ss, off);
    float inv = rsqrtf(ss / (float)H + 1e-6f);
    for (int i = tid; i < H; i += 256) orow[i] = rna_tf32_f(w[i] * xr[i] * inv);
}

// ---------------- RoPE (tf32-rounded) ----------------
__global__ void rope_kernel(float* __restrict__ q, float* __restrict__ k) {
    int s = blockIdx.x, h = blockIdx.y, d = threadIdx.x;  // d in [0,64)
    double invd = exp(-((double)(2 * d) / 128.0) * 13.815510557964274);
    float inv = (float)invd;
    float ang = (float)s * inv;
    float c = cosf(ang), sn = sinf(ang);
    long long base = ((long long)s * NH + h) * D;
    float q1 = q[base + d], q2 = q[base + d + 64];
    q[base + d] = rna_tf32_f(q1 * c - q2 * sn);
    q[base + d + 64] = rna_tf32_f(q2 * c + q1 * sn);
    float k1 = k[base + d], k2 = k[base + d + 64];
    k[base + d] = rna_tf32_f(k1 * c - k2 * sn);
    k[base + d + 64] = rna_tf32_f(k2 * c + k1 * sn);
}

// ---------------- causal softmax (tf32-rounded probs) ----------------
__global__ void softmax_causal_kernel(float* __restrict__ sc) {
    long long row = blockIdx.x;
    int q = (int)(row & (S - 1));
    float* p = sc + row * S;
    int n = q + 1;
    int tid = threadIdx.x;
    __shared__ float sh[8];
    const float scale = 0.08838834764831845f;
    float mx = -3.4e38f;
    for (int i = tid; i < n; i += 256) mx = fmaxf(mx, p[i]);
#pragma unroll
    for (int o = 16; o; o >>= 1) mx = fmaxf(mx, __shfl_xor_sync(0xffffffffu, mx, o));
    if ((tid & 31) == 0) sh[tid >> 5] = mx;
    __syncthreads();
    mx = sh[tid & 7];
#pragma unroll
    for (int o = 4; o; o >>= 1) mx = fmaxf(mx, __shfl_xor_sync(0xffffffffu, mx, o));
    __syncthreads();
    float sum = 0.f;
    for (int i = tid; i < n; i += 256) {
        float e = expf((p[i] - mx) * scale);
        p[i] = e;
        sum += e;
    }
#pragma unroll
    for (int o = 16; o; o >>= 1) sum += __shfl_xor_sync(0xffffffffu, sum, o);
    if ((tid & 31) == 0) sh[tid >> 5] = sum;
    __syncthreads();
    sum = sh[tid & 7];
#pragma unroll
    for (int o = 4; o; o >>= 1) sum += __shfl_xor_sync(0xffffffffu, sum, o);
    float inv = 1.f / sum;
    for (int i = tid; i < S; i += 256) p[i] = (i < n) ? rna_tf32_f(p[i] * inv) : 0.f;
}

// ---------------- router ----------------
__global__ void router_kernel(const float* __restrict__ h2, const float* __restrict__ gw,
                              const float* __restrict__ sgate, float* __restrict__ rl,
                              float* __restrict__ wexp, float* __restrict__ sgl) {
    int s = blockIdx.x;
    int tid = threadIdx.x;
    const float* hr = h2 + (long long)s * H;
    float acc[9];
#pragma unroll
    for (int j = 0; j < 9; j++) acc[j] = 0.f;
    for (int i = tid; i < H; i += 256) {
        float hv = hr[i];
        const float* gr = gw + (long long)i * NE;
#pragma unroll
        for (int e = 0; e < NE; e++) acc[e] += hv * gr[e];
        acc[8] += hv * sgate[i];
    }
    __shared__ float sh[8][9];
    int warp = tid >> 5, lane = tid & 31;
#pragma unroll
    for (int j = 0; j < 9; j++) {
        float v = acc[j];
#pragma unroll
        for (int o = 16; o; o >>= 1) v += __shfl_xor_sync(0xffffffffu, v, o);
        if (lane == 0) sh[warp][j] = v;
    }
    __syncthreads();
    if (tid == 0) {
        float t[9];
#pragma unroll
        for (int j = 0; j < 9; j++) {
            float v = 0.f;
            for (int wi = 0; wi < 8; wi++) v += sh[wi][j];
            t[j] = v;
        }
        float mx = t[0];
        for (int e = 1; e < NE; e++) mx = fmaxf(mx, t[e]);
        float p[NE], sum = 0.f;
        for (int e = 0; e < NE; e++) { p[e] = expf(t[e] - mx); sum += p[e]; }
        for (int e = 0; e < NE; e++) p[e] /= sum;
        float w8[NE];
        for (int e = 0; e < NE; e++) w8[e] = 0.f;
        for (int tI = 0; tI < TOPK; tI++) {
            int bi = 0;
            float bv = p[0];
            for (int e = 1; e < NE; e++)
                if (p[e] > bv) { bv = p[e]; bi = e; }
            w8[bi] = bv;
            p[bi] = -1.f;
        }
        for (int e = 0; e < NE; e++) {
            wexp[e * S + s] = w8[e];
            rl[s * NE + e] = t[e];
        }
        sgl[s] = t[8];
    }
}

// ---------------- silu(g)*u (tf32-rounded) ----------------
__global__ void silumul_kernel(const float* __restrict__ g, const float* __restrict__ u,
                               float* __restrict__ o, long long n) {
    long long i = (long long)blockIdx.x * 256 + threadIdx.x;
    if (i < n) {
        float x = g[i];
        o[i] = rna_tf32_f((x / (1.f + expf(-x))) * u[i]);
    }
}

// ---------------- final combine ----------------
__global__ void final_kernel(const float* __restrict__ x2, const float* __restrict__ eo,
                             const float* __restrict__ wexp, const float* __restrict__ sm,
                             const float* __restrict__ sgl, float* __restrict__ out) {
    int i = blockIdx.x * 256 + threadIdx.x;
    int s = i >> 11;
    float mo = 0.f;
#pragma unroll
    for (int e = 0; e < NE; e++) mo += wexp[e * S + s] * eo[(long long)e * S * H + i];
    float gg = 1.f / (1.f + expf(-sgl[s]));
    out[i] = x2[i] + mo + gg * sm[i];
}

// ---------------- host ----------------
extern "C" void kernel_launch(void* const* d_in, const int* in_sizes, int n_in,
                              void* d_out, int out_size) {
    const float* x = (const float*)d_in[0];
    const float* ln1 = (const float*)d_in[1];
    const float* ln2 = (const float*)d_in[2];
    const float* wq = (const float*)d_in[3];
    const float* bq = (const float*)d_in[4];
    const float* wk = (const float*)d_in[5];
    const float* bk = (const float*)d_in[6];
    const float* wv = (const float*)d_in[7];
    const float* bv = (const float*)d_in[8];
    const float* wo = (const float*)d_in[9];
    const float* gw = (const float*)d_in[10];
    const float* eg = (const float*)d_in[11];
    const float* eu = (const float*)d_in[12];
    const float* ed = (const float*)d_in[13];
    const float* sg = (const float*)d_in[14];
    const float* su = (const float*)d_in[15];
    const float* sd = (const float*)d_in[16];
    const float* sgate = (const float*)d_in[17];
    float* out = (float*)d_out;

    float *h1, *q, *k, *v, *sc, *at, *x2, *h2, *wexp, *gb, *ub, *eo, *sgb, *sub, *sm, *sgl, *rls;
    cudaGetSymbolAddress((void**)&h1, g_h1);
    cudaGetSymbolAddress((void**)&q, g_q);
    cudaGetSymbolAddress((void**)&k, g_k);
    cudaGetSymbolAddress((void**)&v, g_v);
    cudaGetSymbolAddress((void**)&sc, g_sc);
    cudaGetSymbolAddress((void**)&at, g_at);
    cudaGetSymbolAddress((void**)&x2, g_x2);
    cudaGetSymbolAddress((void**)&h2, g_h2);
    cudaGetSymbolAddress((void**)&wexp, g_w);
    cudaGetSymbolAddress((void**)&gb, g_gb);
    cudaGetSymbolAddress((void**)&ub, g_ub);
    cudaGetSymbolAddress((void**)&eo, g_eo);
    cudaGetSymbolAddress((void**)&sgb, g_sgb);
    cudaGetSymbolAddress((void**)&sub, g_sub);
    cudaGetSymbolAddress((void**)&sm, g_sm);
    cudaGetSymbolAddress((void**)&sgl, g_sgl);
    cudaGetSymbolAddress((void**)&rls, g_rl);

    cudaFuncSetAttribute(mma_gemm<false, 1, 0, false>, cudaFuncAttributeMaxDynamicSharedMemorySize, SMEM_NN);
    cudaFuncSetAttribute(mma_gemm<false, 1, 0, true>, cudaFuncAttributeMaxDynamicSharedMemorySize, SMEM_NN);
    cudaFuncSetAttribute(mma_gemm<true, 0, 1, false>, cudaFuncAttributeMaxDynamicSharedMemorySize, SMEM_NT);
    cudaFuncSetAttribute(mma_gemm<false, 0, 2, true>, cudaFuncAttributeMaxDynamicSharedMemorySize, SMEM_NN);
    cudaFuncSetAttribute(mma_gemm<false, 2, 0, false>, cudaFuncAttributeMaxDynamicSharedMemorySize, SMEM_NN);
    cudaFuncSetAttribute(mma_gemm<false, 0, 0, false>, cudaFuncAttributeMaxDynamicSharedMemorySize, SMEM_NN);

    float* rl_dst = (out_size >= S * H + S * NE) ? (out + (size_t)S * H) : rls;

    // 1) h1 = rmsnorm(x, ln1)   [tf32-rounded]
    rmsnorm_kernel<<<S, 256>>>(x, ln1, h1);

    // 2) q,k,v = h1 @ w + b
    {
        dim3 g(16, 8, 1);
        mma_gemm<false, 1, 0, false><<<g, 256, SMEM_NN>>>(h1, wq, q, bq, H, H, H, H, 0, 0, 0);
        mma_gemm<false, 1, 0, false><<<g, 256, SMEM_NN>>>(h1, wk, k, bk, H, H, H, H, 0, 0, 0);
        mma_gemm<false, 1, 0, true><<<g, 256, SMEM_NN>>>(h1, wv, v, bv, H, H, H, H, 0, 0, 0);
    }

    // 3) RoPE [rounds q,k]
    rope_kernel<<<dim3(S, NH), 64>>>(q, k);

    // 4) scores[h] = q_h @ k_h^T  (NT, causal tile skip)
    mma_gemm<true, 0, 1, false><<<dim3(16, 8, NH), 256, SMEM_NT>>>(
        q, k, sc, (const float*)0, D, H, H, S,
        (long long)D, (long long)D, (long long)S * S);

    // 5) softmax [rounds probs]
    softmax_causal_kernel<<<NH * S, 256>>>(sc);

    // 6) at[h] = probs_h @ v_h  (NN, causal K-trim, rounded output)
    mma_gemm<false, 0, 2, true><<<dim3(1, 8, NH), 256, SMEM_NN>>>(
        sc, v, at, (const float*)0, S, S, H, H,
        (long long)S * S, (long long)D, (long long)D);

    // 7) x2 = x + at @ wo
    mma_gemm<false, 2, 0, false><<<dim3(16, 8, 1), 256, SMEM_NN>>>(at, wo, x2, x, H, H, H, H, 0, 0, 0);

    // 8) h2 = rmsnorm(x2, ln2)  [rounded]
    rmsnorm_kernel<<<S, 256>>>(x2, ln2, h2);

    // 9) router
    router_kernel<<<S, 256>>>(h2, gw, sgate, rl_dst, wexp, sgl);

    // 10) dense MoE
    {
        dim3 g(IE / 128, 8, NE);
        mma_gemm<false, 0, 0, false><<<g, 256, SMEM_NN>>>(h2, eg, gb, (const float*)0,
            H, H, IE, IE, 0LL, (long long)H * IE, (long long)S * IE);
        mma_gemm<false, 0, 0, false><<<g, 256, SMEM_NN>>>(h2, eu, ub, (const float*)0,
            H, H, IE, IE, 0LL, (long long)H * IE, (long long)S * IE);
    }
    {
        long long n = (long long)NE * S * IE;
        silumul_kernel<<<(unsigned)((n + 255) / 256), 256>>>(gb, ub, gb, n);
    }
    mma_gemm<false, 0, 0, false><<<dim3(16, 8, NE), 256, SMEM_NN>>>(gb, ed, eo, (const float*)0,
        IE, IE, H, H, (long long)S * IE, (long long)IE * H, (long long)S * H);

    // 11) shared MLP
    {
        dim3 g(IS / 128, 8, 1);
        mma_gemm<false, 0, 0, false><<<g, 256, SMEM_NN>>>(h2, sg, sgb, (const float*)0, H, H, IS, IS, 0, 0, 0);
        mma_gemm<false, 0, 0, false><<<g, 256, SMEM_NN>>>(h2, su, sub, (const float*)0, H, H, IS, IS, 0, 0, 0);
    }
    {
        long long n = (long long)S * IS;
        silumul_kernel<<<(unsigned)((n + 255) / 256), 256>>>(sgb, sub, sgb, n);
    }
    mma_gemm<false, 0, 0, false><<<dim3(16, 8, 1), 256, SMEM_NN>>>(sgb, sd, sm, (const float*)0,
        IS, IS, H, H, 0, 0, 0);

    // 12) combine
    final_kernel<<<(S * H) / 256, 256>>>(x2, eo, wexp, sm, sgl, out);
}

// round 5
// speedup vs baseline: 1.3111x; 1.3111x over previous
#include <cuda_runtime.h>
#include <cstdint>
#include <math.h>

#define S 2048
#define H 2048
#define NH 16
#define D 128
#define NE 8
#define TOPK 4
#define IE 1408
#define IS 5632

// ---------------- scratch ----------------
static __device__ float g_h1[S * H];
static __device__ float g_q[S * H];
static __device__ float g_k[S * H];
static __device__ float g_v[S * H];
static __device__ float g_sc[(long long)NH * S * S];
static __device__ float g_at[S * H];
static __device__ float g_x2[S * H];
static __device__ float g_h2[S * H];
static __device__ float g_gb[(long long)NE * S * IE];
static __device__ float g_ub[(long long)NE * S * IE];
static __device__ float g_eo[(long long)NE * S * H];
static __device__ float g_sgb[(long long)S * IS];
static __device__ float g_sub[(long long)S * IS];
static __device__ float g_sm[S * H];
static __device__ float g_sgl[S];
static __device__ float g_rl[S * NE];
static __device__ int g_cnt[NE];
static __device__ int g_glist[NE * S];
static __device__ int g_slot[S * TOPK];
static __device__ float g_wt4[S * TOPK];

// ---------------- helpers ----------------
__device__ __forceinline__ uint32_t smem_u32(const void* p) {
    uint32_t a;
    asm("{ .reg .u64 t; cvta.to.shared.u64 t, %1; cvt.u32.u64 %0, t; }" : "=r"(a) : "l"(p));
    return a;
}
__device__ __forceinline__ uint32_t rna_tf32_u(float x) {
    uint32_t u;
    asm("cvt.rna.tf32.f32 %0, %1;" : "=r"(u) : "f"(x));
    return u;
}
__device__ __forceinline__ float rna_tf32_f(float x) {
    return __uint_as_float(rna_tf32_u(x));
}
__device__ __forceinline__ void cp16(uint32_t dst, const void* src) {
    asm volatile("cp.async.cg.shared.global [%0], [%1], 16;" :: "r"(dst), "l"(src));
}
#define CP_COMMIT() asm volatile("cp.async.commit_group;" ::: "memory")
#define CP_WAIT1() asm volatile("cp.async.wait_group 1;" ::: "memory")
#define CP_WAIT0() asm volatile("cp.async.wait_group 0;" ::: "memory")

__device__ __forceinline__ void mma_tf32(float* d, const uint32_t* a, const uint32_t* b) {
    asm volatile(
        "mma.sync.aligned.m16n8k8.row.col.f32.tf32.tf32.f32 "
        "{%0,%1,%2,%3}, {%4,%5,%6,%7}, {%8,%9}, {%0,%1,%2,%3};"
        : "+f"(d[0]), "+f"(d[1]), "+f"(d[2]), "+f"(d[3])
        : "r"(a[0]), "r"(a[1]), "r"(a[2]), "r"(a[3]), "r"(b[0]), "r"(b[1]));
}

// ---------------- tf32 mma.sync GEMM (128x128 CTA, 8 warps 64x32) ----------------
// C[M,N] = A[M,K] @ B (+ epilogue). A fragments raw (producers pre-round to tf32).
// TB: B is [N][K] (A@B^T) else [K][N].
// EPI: 0 none, 1 +bias[col], 2 +resid. RNA: round output to tf32.
// CMODE: 0 none, 1 causal tile skip, 2 causal K-trim.
// IDX: 0 none, 1 gather A rows via glist + bound cnt[z], 2 bound cnt[z] only.
template <bool TB, int EPI, int CMODE, bool RNA, int IDX>
__global__ void __launch_bounds__(256, 2)
mma_gemm(const float* __restrict__ A, const float* __restrict__ B,
         float* __restrict__ C, const float* __restrict__ X,
         const int* __restrict__ glist, const int* __restrict__ cnt,
         int K, int lda, int ldb, int ldc,
         long long sA, long long sB, long long sC) {
    if (CMODE == 1 && blockIdx.x > blockIdx.y) return;
    int cbound = 0x7fffffff;
    if (IDX) {
        cbound = cnt[blockIdx.z];
        if ((int)blockIdx.y * 128 >= cbound) return;
    }

    constexpr int BROWS = TB ? 128 : 16;
    constexpr int BCOLS = TB ? 20 : 132;
    __shared__ __align__(16) float As[2][128][20];
    __shared__ __align__(16) float Bs[2][BROWS][BCOLS];

    int tid = threadIdx.x, lane = tid & 31, wid = tid >> 5;
    int row0 = blockIdx.y * 128, col0 = blockIdx.x * 128;

    A += (long long)blockIdx.z * sA;
    if (IDX != 1) A += (long long)row0 * lda;
    B += (long long)blockIdx.z * sB + (TB ? (long long)col0 * ldb : (long long)col0);
    C += (long long)blockIdx.z * sC;

    int nstg = K >> 4;
    if (CMODE == 2) { int lim = (blockIdx.y + 1) * 8; if (lim < nstg) nstg = lim; }

    int arow = tid >> 2, acol = (tid & 3) * 4;
    int brow = tid >> 5, bcol = (tid & 31) * 4;

    // per-thread A row pointers (constant over K)
    const float* aptr[2];
#pragma unroll
    for (int i = 0; i < 2; i++) {
        int r = arow + i * 64;
        if (IDX == 1) {
            int gr = row0 + r;
            int ti = glist[blockIdx.z * S + (gr < cbound ? gr : 0)];
            aptr[i] = A + (long long)ti * lda;
        } else {
            aptr[i] = A + (long long)r * lda;
        }
    }

    auto loadA = [&](int buf, int k0) {
#pragma unroll
        for (int i = 0; i < 2; i++) {
            int r = arow + i * 64;
            cp16(smem_u32(&As[buf][r][acol]), aptr[i] + k0 + acol);
        }
    };
    auto loadB = [&](int buf, int k0) {
        if (TB) {
#pragma unroll
            for (int i = 0; i < 2; i++) {
                int r = arow + i * 64;
                cp16(smem_u32(&Bs[buf][r][acol]), B + (long long)r * ldb + k0 + acol);
            }
        } else {
#pragma unroll
            for (int i = 0; i < 2; i++) {
                int r = brow + i * 8;
                cp16(smem_u32(&Bs[buf][r][bcol]), B + (long long)(k0 + r) * ldb + bcol);
            }
        }
    };

    float acc[4][4][4];
#pragma unroll
    for (int i = 0; i < 4; i++)
#pragma unroll
        for (int j = 0; j < 4; j++)
#pragma unroll
            for (int u = 0; u < 4; u++) acc[i][j][u] = 0.f;

    int wm = (wid & 1) * 64, wn = (wid >> 1) * 32;
    int fr = lane >> 2, fc = lane & 3;

    loadA(0, 0); loadB(0, 0); CP_COMMIT();

    for (int t = 0; t < nstg; t++) {
        if (t + 1 < nstg) {
            loadA((t + 1) & 1, (t + 1) * 16);
            loadB((t + 1) & 1, (t + 1) * 16);
            CP_COMMIT();
            CP_WAIT1();
        } else {
            CP_WAIT0();
        }
        __syncthreads();
        int buf = t & 1;
#pragma unroll
        for (int kk = 0; kk < 16; kk += 8) {
            uint32_t af[4][4];
#pragma unroll
            for (int mt = 0; mt < 4; mt++) {
                const uint32_t* ap = (const uint32_t*)&As[buf][wm + mt * 16 + fr][kk + fc];
                af[mt][0] = ap[0];
                af[mt][1] = ap[8 * 20];
                af[mt][2] = ap[4];
                af[mt][3] = ap[8 * 20 + 4];
            }
            uint32_t bf[4][2];
#pragma unroll
            for (int nt = 0; nt < 4; nt++) {
                if (TB) {
                    const float* bp = &Bs[buf][wn + nt * 8 + fr][kk + fc];
                    bf[nt][0] = rna_tf32_u(bp[0]);
                    bf[nt][1] = rna_tf32_u(bp[4]);
                } else {
                    const float* bp = &Bs[buf][kk + fc][wn + nt * 8 + fr];
                    bf[nt][0] = rna_tf32_u(bp[0]);
                    bf[nt][1] = rna_tf32_u(bp[4 * 132]);
                }
            }
#pragma unroll
            for (int mt = 0; mt < 4; mt++)
#pragma unroll
                for (int nt = 0; nt < 4; nt++) mma_tf32(acc[mt][nt], af[mt], bf[nt]);
        }
        __syncthreads();
    }

    // epilogue
#pragma unroll
    for (int mt = 0; mt < 4; mt++) {
        int m = row0 + wm + mt * 16 + fr;
#pragma unroll
        for (int nt = 0; nt < 4; nt++) {
            int n = col0 + wn + nt * 8 + fc * 2;
            float2 v0 = make_float2(acc[mt][nt][0], acc[mt][nt][1]);
            float2 v1 = make_float2(acc[mt][nt][2], acc[mt][nt][3]);
            if (EPI == 1) {
                v0.x += X[n]; v0.y += X[n + 1];
                v1.x += X[n]; v1.y += X[n + 1];
            }
            if (EPI == 2) {
                const float2 r0 = *(const float2*)&X[(long long)m * ldc + n];
                const float2 r1 = *(const float2*)&X[(long long)(m + 8) * ldc + n];
                v0.x += r0.x; v0.y += r0.y;
                v1.x += r1.x; v1.y += r1.y;
            }
            if (RNA) {
                v0.x = rna_tf32_f(v0.x); v0.y = rna_tf32_f(v0.y);
                v1.x = rna_tf32_f(v1.x); v1.y = rna_tf32_f(v1.y);
            }
            if (!IDX || m < cbound)
                *(float2*)&C[(long long)m * ldc + n] = v0;
            if (!IDX || m + 8 < cbound)
                *(float2*)&C[(long long)(m + 8) * ldc + n] = v1;
        }
    }
}

// ---------------- RMSNorm (tf32-rounded) ----------------
__global__ void rmsnorm_kernel(const float* __restrict__ x, const float* __restrict__ w,
                               float* __restrict__ o) {
    int s = blockIdx.x;
    const float* xr = x + (long long)s * H;
    float* orow = o + (long long)s * H;
    int tid = threadIdx.x;
    float ss = 0.f;
    for (int i = tid; i < H; i += 256) { float v = xr[i]; ss += v * v; }
    __shared__ float sh[8];
#pragma unroll
    for (int off = 16; off; off >>= 1) ss += __shfl_xor_sync(0xffffffffu, ss, off);
    if ((tid & 31) == 0) sh[tid >> 5] = ss;
    __syncthreads();
    ss = sh[tid & 7];
#pragma unroll
    for (int off = 4; off; off >>= 1) ss += __shfl_xor_sync(0xffffffffu, ss, off);
    float inv = rsqrtf(ss / (float)H + 1e-6f);
    for (int i = tid; i < H; i += 256) orow[i] = rna_tf32_f(w[i] * xr[i] * inv);
}

// ---------------- RoPE (tf32-rounded) ----------------
__global__ void rope_kernel(float* __restrict__ q, float* __restrict__ k) {
    int s = blockIdx.x, h = blockIdx.y, d = threadIdx.x;
    double invd = exp(-((double)(2 * d) / 128.0) * 13.815510557964274);
    float inv = (float)invd;
    float ang = (float)s * inv;
    float c = cosf(ang), sn = sinf(ang);
    long long base = ((long long)s * NH + h) * D;
    float q1 = q[base + d], q2 = q[base + d + 64];
    q[base + d] = rna_tf32_f(q1 * c - q2 * sn);
    q[base + d + 64] = rna_tf32_f(q2 * c + q1 * sn);
    float k1 = k[base + d], k2 = k[base + d + 64];
    k[base + d] = rna_tf32_f(k1 * c - k2 * sn);
    k[base + d + 64] = rna_tf32_f(k2 * c + k1 * sn);
}

// ---------------- causal softmax (tf32-rounded; zero-fill to 128-tile bound) ----------------
__global__ void softmax_causal_kernel(float* __restrict__ sc) {
    long long row = blockIdx.x;
    int q = (int)(row & (S - 1));
    float* p = sc + row * S;
    int n = q + 1;
    int lim = (q | 127) + 1;  // PV K-trim reads only up to this column
    int tid = threadIdx.x;
    __shared__ float sh[8];
    const float scale = 0.08838834764831845f;
    float mx = -3.4e38f;
    for (int i = tid; i < n; i += 256) mx = fmaxf(mx, p[i]);
#pragma unroll
    for (int o = 16; o; o >>= 1) mx = fmaxf(mx, __shfl_xor_sync(0xffffffffu, mx, o));
    if ((tid & 31) == 0) sh[tid >> 5] = mx;
    __syncthreads();
    mx = sh[tid & 7];
#pragma unroll
    for (int o = 4; o; o >>= 1) mx = fmaxf(mx, __shfl_xor_sync(0xffffffffu, mx, o));
    __syncthreads();
    float sum = 0.f;
    for (int i = tid; i < n; i += 256) {
        float e = expf((p[i] - mx) * scale);
        p[i] = e;
        sum += e;
    }
#pragma unroll
    for (int o = 16; o; o >>= 1) sum += __shfl_xor_sync(0xffffffffu, sum, o);
    if ((tid & 31) == 0) sh[tid >> 5] = sum;
    __syncthreads();
    sum = sh[tid & 7];
#pragma unroll
    for (int o = 4; o; o >>= 1) sum += __shfl_xor_sync(0xffffffffu, sum, o);
    float inv = 1.f / sum;
    for (int i = tid; i < lim; i += 256) p[i] = (i < n) ? rna_tf32_f(p[i] * inv) : 0.f;
}

// ---------------- zero expert counters ----------------
__global__ void zero_cnt_kernel(int* cnt) {
    if (threadIdx.x < NE) cnt[threadIdx.x] = 0;
}

// ---------------- router + top-k compaction ----------------
__global__ void router_kernel(const float* __restrict__ h2, const float* __restrict__ gw,
                              const float* __restrict__ sgate, float* __restrict__ rl,
                              float* __restrict__ sgl, int* __restrict__ cnt,
                              int* __restrict__ glist, int* __restrict__ slot,
                              float* __restrict__ wt4) {
    int s = blockIdx.x;
    int tid = threadIdx.x;
    const float* hr = h2 + (long long)s * H;
    float acc[9];
#pragma unroll
    for (int j = 0; j < 9; j++) acc[j] = 0.f;
    for (int i = tid; i < H; i += 256) {
        float hv = hr[i];
        const float* gr = gw + (long long)i * NE;
#pragma unroll
        for (int e = 0; e < NE; e++) acc[e] += hv * gr[e];
        acc[8] += hv * sgate[i];
    }
    __shared__ float sh[8][9];
    int warp = tid >> 5, lane = tid & 31;
#pragma unroll
    for (int j = 0; j < 9; j++) {
        float v = acc[j];
#pragma unroll
        for (int o = 16; o; o >>= 1) v += __shfl_xor_sync(0xffffffffu, v, o);
        if (lane == 0) sh[warp][j] = v;
    }
    __syncthreads();
    if (tid == 0) {
        float t[9];
#pragma unroll
        for (int j = 0; j < 9; j++) {
            float v = 0.f;
            for (int wi = 0; wi < 8; wi++) v += sh[wi][j];
            t[j] = v;
        }
        float mx = t[0];
        for (int e = 1; e < NE; e++) mx = fmaxf(mx, t[e]);
        float p[NE], sum = 0.f;
        for (int e = 0; e < NE; e++) { p[e] = expf(t[e] - mx); sum += p[e]; }
        for (int e = 0; e < NE; e++) p[e] /= sum;
        for (int kI = 0; kI < TOPK; kI++) {
            int bi = 0;
            float bv = p[0];
            for (int e = 1; e < NE; e++)
                if (p[e] > bv) { bv = p[e]; bi = e; }
            int pos = atomicAdd(&cnt[bi], 1);
            glist[bi * S + pos] = s;
            slot[s * TOPK + kI] = bi * S + pos;
            wt4[s * TOPK + kI] = bv;
            p[bi] = -1.f;
        }
        for (int e = 0; e < NE; e++) rl[s * NE + e] = t[e];
        sgl[s] = t[8];
    }
}

// ---------------- silu(g)*u on gathered expert rows ----------------
__global__ void silumul_moe_kernel(float* __restrict__ g, const float* __restrict__ u,
                                   const int* __restrict__ cnt) {
    int e = blockIdx.z, r = blockIdx.y;
    if (r >= cnt[e]) return;
    long long base = ((long long)e * S + r) * IE + blockIdx.x * 128 + threadIdx.x;
    float x = g[base];
    g[base] = rna_tf32_f((x / (1.f + expf(-x))) * u[base]);
}

// ---------------- silu(g)*u flat (shared MLP) ----------------
__global__ void silumul_kernel(const float* __restrict__ g, const float* __restrict__ u,
                               float* __restrict__ o, long long n) {
    long long i = (long long)blockIdx.x * 256 + threadIdx.x;
    if (i < n) {
        float x = g[i];
        o[i] = rna_tf32_f((x / (1.f + expf(-x))) * u[i]);
    }
}

// ---------------- final combine (sparse slots) ----------------
__global__ void final_kernel(const float* __restrict__ x2, const float* __restrict__ eo,
                             const int* __restrict__ slot, const float* __restrict__ wt4,
                             const float* __restrict__ sm, const float* __restrict__ sgl,
                             float* __restrict__ out) {
    int i = blockIdx.x * 256 + threadIdx.x;
    int s = i >> 11, c = i & 2047;
    float mo = 0.f;
#pragma unroll
    for (int kI = 0; kI < TOPK; kI++)
        mo += wt4[s * TOPK + kI] * eo[(long long)slot[s * TOPK + kI] * H + c];
    float gg = 1.f / (1.f + expf(-sgl[s]));
    out[i] = x2[i] + mo + gg * sm[i];
}

// ---------------- host ----------------
extern "C" void kernel_launch(void* const* d_in, const int* in_sizes, int n_in,
                              void* d_out, int out_size) {
    const float* x = (const float*)d_in[0];
    const float* ln1 = (const float*)d_in[1];
    const float* ln2 = (const float*)d_in[2];
    const float* wq = (const float*)d_in[3];
    const float* bq = (const float*)d_in[4];
    const float* wk = (const float*)d_in[5];
    const float* bk = (const float*)d_in[6];
    const float* wv = (const float*)d_in[7];
    const float* bv = (const float*)d_in[8];
    const float* wo = (const float*)d_in[9];
    const float* gw = (const float*)d_in[10];
    const float* eg = (const float*)d_in[11];
    const float* eu = (const float*)d_in[12];
    const float* ed = (const float*)d_in[13];
    const float* sg = (const float*)d_in[14];
    const float* su = (const float*)d_in[15];
    const float* sd = (const float*)d_in[16];
    const float* sgate = (const float*)d_in[17];
    float* out = (float*)d_out;

    float *h1, *q, *k, *v, *sc, *at, *x2, *h2, *gb, *ub, *eo, *sgb, *sub, *sm, *sgl, *rls, *wt4;
    int *cnt, *glist, *slot;
    cudaGetSymbolAddress((void**)&h1, g_h1);
    cudaGetSymbolAddress((void**)&q, g_q);
    cudaGetSymbolAddress((void**)&k, g_k);
    cudaGetSymbolAddress((void**)&v, g_v);
    cudaGetSymbolAddress((void**)&sc, g_sc);
    cudaGetSymbolAddress((void**)&at, g_at);
    cudaGetSymbolAddress((void**)&x2, g_x2);
    cudaGetSymbolAddress((void**)&h2, g_h2);
    cudaGetSymbolAddress((void**)&gb, g_gb);
    cudaGetSymbolAddress((void**)&ub, g_ub);
    cudaGetSymbolAddress((void**)&eo, g_eo);
    cudaGetSymbolAddress((void**)&sgb, g_sgb);
    cudaGetSymbolAddress((void**)&sub, g_sub);
    cudaGetSymbolAddress((void**)&sm, g_sm);
    cudaGetSymbolAddress((void**)&sgl, g_sgl);
    cudaGetSymbolAddress((void**)&rls, g_rl);
    cudaGetSymbolAddress((void**)&wt4, g_wt4);
    cudaGetSymbolAddress((void**)&cnt, g_cnt);
    cudaGetSymbolAddress((void**)&glist, g_glist);
    cudaGetSymbolAddress((void**)&slot, g_slot);

    float* rl_dst = (out_size >= S * H + S * NE) ? (out + (size_t)S * H) : rls;

    // 1) h1 = rmsnorm(x, ln1)
    rmsnorm_kernel<<<S, 256>>>(x, ln1, h1);

    // 2) q,k,v
    {
        dim3 g(16, 16, 1);
        mma_gemm<false, 1, 0, false, 0><<<g, 256>>>(h1, wq, q, bq, 0, 0, H, H, H, H, 0, 0, 0);
        mma_gemm<false, 1, 0, false, 0><<<g, 256>>>(h1, wk, k, bk, 0, 0, H, H, H, H, 0, 0, 0);
        mma_gemm<false, 1, 0, true, 0><<<g, 256>>>(h1, wv, v, bv, 0, 0, H, H, H, H, 0, 0, 0);
    }

    // 3) RoPE
    rope_kernel<<<dim3(S, NH), 64>>>(q, k);

    // 4) scores (NT, causal tile skip)
    mma_gemm<true, 0, 1, false, 0><<<dim3(16, 16, NH), 256>>>(
        q, k, sc, (const float*)0, 0, 0, D, H, H, S,
        (long long)D, (long long)D, (long long)S * S);

    // 5) softmax
    softmax_causal_kernel<<<NH * S, 256>>>(sc);

    // 6) PV (NN, causal K-trim)
    mma_gemm<false, 0, 2, true, 0><<<dim3(1, 16, NH), 256>>>(
        sc, v, at, (const float*)0, 0, 0, S, S, H, H,
        (long long)S * S, (long long)D, (long long)D);

    // 7) x2 = x + at @ wo
    mma_gemm<false, 2, 0, false, 0><<<dim3(16, 16, 1), 256>>>(at, wo, x2, x, 0, 0, H, H, H, H, 0, 0, 0);

    // 8) h2 = rmsnorm(x2, ln2)
    rmsnorm_kernel<<<S, 256>>>(x2, ln2, h2);

    // 9) router + compaction
    zero_cnt_kernel<<<1, 32>>>(cnt);
    router_kernel<<<S, 256>>>(h2, gw, sgate, rl_dst, sgl, cnt, glist, slot, wt4);

    // 10) sparse MoE: gate/up gathered GEMMs
    {
        dim3 g(IE / 128, 16, NE);
        mma_gemm<false, 0, 0, false, 1><<<g, 256>>>(h2, eg, gb, (const float*)0, glist, cnt,
            H, H, IE, IE, 0LL, (long long)H * IE, (long long)S * IE);
        mma_gemm<false, 0, 0, false, 1><<<g, 256>>>(h2, eu, ub, (const float*)0, glist, cnt,
            H, H, IE, IE, 0LL, (long long)H * IE, (long long)S * IE);
    }
    silumul_moe_kernel<<<dim3(IE / 128, S, NE), 128>>>(gb, ub, cnt);
    mma_gemm<false, 0, 0, false, 2><<<dim3(16, 16, NE), 256>>>(gb, ed, eo, (const float*)0,
        (const int*)0, cnt, IE, IE, H, H,
        (long long)S * IE, (long long)IE * H, (long long)S * H);

    // 11) shared MLP
    {
        dim3 g(IS / 128, 16, 1);
        mma_gemm<false, 0, 0, false, 0><<<g, 256>>>(h2, sg, sgb, (const float*)0, 0, 0, H, H, IS, IS, 0, 0, 0);
        mma_gemm<false, 0, 0, false, 0><<<g, 256>>>(h2, su, sub, (const float*)0, 0, 0, H, H, IS, IS, 0, 0, 0);
    }
    {
        long long n = (long long)S * IS;
        silumul_kernel<<<(unsigned)((n + 255) / 256), 256>>>(sgb, sub, sgb, n);
    }
    mma_gemm<false, 0, 0, false, 0><<<dim3(16, 16, 1), 256>>>(sgb, sd, sm, (const float*)0,
        0, 0, IS, IS, H, H, 0, 0, 0);

    // 12) combine
    final_kernel<<<(S * H) / 256, 256>>>(x2, eo, slot, wt4, sm, sgl, out);
}

// round 6
// speedup vs baseline: 2.3256x; 1.7738x over previous
#include <cuda_runtime.h>
#include <cuda_fp16.h>
#include <cstdint>
#include <math.h>

#define S 2048
#define H 2048
#define NH 16
#define D 128
#define NE 8
#define TOPK 4
#define IE 1408
#define IS 5632

// ---------------- fp32 scratch ----------------
static __device__ float g_sc[(long long)NH * S * S];
static __device__ float g_x2[S * H];
static __device__ float g_h2f[S * H];
static __device__ float g_gb[(long long)NE * S * IE];
static __device__ float g_ub[(long long)NE * S * IE];
static __device__ float g_eo[(long long)NE * S * H];
static __device__ float g_sgb[(long long)S * IS];
static __device__ float g_sub[(long long)S * IS];
static __device__ float g_sm[S * H];
static __device__ float g_sgl[S];
static __device__ float g_rl[S * NE];
static __device__ float g_wt4[S * TOPK];
static __device__ int g_cnt[NE];
static __device__ int g_glist[NE * S];
static __device__ int g_slot[S * TOPK];
// ---------------- half scratch ----------------
static __device__ __half g_h1h[S * H];
static __device__ __half g_qh[S * H];
static __device__ __half g_kh[S * H];
static __device__ __half g_vh[S * H];
static __device__ __half g_scp[(long long)NH * S * S];
static __device__ __half g_ath[S * H];
static __device__ __half g_h2h[S * H];
static __device__ __half g_ghh[(long long)NE * S * IE];
static __device__ __half g_ssh[(long long)S * IS];
// half weights
static __device__ __half g_wqh[H * H];
static __device__ __half g_wkh[H * H];
static __device__ __half g_wvh[H * H];
static __device__ __half g_woh[H * H];
static __device__ __half g_egh[(long long)NE * H * IE];
static __device__ __half g_euh[(long long)NE * H * IE];
static __device__ __half g_edh[(long long)NE * IE * H];
static __device__ __half g_sgw[(long long)H * IS];
static __device__ __half g_suw[(long long)H * IS];
static __device__ __half g_sdw[(long long)IS * H];

// ---------------- helpers ----------------
__device__ __forceinline__ uint32_t smem_u32(const void* p) {
    uint32_t a;
    asm("{ .reg .u64 t; cvta.to.shared.u64 t, %1; cvt.u32.u64 %0, t; }" : "=r"(a) : "l"(p));
    return a;
}
__device__ __forceinline__ void cp16(uint32_t dst, const void* src) {
    asm volatile("cp.async.cg.shared.global [%0], [%1], 16;" :: "r"(dst), "l"(src));
}
#define CP_COMMIT() asm volatile("cp.async.commit_group;" ::: "memory")
#define CP_WAIT1() asm volatile("cp.async.wait_group 1;" ::: "memory")
#define CP_WAIT0() asm volatile("cp.async.wait_group 0;" ::: "memory")

__device__ __forceinline__ void ldsm_x4(uint32_t* r, uint32_t addr) {
    asm volatile("ldmatrix.sync.aligned.m8n8.x4.shared.b16 {%0,%1,%2,%3}, [%4];"
        : "=r"(r[0]), "=r"(r[1]), "=r"(r[2]), "=r"(r[3]) : "r"(addr));
}
__device__ __forceinline__ void ldsm_x4_t(uint32_t* r, uint32_t addr) {
    asm volatile("ldmatrix.sync.aligned.m8n8.x4.trans.shared.b16 {%0,%1,%2,%3}, [%4];"
        : "=r"(r[0]), "=r"(r[1]), "=r"(r[2]), "=r"(r[3]) : "r"(addr));
}
__device__ __forceinline__ void mma_f16(float* d, const uint32_t* a, const uint32_t* b) {
    asm volatile(
        "mma.sync.aligned.m16n8k16.row.col.f32.f16.f16.f32 "
        "{%0,%1,%2,%3}, {%4,%5,%6,%7}, {%8,%9}, {%0,%1,%2,%3};"
        : "+f"(d[0]), "+f"(d[1]), "+f"(d[2]), "+f"(d[3])
        : "r"(a[0]), "r"(a[1]), "r"(a[2]), "r"(a[3]), "r"(b[0]), "r"(b[1]));
}

// ---------------- fp16 mma GEMM (128x128 CTA, 8 warps 64x32, K-stage 32) ----------------
// C[M,N] = A[M,K] @ B (+ epilogue). A,B half; C half or float.
// TB: B is [N][K] (A@B^T) else [K][N].
// EPI: 0 none, 1 +bias[col] (fp32 X), 2 +resid[row][col] (fp32 X).
// CMODE: 0 none, 1 causal tile skip, 2 causal K-trim.
// OUTH: store half. IDX: 0 none, 1 gather A rows via glist + bound, 2 bound only.
template <bool TB, int EPI, int CMODE, bool OUTH, int IDX>
__global__ void __launch_bounds__(256, 2)
hgemm(const __half* __restrict__ A, const __half* __restrict__ B,
      void* __restrict__ Cv, const float* __restrict__ X,
      const int* __restrict__ glist, const int* __restrict__ cnt,
      int K, int lda, int ldb, int ldc,
      long long sA, long long sB, long long sC) {
    if (CMODE == 1 && blockIdx.x > blockIdx.y) return;
    int cbound = 0x7fffffff;
    if (IDX) {
        cbound = cnt[blockIdx.z];
        if ((int)blockIdx.y * 128 >= cbound) return;
    }

    constexpr int BR = TB ? 128 : 32;
    constexpr int BCOL = TB ? 40 : 136;
    __shared__ __align__(16) __half As[2][128][40];
    __shared__ __align__(16) __half Bs[2][BR][BCOL];

    int tid = threadIdx.x, lane = tid & 31, wid = tid >> 5;
    int row0 = blockIdx.y * 128, col0 = blockIdx.x * 128;

    A += (long long)blockIdx.z * sA;
    if (IDX != 1) A += (long long)row0 * lda;
    B += (long long)blockIdx.z * sB + (TB ? (long long)col0 * ldb : (long long)col0);

    int nstg = K >> 5;
    if (CMODE == 2) { int lim = (blockIdx.y + 1) * 4; if (lim < nstg) nstg = lim; }

    int arow = tid >> 2, acol = (tid & 3) * 8;   // A/B-NT: 128 rows x 32 halfs
    int nrow = tid >> 4, ncol = (tid & 15) * 8;  // B-NN: 32 rows x 128 halfs

    const __half* aptr[2];
#pragma unroll
    for (int i = 0; i < 2; i++) {
        int r = arow + i * 64;
        if (IDX == 1) {
            int gr = row0 + r;
            int ti = glist[blockIdx.z * S + (gr < cbound ? gr : 0)];
            aptr[i] = A + (long long)ti * lda;
        } else {
            aptr[i] = A + (long long)r * lda;
        }
    }

    auto loadA = [&](int buf, int k0) {
#pragma unroll
        for (int i = 0; i < 2; i++)
            cp16(smem_u32(&As[buf][arow + i * 64][acol]), aptr[i] + k0 + acol);
    };
    auto loadB = [&](int buf, int k0) {
        if (TB) {
#pragma unroll
            for (int i = 0; i < 2; i++)
                cp16(smem_u32(&Bs[buf][arow + i * 64][acol]),
                     B + (long long)(arow + i * 64) * ldb + k0 + acol);
        } else {
#pragma unroll
            for (int i = 0; i < 2; i++)
                cp16(smem_u32(&Bs[buf][nrow + i * 16][ncol]),
                     B + (long long)(k0 + nrow + i * 16) * ldb + ncol);
        }
    };

    float acc[4][4][4];
#pragma unroll
    for (int i = 0; i < 4; i++)
#pragma unroll
        for (int j = 0; j < 4; j++)
#pragma unroll
            for (int u = 0; u < 4; u++) acc[i][j][u] = 0.f;

    int wm = (wid & 1) * 64, wn = (wid >> 1) * 32;
    int fr = lane >> 2, fc = lane & 3;
    int l15 = lane & 15, lhi = (lane >> 4) << 3;

    loadA(0, 0); loadB(0, 0); CP_COMMIT();

    for (int t = 0; t < nstg; t++) {
        if (t + 1 < nstg) {
            loadA((t + 1) & 1, (t + 1) * 32);
            loadB((t + 1) & 1, (t + 1) * 32);
            CP_COMMIT();
            CP_WAIT1();
        } else {
            CP_WAIT0();
        }
        __syncthreads();
        int buf = t & 1;
#pragma unroll
        for (int kk = 0; kk < 32; kk += 16) {
            uint32_t af[4][4];
#pragma unroll
            for (int mt = 0; mt < 4; mt++)
                ldsm_x4(af[mt], smem_u32(&As[buf][wm + mt * 16 + l15][kk + lhi]));
            uint32_t bf[4][2];
            if (TB) {
#pragma unroll
                for (int nt = 0; nt < 4; nt++) {
                    bf[nt][0] = *(const uint32_t*)&Bs[buf][wn + nt * 8 + fr][kk + 2 * fc];
                    bf[nt][1] = *(const uint32_t*)&Bs[buf][wn + nt * 8 + fr][kk + 2 * fc + 8];
                }
            } else {
#pragma unroll
                for (int p = 0; p < 2; p++) {
                    uint32_t tmp[4];
                    ldsm_x4_t(tmp, smem_u32(&Bs[buf][kk + l15][wn + p * 16 + lhi]));
                    bf[2 * p][0] = tmp[0]; bf[2 * p][1] = tmp[1];
                    bf[2 * p + 1][0] = tmp[2]; bf[2 * p + 1][1] = tmp[3];
                }
            }
#pragma unroll
            for (int mt = 0; mt < 4; mt++)
#pragma unroll
                for (int nt = 0; nt < 4; nt++) mma_f16(acc[mt][nt], af[mt], bf[nt]);
        }
        __syncthreads();
    }

    // epilogue
#pragma unroll
    for (int mt = 0; mt < 4; mt++) {
        int m = row0 + wm + mt * 16 + fr;
#pragma unroll
        for (int nt = 0; nt < 4; nt++) {
            int n = col0 + wn + nt * 8 + fc * 2;
            float2 v0 = make_float2(acc[mt][nt][0], acc[mt][nt][1]);
            float2 v1 = make_float2(acc[mt][nt][2], acc[mt][nt][3]);
            if (EPI == 1) {
                v0.x += X[n]; v0.y += X[n + 1];
                v1.x += X[n]; v1.y += X[n + 1];
            }
            if (EPI == 2) {
                const float2 r0 = *(const float2*)&X[(long long)m * ldc + n];
                const float2 r1 = *(const float2*)&X[(long long)(m + 8) * ldc + n];
                v0.x += r0.x; v0.y += r0.y;
                v1.x += r1.x; v1.y += r1.y;
            }
            if (OUTH) {
                __half* C = (__half*)Cv + (long long)blockIdx.z * sC;
                if (!IDX || m < cbound)
                    *(half2*)&C[(long long)m * ldc + n] = __floats2half2_rn(v0.x, v0.y);
                if (!IDX || m + 8 < cbound)
                    *(half2*)&C[(long long)(m + 8) * ldc + n] = __floats2half2_rn(v1.x, v1.y);
            } else {
                float* C = (float*)Cv + (long long)blockIdx.z * sC;
                if (!IDX || m < cbound)
                    *(float2*)&C[(long long)m * ldc + n] = v0;
                if (!IDX || m + 8 < cbound)
                    *(float2*)&C[(long long)(m + 8) * ldc + n] = v1;
            }
        }
    }
}

// ---------------- fp32 -> fp16 convert ----------------
__global__ void f2h_kernel(const float* __restrict__ in, __half* __restrict__ out, long long n) {
    long long i = (long long)blockIdx.x * 1024 + threadIdx.x * 4;
    for (; i + 3 < n; i += (long long)gridDim.x * 1024) {
        float4 v = *(const float4*)&in[i];
        half2 a = __floats2half2_rn(v.x, v.y);
        half2 b = __floats2half2_rn(v.z, v.w);
        *(half2*)&out[i] = a;
        *(half2*)&out[i + 2] = b;
    }
}

// ---------------- RMSNorm: half out + optional fp32 out ----------------
__global__ void rmsnorm_kernel(const float* __restrict__ x, const float* __restrict__ w,
                               __half* __restrict__ oh, float* __restrict__ of) {
    int s = blockIdx.x;
    const float* xr = x + (long long)s * H;
    int tid = threadIdx.x;
    float ss = 0.f;
    for (int i = tid; i < H; i += 256) { float v = xr[i]; ss += v * v; }
    __shared__ float sh[8];
#pragma unroll
    for (int off = 16; off; off >>= 1) ss += __shfl_xor_sync(0xffffffffu, ss, off);
    if ((tid & 31) == 0) sh[tid >> 5] = ss;
    __syncthreads();
    ss = sh[tid & 7];
#pragma unroll
    for (int off = 4; off; off >>= 1) ss += __shfl_xor_sync(0xffffffffu, ss, off);
    float inv = rsqrtf(ss / (float)H + 1e-6f);
    for (int i = tid; i < H; i += 256) {
        float v = w[i] * xr[i] * inv;
        oh[(long long)s * H + i] = __float2half_rn(v);
        if (of) of[(long long)s * H + i] = v;
    }
}

// ---------------- RoPE on half ----------------
__global__ void rope_kernel(__half* __restrict__ q, __half* __restrict__ k) {
    int s = blockIdx.x, h = blockIdx.y, d = threadIdx.x;  // d in [0,64)
    double invd = exp(-((double)(2 * d) / 128.0) * 13.815510557964274);
    float inv = (float)invd;
    float ang = (float)s * inv;
    float c = cosf(ang), sn = sinf(ang);
    long long base = ((long long)s * NH + h) * D;
    float q1 = __half2float(q[base + d]), q2 = __half2float(q[base + d + 64]);
    q[base + d] = __float2half_rn(q1 * c - q2 * sn);
    q[base + d + 64] = __float2half_rn(q2 * c + q1 * sn);
    float k1 = __half2float(k[base + d]), k2 = __half2float(k[base + d + 64]);
    k[base + d] = __float2half_rn(k1 * c - k2 * sn);
    k[base + d + 64] = __float2half_rn(k2 * c + k1 * sn);
}

// ---------------- causal softmax: fp32 in, half out (zero-filled to tile bound) --------
__global__ void softmax_causal_kernel(const float* __restrict__ sc, __half* __restrict__ sp) {
    long long row = blockIdx.x;
    int q = (int)(row & (S - 1));
    const float* p = sc + row * S;
    __half* ph = sp + row * S;
    int n = q + 1;
    int lim = (q | 127) + 1;
    int tid = threadIdx.x;
    __shared__ float sh[8];
    __shared__ float red[2];
    const float scale = 0.08838834764831845f;
    float mx = -3.4e38f;
    for (int i = tid; i < n; i += 256) mx = fmaxf(mx, p[i]);
#pragma unroll
    for (int o = 16; o; o >>= 1) mx = fmaxf(mx, __shfl_xor_sync(0xffffffffu, mx, o));
    if ((tid & 31) == 0) sh[tid >> 5] = mx;
    __syncthreads();
    if (tid < 32) {
        mx = sh[tid & 7];
#pragma unroll
        for (int o = 4; o; o >>= 1) mx = fmaxf(mx, __shfl_xor_sync(0xffffffffu, mx, o));
        if (tid == 0) red[0] = mx;
    }
    __syncthreads();
    mx = red[0];
    float sum = 0.f;
    for (int i = tid; i < n; i += 256) sum += expf((p[i] - mx) * scale);
#pragma unroll
    for (int o = 16; o; o >>= 1) sum += __shfl_xor_sync(0xffffffffu, sum, o);
    if ((tid & 31) == 0) sh[tid >> 5] = sum;
    __syncthreads();
    if (tid < 32) {
        sum = sh[tid & 7];
#pragma unroll
        for (int o = 4; o; o >>= 1) sum += __shfl_xor_sync(0xffffffffu, sum, o);
        if (tid == 0) red[1] = sum;
    }
    __syncthreads();
    float invs = 1.f / red[1];
    for (int i = tid; i < lim; i += 256)
        ph[i] = (i < n) ? __float2half_rn(expf((p[i] - mx) * scale) * invs) : __half(0.f);
}

// ---------------- zero counters ----------------
__global__ void zero_cnt_kernel(int* cnt) {
    if (threadIdx.x < NE) cnt[threadIdx.x] = 0;
}

// ---------------- router (fp32 h2) + top-k compaction ----------------
__global__ void router_kernel(const float* __restrict__ h2, const float* __restrict__ gw,
                              const float* __restrict__ sgate, float* __restrict__ rl,
                              float* __restrict__ sgl, int* __restrict__ cnt,
                              int* __restrict__ glist, int* __restrict__ slot,
                              float* __restrict__ wt4) {
    int s = blockIdx.x;
    int tid = threadIdx.x;
    const float* hr = h2 + (long long)s * H;
    float acc[9];
#pragma unroll
    for (int j = 0; j < 9; j++) acc[j] = 0.f;
    for (int i = tid; i < H; i += 256) {
        float hv = hr[i];
        const float* gr = gw + (long long)i * NE;
#pragma unroll
        for (int e = 0; e < NE; e++) acc[e] += hv * gr[e];
        acc[8] += hv * sgate[i];
    }
    __shared__ float sh[8][9];
    int warp = tid >> 5, lane = tid & 31;
#pragma unroll
    for (int j = 0; j < 9; j++) {
        float v = acc[j];
#pragma unroll
        for (int o = 16; o; o >>= 1) v += __shfl_xor_sync(0xffffffffu, v, o);
        if (lane == 0) sh[warp][j] = v;
    }
    __syncthreads();
    if (tid == 0) {
        float t[9];
#pragma unroll
        for (int j = 0; j < 9; j++) {
            float v = 0.f;
            for (int wi = 0; wi < 8; wi++) v += sh[wi][j];
            t[j] = v;
        }
        float mx = t[0];
        for (int e = 1; e < NE; e++) mx = fmaxf(mx, t[e]);
        float p[NE], sum = 0.f;
        for (int e = 0; e < NE; e++) { p[e] = expf(t[e] - mx); sum += p[e]; }
        for (int e = 0; e < NE; e++) p[e] /= sum;
        for (int kI = 0; kI < TOPK; kI++) {
            int bi = 0;
            float bv = p[0];
            for (int e = 1; e < NE; e++)
                if (p[e] > bv) { bv = p[e]; bi = e; }
            int pos = atomicAdd(&cnt[bi], 1);
            glist[bi * S + pos] = s;
            slot[s * TOPK + kI] = bi * S + pos;
            wt4[s * TOPK + kI] = bv;
            p[bi] = -1.f;
        }
        for (int e = 0; e < NE; e++) rl[s * NE + e] = t[e];
        sgl[s] = t[8];
    }
}

// ---------------- silu(g)*u: fp32 in, half out ----------------
__global__ void silumul_moe_kernel(const float* __restrict__ g, const float* __restrict__ u,
                                   __half* __restrict__ o, const int* __restrict__ cnt) {
    int e = blockIdx.z, r = blockIdx.y;
    if (r >= cnt[e]) return;
    long long base = ((long long)e * S + r) * IE + blockIdx.x * 128 + threadIdx.x;
    float x = g[base];
    o[base] = __float2half_rn((x / (1.f + expf(-x))) * u[base]);
}
__global__ void silumul_kernel(const float* __restrict__ g, const float* __restrict__ u,
                               __half* __restrict__ o, long long n) {
    long long i = (long long)blockIdx.x * 256 + threadIdx.x;
    if (i < n) {
        float x = g[i];
        o[i] = __float2half_rn((x / (1.f + expf(-x))) * u[i]);
    }
}

// ---------------- final combine ----------------
__global__ void final_kernel(const float* __restrict__ x2, const float* __restrict__ eo,
                             const int* __restrict__ slot, const float* __restrict__ wt4,
                             const float* __restrict__ sm, const float* __restrict__ sgl,
                             float* __restrict__ out) {
    int i = blockIdx.x * 256 + threadIdx.x;
    int s = i >> 11, c = i & 2047;
    float mo = 0.f;
#pragma unroll
    for (int kI = 0; kI < TOPK; kI++)
        mo += wt4[s * TOPK + kI] * eo[(long long)slot[s * TOPK + kI] * H + c];
    float gg = 1.f / (1.f + expf(-sgl[s]));
    out[i] = x2[i] + mo + gg * sm[i];
}

// ---------------- host ----------------
extern "C" void kernel_launch(void* const* d_in, const int* in_sizes, int n_in,
                              void* d_out, int out_size) {
    const float* x = (const float*)d_in[0];
    const float* ln1 = (const float*)d_in[1];
    const float* ln2 = (const float*)d_in[2];
    const float* wq = (const float*)d_in[3];
    const float* bq = (const float*)d_in[4];
    const float* wk = (const float*)d_in[5];
    const float* bk = (const float*)d_in[6];
    const float* wv = (const float*)d_in[7];
    const float* bv = (const float*)d_in[8];
    const float* wo = (const float*)d_in[9];
    const float* gw = (const float*)d_in[10];
    const float* eg = (const float*)d_in[11];
    const float* eu = (const float*)d_in[12];
    const float* ed = (const float*)d_in[13];
    const float* sg = (const float*)d_in[14];
    const float* su = (const float*)d_in[15];
    const float* sd = (const float*)d_in[16];
    const float* sgate = (const float*)d_in[17];
    float* out = (float*)d_out;

    float *sc, *x2, *h2f, *gb, *ub, *eo, *sgb, *sub, *sm, *sgl, *rls, *wt4;
    int *cnt, *glist, *slot;
    __half *h1h, *qh, *kh, *vh, *scp, *ath, *h2h, *ghh, *ssh;
    __half *wqh, *wkh, *wvh, *woh, *egh, *euh, *edh, *sgw, *suw, *sdw;
    cudaGetSymbolAddress((void**)&sc, g_sc);
    cudaGetSymbolAddress((void**)&x2, g_x2);
    cudaGetSymbolAddress((void**)&h2f, g_h2f);
    cudaGetSymbolAddress((void**)&gb, g_gb);
    cudaGetSymbolAddress((void**)&ub, g_ub);
    cudaGetSymbolAddress((void**)&eo, g_eo);
    cudaGetSymbolAddress((void**)&sgb, g_sgb);
    cudaGetSymbolAddress((void**)&sub, g_sub);
    cudaGetSymbolAddress((void**)&sm, g_sm);
    cudaGetSymbolAddress((void**)&sgl, g_sgl);
    cudaGetSymbolAddress((void**)&rls, g_rl);
    cudaGetSymbolAddress((void**)&wt4, g_wt4);
    cudaGetSymbolAddress((void**)&cnt, g_cnt);
    cudaGetSymbolAddress((void**)&glist, g_glist);
    cudaGetSymbolAddress((void**)&slot, g_slot);
    cudaGetSymbolAddress((void**)&h1h, g_h1h);
    cudaGetSymbolAddress((void**)&qh, g_qh);
    cudaGetSymbolAddress((void**)&kh, g_kh);
    cudaGetSymbolAddress((void**)&vh, g_vh);
    cudaGetSymbolAddress((void**)&scp, g_scp);
    cudaGetSymbolAddress((void**)&ath, g_ath);
    cudaGetSymbolAddress((void**)&h2h, g_h2h);
    cudaGetSymbolAddress((void**)&ghh, g_ghh);
    cudaGetSymbolAddress((void**)&ssh, g_ssh);
    cudaGetSymbolAddress((void**)&wqh, g_wqh);
    cudaGetSymbolAddress((void**)&wkh, g_wkh);
    cudaGetSymbolAddress((void**)&wvh, g_wvh);
    cudaGetSymbolAddress((void**)&woh, g_woh);
    cudaGetSymbolAddress((void**)&egh, g_egh);
    cudaGetSymbolAddress((void**)&euh, g_euh);
    cudaGetSymbolAddress((void**)&edh, g_edh);
    cudaGetSymbolAddress((void**)&sgw, g_sgw);
    cudaGetSymbolAddress((void**)&suw, g_suw);
    cudaGetSymbolAddress((void**)&sdw, g_sdw);

    float* rl_dst = (out_size >= S * H + S * NE) ? (out + (size_t)S * H) : rls;

    // 0) weight conversions to fp16
    f2h_kernel<<<2048, 256>>>(wq, wqh, (long long)H * H);
    f2h_kernel<<<2048, 256>>>(wk, wkh, (long long)H * H);
    f2h_kernel<<<2048, 256>>>(wv, wvh, (long long)H * H);
    f2h_kernel<<<2048, 256>>>(wo, woh, (long long)H * H);
    f2h_kernel<<<4096, 256>>>(eg, egh, (long long)NE * H * IE);
    f2h_kernel<<<4096, 256>>>(eu, euh, (long long)NE * H * IE);
    f2h_kernel<<<4096, 256>>>(ed, edh, (long long)NE * IE * H);
    f2h_kernel<<<4096, 256>>>(sg, sgw, (long long)H * IS);
    f2h_kernel<<<4096, 256>>>(su, suw, (long long)H * IS);
    f2h_kernel<<<4096, 256>>>(sd, sdw, (long long)IS * H);

    // 1) h1 = rmsnorm(x, ln1)  (half)
    rmsnorm_kernel<<<S, 256>>>(x, ln1, h1h, (float*)0);

    // 2) q,k,v (half outputs, fp32 bias)
    {
        dim3 g(16, 16, 1);
        hgemm<false, 1, 0, true, 0><<<g, 256>>>(h1h, wqh, qh, bq, 0, 0, H, H, H, H, 0, 0, 0);
        hgemm<false, 1, 0, true, 0><<<g, 256>>>(h1h, wkh, kh, bk, 0, 0, H, H, H, H, 0, 0, 0);
        hgemm<false, 1, 0, true, 0><<<g, 256>>>(h1h, wvh, vh, bv, 0, 0, H, H, H, H, 0, 0, 0);
    }

    // 3) RoPE
    rope_kernel<<<dim3(S, NH), 64>>>(qh, kh);

    // 4) scores (NT, fp32 out, causal tile skip)
    hgemm<true, 0, 1, false, 0><<<dim3(16, 16, NH), 256>>>(
        qh, kh, sc, (const float*)0, 0, 0, D, H, H, S,
        (long long)D, (long long)D, (long long)S * S);

    // 5) softmax -> half probs
    softmax_causal_kernel<<<NH * S, 256>>>(sc, scp);

    // 6) PV (NN, half out, causal K-trim)
    hgemm<false, 0, 2, true, 0><<<dim3(1, 16, NH), 256>>>(
        scp, vh, ath, (const float*)0, 0, 0, S, S, H, H,
        (long long)S * S, (long long)D, (long long)D);

    // 7) x2 = x + at @ wo (fp32 out)
    hgemm<false, 2, 0, false, 0><<<dim3(16, 16, 1), 256>>>(
        ath, woh, x2, x, 0, 0, H, H, H, H, 0, 0, 0);

    // 8) h2 = rmsnorm(x2, ln2)  (half + fp32)
    rmsnorm_kernel<<<S, 256>>>(x2, ln2, h2h, h2f);

    // 9) router + compaction (fp32 h2)
    zero_cnt_kernel<<<1, 32>>>(cnt);
    router_kernel<<<S, 256>>>(h2f, gw, sgate, rl_dst, sgl, cnt, glist, slot, wt4);

    // 10) sparse MoE
    {
        dim3 g(IE / 128, 16, NE);
        hgemm<false, 0, 0, false, 1><<<g, 256>>>(h2h, egh, gb, (const float*)0, glist, cnt,
            H, H, IE, IE, 0LL, (long long)H * IE, (long long)S * IE);
        hgemm<false, 0, 0, false, 1><<<g, 256>>>(h2h, euh, ub, (const float*)0, glist, cnt,
            H, H, IE, IE, 0LL, (long long)H * IE, (long long)S * IE);
    }
    silumul_moe_kernel<<<dim3(IE / 128, S, NE), 128>>>(gb, ub, ghh, cnt);
    hgemm<false, 0, 0, false, 2><<<dim3(16, 16, NE), 256>>>(ghh, edh, eo, (const float*)0,
        (const int*)0, cnt, IE, IE, H, H,
        (long long)S * IE, (long long)IE * H, (long long)S * H);

    // 11) shared MLP
    {
        dim3 g(IS / 128, 16, 1);
        hgemm<false, 0, 0, false, 0><<<g, 256>>>(h2h, sgw, sgb, (const float*)0, 0, 0, H, H, IS, IS, 0, 0, 0);
        hgemm<false, 0, 0, false, 0><<<g, 256>>>(h2h, suw, sub, (const float*)0, 0, 0, H, H, IS, IS, 0, 0, 0);
    }
    {
        long long n = (long long)S * IS;
        silumul_kernel<<<(unsigned)((n + 255) / 256), 256>>>(sgb, sub, ssh, n);
    }
    hgemm<false, 0, 0, false, 0><<<dim3(16, 16, 1), 256>>>(ssh, sdw, sm, (const float*)0,
        0, 0, IS, IS, H, H, 0, 0, 0);

    // 12) combine
    final_kernel<<<(S * H) / 256, 256>>>(x2, eo, slot, wt4, sm, sgl, out);
}

// round 7
// speedup vs baseline: 2.5634x; 1.1023x over previous
#include <cuda_runtime.h>
#include <cuda_fp16.h>
#include <cstdint>
#include <math.h>

#define S 2048
#define H 2048
#define NH 16
#define D 128
#define NE 8
#define TOPK 4
#define IE 1408
#define IS 5632

// ---------------- fp32 scratch ----------------
static __device__ float g_x2[S * H];
static __device__ float g_h2f[S * H];
static __device__ float g_eo[(long long)NE * S * H];
static __device__ float g_sm[S * H];
static __device__ float g_sgl[S];
static __device__ float g_rl[S * NE];
static __device__ float g_wt4[S * TOPK];
static __device__ int g_cnt[NE];
static __device__ int g_glist[NE * S];
static __device__ int g_slot[S * TOPK];
// ---------------- half scratch ----------------
static __device__ __half g_h1h[S * H];
static __device__ __half g_qh[S * H];
static __device__ __half g_kh[S * H];
static __device__ __half g_vh[S * H];
static __device__ __half g_ath[S * H];
static __device__ __half g_h2h[S * H];
static __device__ __half g_ghh[(long long)NE * S * IE];   // MoE gate out
static __device__ __half g_uhh[(long long)NE * S * IE];   // MoE silu(g)*u
static __device__ __half g_ssg[(long long)S * IS];        // shared gate out
static __device__ __half g_ssh[(long long)S * IS];        // shared silu(g)*u
// half weights
static __device__ __half g_wqh[H * H];
static __device__ __half g_wkh[H * H];
static __device__ __half g_wvh[H * H];
static __device__ __half g_woh[H * H];
static __device__ __half g_egh[(long long)NE * H * IE];
static __device__ __half g_euh[(long long)NE * H * IE];
static __device__ __half g_edh[(long long)NE * IE * H];
static __device__ __half g_sgw[(long long)H * IS];
static __device__ __half g_suw[(long long)H * IS];
static __device__ __half g_sdw[(long long)IS * H];

// ---------------- helpers ----------------
__device__ __forceinline__ uint32_t smem_u32(const void* p) {
    uint32_t a;
    asm("{ .reg .u64 t; cvta.to.shared.u64 t, %1; cvt.u32.u64 %0, t; }" : "=r"(a) : "l"(p));
    return a;
}
__device__ __forceinline__ void cp16(uint32_t dst, const void* src) {
    asm volatile("cp.async.cg.shared.global [%0], [%1], 16;" :: "r"(dst), "l"(src));
}
#define CP_COMMIT() asm volatile("cp.async.commit_group;" ::: "memory")
#define CP_WAIT1() asm volatile("cp.async.wait_group 1;" ::: "memory")
#define CP_WAIT0() asm volatile("cp.async.wait_group 0;" ::: "memory")

__device__ __forceinline__ void ldsm_x4(uint32_t* r, uint32_t addr) {
    asm volatile("ldmatrix.sync.aligned.m8n8.x4.shared.b16 {%0,%1,%2,%3}, [%4];"
        : "=r"(r[0]), "=r"(r[1]), "=r"(r[2]), "=r"(r[3]) : "r"(addr));
}
__device__ __forceinline__ void ldsm_x4_t(uint32_t* r, uint32_t addr) {
    asm volatile("ldmatrix.sync.aligned.m8n8.x4.trans.shared.b16 {%0,%1,%2,%3}, [%4];"
        : "=r"(r[0]), "=r"(r[1]), "=r"(r[2]), "=r"(r[3]) : "r"(addr));
}
__device__ __forceinline__ void mma_f16(float* d, const uint32_t* a, const uint32_t* b) {
    asm volatile(
        "mma.sync.aligned.m16n8k16.row.col.f32.f16.f16.f32 "
        "{%0,%1,%2,%3}, {%4,%5,%6,%7}, {%8,%9}, {%0,%1,%2,%3};"
        : "+f"(d[0]), "+f"(d[1]), "+f"(d[2]), "+f"(d[3])
        : "r"(a[0]), "r"(a[1]), "r"(a[2]), "r"(a[3]), "r"(b[0]), "r"(b[1]));
}
__device__ __forceinline__ uint32_t pack_h2(float a, float b) {
    half2 h = __floats2half2_rn(a, b);
    return *(uint32_t*)&h;
}

// ---------------- fp16 mma GEMM (128x128 CTA, 8 warps 64x32, K-stage 32) ----------------
// EPI: 0 none, 1 +bias[col] (fp32 X), 2 +resid (fp32 X), 3 silu(Xh[m][n])*acc (half Xh).
// TB: B is [N][K]. OUTH: store half. IDX: 0 none, 1 gather A via glist+bound, 2 bound only.
template <bool TB, int EPI, bool OUTH, int IDX>
__global__ void __launch_bounds__(256, 2)
hgemm(const __half* __restrict__ A, const __half* __restrict__ B,
      void* __restrict__ Cv, const float* __restrict__ X, const __half* __restrict__ Xh,
      const int* __restrict__ glist, const int* __restrict__ cnt,
      int K, int lda, int ldb, int ldc,
      long long sA, long long sB, long long sC) {
    int cbound = 0x7fffffff;
    if (IDX) {
        cbound = cnt[blockIdx.z];
        if ((int)blockIdx.y * 128 >= cbound) return;
    }

    constexpr int BR = TB ? 128 : 32;
    constexpr int BCOL = TB ? 40 : 136;
    __shared__ __align__(16) __half As[2][128][40];
    __shared__ __align__(16) __half Bs[2][BR][BCOL];

    int tid = threadIdx.x, lane = tid & 31, wid = tid >> 5;
    int row0 = blockIdx.y * 128, col0 = blockIdx.x * 128;

    A += (long long)blockIdx.z * sA;
    if (IDX != 1) A += (long long)row0 * lda;
    B += (long long)blockIdx.z * sB + (TB ? (long long)col0 * ldb : (long long)col0);

    int nstg = K >> 5;

    int arow = tid >> 2, acol = (tid & 3) * 8;
    int nrow = tid >> 4, ncol = (tid & 15) * 8;

    const __half* aptr[2];
#pragma unroll
    for (int i = 0; i < 2; i++) {
        int r = arow + i * 64;
        if (IDX == 1) {
            int gr = row0 + r;
            int ti = glist[blockIdx.z * S + (gr < cbound ? gr : 0)];
            aptr[i] = A + (long long)ti * lda;
        } else {
            aptr[i] = A + (long long)r * lda;
        }
    }

    auto loadA = [&](int buf, int k0) {
#pragma unroll
        for (int i = 0; i < 2; i++)
            cp16(smem_u32(&As[buf][arow + i * 64][acol]), aptr[i] + k0 + acol);
    };
    auto loadB = [&](int buf, int k0) {
        if (TB) {
#pragma unroll
            for (int i = 0; i < 2; i++)
                cp16(smem_u32(&Bs[buf][arow + i * 64][acol]),
                     B + (long long)(arow + i * 64) * ldb + k0 + acol);
        } else {
#pragma unroll
            for (int i = 0; i < 2; i++)
                cp16(smem_u32(&Bs[buf][nrow + i * 16][ncol]),
                     B + (long long)(k0 + nrow + i * 16) * ldb + ncol);
        }
    };

    float acc[4][4][4];
#pragma unroll
    for (int i = 0; i < 4; i++)
#pragma unroll
        for (int j = 0; j < 4; j++)
#pragma unroll
            for (int u = 0; u < 4; u++) acc[i][j][u] = 0.f;

    int wm = (wid & 1) * 64, wn = (wid >> 1) * 32;
    int fr = lane >> 2, fc = lane & 3;
    int l15 = lane & 15, lhi = (lane >> 4) << 3;

    loadA(0, 0); loadB(0, 0); CP_COMMIT();

    for (int t = 0; t < nstg; t++) {
        if (t + 1 < nstg) {
            loadA((t + 1) & 1, (t + 1) * 32);
            loadB((t + 1) & 1, (t + 1) * 32);
            CP_COMMIT();
            CP_WAIT1();
        } else {
            CP_WAIT0();
        }
        __syncthreads();
        int buf = t & 1;
#pragma unroll
        for (int kk = 0; kk < 32; kk += 16) {
            uint32_t af[4][4];
#pragma unroll
            for (int mt = 0; mt < 4; mt++)
                ldsm_x4(af[mt], smem_u32(&As[buf][wm + mt * 16 + l15][kk + lhi]));
            uint32_t bf[4][2];
            if (TB) {
#pragma unroll
                for (int nt = 0; nt < 4; nt++) {
                    bf[nt][0] = *(const uint32_t*)&Bs[buf][wn + nt * 8 + fr][kk + 2 * fc];
                    bf[nt][1] = *(const uint32_t*)&Bs[buf][wn + nt * 8 + fr][kk + 2 * fc + 8];
                }
            } else {
#pragma unroll
                for (int p = 0; p < 2; p++) {
                    uint32_t tmp[4];
                    ldsm_x4_t(tmp, smem_u32(&Bs[buf][kk + l15][wn + p * 16 + lhi]));
                    bf[2 * p][0] = tmp[0]; bf[2 * p][1] = tmp[1];
                    bf[2 * p + 1][0] = tmp[2]; bf[2 * p + 1][1] = tmp[3];
                }
            }
#pragma unroll
            for (int mt = 0; mt < 4; mt++)
#pragma unroll
                for (int nt = 0; nt < 4; nt++) mma_f16(acc[mt][nt], af[mt], bf[nt]);
        }
        __syncthreads();
    }

    // epilogue
    const __half* XhB = (EPI == 3) ? Xh + (long long)blockIdx.z * sC : (const __half*)0;
#pragma unroll
    for (int mt = 0; mt < 4; mt++) {
        int m = row0 + wm + mt * 16 + fr;
#pragma unroll
        for (int nt = 0; nt < 4; nt++) {
            int n = col0 + wn + nt * 8 + fc * 2;
            float2 v0 = make_float2(acc[mt][nt][0], acc[mt][nt][1]);
            float2 v1 = make_float2(acc[mt][nt][2], acc[mt][nt][3]);
            if (EPI == 1) {
                v0.x += X[n]; v0.y += X[n + 1];
                v1.x += X[n]; v1.y += X[n + 1];
            }
            if (EPI == 2) {
                const float2 r0 = *(const float2*)&X[(long long)m * ldc + n];
                const float2 r1 = *(const float2*)&X[(long long)(m + 8) * ldc + n];
                v0.x += r0.x; v0.y += r0.y;
                v1.x += r1.x; v1.y += r1.y;
            }
            if (EPI == 3) {
                bool ok0 = (!IDX || m < cbound), ok1 = (!IDX || m + 8 < cbound);
                if (ok0) {
                    half2 gh = *(const half2*)&XhB[(long long)m * ldc + n];
                    float gx = __half2float(gh.x), gy = __half2float(gh.y);
                    v0.x *= gx / (1.f + expf(-gx));
                    v0.y *= gy / (1.f + expf(-gy));
                }
                if (ok1) {
                    half2 gh = *(const half2*)&XhB[(long long)(m + 8) * ldc + n];
                    float gx = __half2float(gh.x), gy = __half2float(gh.y);
                    v1.x *= gx / (1.f + expf(-gx));
                    v1.y *= gy / (1.f + expf(-gy));
                }
            }
            if (OUTH) {
                __half* C = (__half*)Cv + (long long)blockIdx.z * sC;
                if (!IDX || m < cbound)
                    *(half2*)&C[(long long)m * ldc + n] = __floats2half2_rn(v0.x, v0.y);
                if (!IDX || m + 8 < cbound)
                    *(half2*)&C[(long long)(m + 8) * ldc + n] = __floats2half2_rn(v1.x, v1.y);
            } else {
                float* C = (float*)Cv + (long long)blockIdx.z * sC;
                if (!IDX || m < cbound)
                    *(float2*)&C[(long long)m * ldc + n] = v0;
                if (!IDX || m + 8 < cbound)
                    *(float2*)&C[(long long)(m + 8) * ldc + n] = v1;
            }
        }
    }
}

// ---------------- flash attention (1 CTA = 128 q-rows x 1 head) ----------------
#define FSC 0.12751744f  // (1/sqrt(128)) * log2(e)
__global__ void __launch_bounds__(256, 1)
flash_kernel(const __half* __restrict__ Q, const __half* __restrict__ K,
             const __half* __restrict__ V, __half* __restrict__ O) {
    int qb = 15 - (int)blockIdx.x;   // big blocks first
    int h = blockIdx.y;
    extern __shared__ __half fsm[];
    __half* Qs = fsm;                    // [128][136]
    __half* Ks = fsm + 128 * 136;        // [2][128][136]
    __half* Vs = Ks + 2 * 128 * 136;     // [2][128][136]

    int tid = threadIdx.x, lane = tid & 31, wid = tid >> 5;
    int fr = lane >> 2, fc = lane & 3;
    int l15 = lane & 15, lhi = (lane >> 4) << 3;
    int wm = wid * 16;

    const __half* qg = Q + (long long)(qb * 128) * H + h * D;
    const __half* kg = K + h * D;
    const __half* vg = V + h * D;

    int lr = tid >> 1, lc = (tid & 1) * 64;
    // Q load (group 0, with K0/V0)
#pragma unroll
    for (int j = 0; j < 8; j++)
        cp16(smem_u32(Qs + lr * 136 + lc + j * 8), qg + (long long)lr * H + lc + j * 8);

    auto loadKV = [&](int buf, int kt) {
        const __half* ks = kg + (long long)(kt * 128) * H;
        const __half* vs = vg + (long long)(kt * 128) * H;
        __half* kd = Ks + buf * (128 * 136);
        __half* vd = Vs + buf * (128 * 136);
#pragma unroll
        for (int j = 0; j < 8; j++) {
            cp16(smem_u32(kd + lr * 136 + lc + j * 8), ks + (long long)lr * H + lc + j * 8);
            cp16(smem_u32(vd + lr * 136 + lc + j * 8), vs + (long long)lr * H + lc + j * 8);
        }
    };
    loadKV(0, 0); CP_COMMIT();

    float oacc[16][4];
#pragma unroll
    for (int i = 0; i < 16; i++)
#pragma unroll
        for (int u = 0; u < 4; u++) oacc[i][u] = 0.f;
    float m0 = -1e30f, m1 = -1e30f, l0 = 0.f, l1 = 0.f;

    int ntile = qb + 1;
    for (int t = 0; t < ntile; t++) {
        if (t + 1 < ntile) { loadKV((t + 1) & 1, t + 1); CP_COMMIT(); CP_WAIT1(); }
        else CP_WAIT0();
        __syncthreads();
        const __half* kb = Ks + (t & 1) * (128 * 136);
        const __half* vb = Vs + (t & 1) * (128 * 136);

        float s[16][4];
#pragma unroll
        for (int i = 0; i < 16; i++)
#pragma unroll
            for (int u = 0; u < 4; u++) s[i][u] = 0.f;

#pragma unroll
        for (int kk = 0; kk < 8; kk++) {
            uint32_t aq[4];
            ldsm_x4(aq, smem_u32(Qs + (wm + l15) * 136 + kk * 16 + lhi));
#pragma unroll
            for (int nt = 0; nt < 16; nt++) {
                uint32_t bk[2];
                bk[0] = *(const uint32_t*)(kb + (nt * 8 + fr) * 136 + kk * 16 + 2 * fc);
                bk[1] = *(const uint32_t*)(kb + (nt * 8 + fr) * 136 + kk * 16 + 2 * fc + 8);
                mma_f16(s[nt], aq, bk);
            }
        }

        if (t == qb) {  // diagonal tile: mask col > row
            int r0 = wm + fr, r1 = r0 + 8;
#pragma unroll
            for (int nt = 0; nt < 16; nt++) {
                int c0 = nt * 8 + 2 * fc;
                if (c0 > r0) s[nt][0] = -1e30f;
                if (c0 + 1 > r0) s[nt][1] = -1e30f;
                if (c0 > r1) s[nt][2] = -1e30f;
                if (c0 + 1 > r1) s[nt][3] = -1e30f;
            }
        }

        float mx0 = -1e30f, mx1 = -1e30f;
#pragma unroll
        for (int nt = 0; nt < 16; nt++) {
            mx0 = fmaxf(mx0, fmaxf(s[nt][0], s[nt][1]));
            mx1 = fmaxf(mx1, fmaxf(s[nt][2], s[nt][3]));
        }
        mx0 = fmaxf(mx0, __shfl_xor_sync(0xffffffffu, mx0, 1));
        mx0 = fmaxf(mx0, __shfl_xor_sync(0xffffffffu, mx0, 2));
        mx1 = fmaxf(mx1, __shfl_xor_sync(0xffffffffu, mx1, 1));
        mx1 = fmaxf(mx1, __shfl_xor_sync(0xffffffffu, mx1, 2));

        float mn0 = fmaxf(m0, mx0), mn1 = fmaxf(m1, mx1);
        float rs0 = exp2f((m0 - mn0) * FSC), rs1 = exp2f((m1 - mn1) * FSC);
        m0 = mn0; m1 = mn1;

        float sm0 = 0.f, sm1 = 0.f;
#pragma unroll
        for (int nt = 0; nt < 16; nt++) {
            s[nt][0] = exp2f((s[nt][0] - m0) * FSC);
            s[nt][1] = exp2f((s[nt][1] - m0) * FSC);
            s[nt][2] = exp2f((s[nt][2] - m1) * FSC);
            s[nt][3] = exp2f((s[nt][3] - m1) * FSC);
            sm0 += s[nt][0] + s[nt][1];
            sm1 += s[nt][2] + s[nt][3];
        }
        sm0 += __shfl_xor_sync(0xffffffffu, sm0, 1);
        sm0 += __shfl_xor_sync(0xffffffffu, sm0, 2);
        sm1 += __shfl_xor_sync(0xffffffffu, sm1, 1);
        sm1 += __shfl_xor_sync(0xffffffffu, sm1, 2);
        l0 = l0 * rs0 + sm0;
        l1 = l1 * rs1 + sm1;
#pragma unroll
        for (int nt = 0; nt < 16; nt++) {
            oacc[nt][0] *= rs0; oacc[nt][1] *= rs0;
            oacc[nt][2] *= rs1; oacc[nt][3] *= rs1;
        }

        // PV: P from registers, V via ldmatrix.trans
#pragma unroll
        for (int kc = 0; kc < 8; kc++) {
            uint32_t pa[4];
            pa[0] = pack_h2(s[2 * kc][0], s[2 * kc][1]);
            pa[1] = pack_h2(s[2 * kc][2], s[2 * kc][3]);
            pa[2] = pack_h2(s[2 * kc + 1][0], s[2 * kc + 1][1]);
            pa[3] = pack_h2(s[2 * kc + 1][2], s[2 * kc + 1][3]);
#pragma unroll
            for (int p = 0; p < 8; p++) {
                uint32_t tmp[4];
                ldsm_x4_t(tmp, smem_u32(vb + (kc * 16 + l15) * 136 + p * 16 + lhi));
                mma_f16(oacc[2 * p], pa, tmp);
                mma_f16(oacc[2 * p + 1], pa, tmp + 2);
            }
        }
        __syncthreads();
    }

    float inv0 = 1.f / l0, inv1 = 1.f / l1;
    __half* og = O + (long long)(qb * 128) * H + h * D;
    int r0 = wm + fr, r1 = r0 + 8;
#pragma unroll
    for (int nt = 0; nt < 16; nt++) {
        int col = nt * 8 + 2 * fc;
        *(half2*)(og + (long long)r0 * H + col) =
            __floats2half2_rn(oacc[nt][0] * inv0, oacc[nt][1] * inv0);
        *(half2*)(og + (long long)r1 * H + col) =
            __floats2half2_rn(oacc[nt][2] * inv1, oacc[nt][3] * inv1);
    }
}
#define FLASH_SMEM ((128 + 256 + 256) * 136 * 2)

// ---------------- fp32 -> fp16 ----------------
__global__ void f2h_kernel(const float* __restrict__ in, __half* __restrict__ out, long long n) {
    long long i = (long long)blockIdx.x * 1024 + threadIdx.x * 4;
    for (; i + 3 < n; i += (long long)gridDim.x * 1024) {
        float4 v = *(const float4*)&in[i];
        *(half2*)&out[i] = __floats2half2_rn(v.x, v.y);
        *(half2*)&out[i + 2] = __floats2half2_rn(v.z, v.w);
    }
}

// ---------------- RMSNorm: half out + optional fp32 out ----------------
__global__ void rmsnorm_kernel(const float* __restrict__ x, const float* __restrict__ w,
                               __half* __restrict__ oh, float* __restrict__ of) {
    int s = blockIdx.x;
    const float* xr = x + (long long)s * H;
    int tid = threadIdx.x;
    float ss = 0.f;
    for (int i = tid; i < H; i += 256) { float v = xr[i]; ss += v * v; }
    __shared__ float sh[8];
#pragma unroll
    for (int off = 16; off; off >>= 1) ss += __shfl_xor_sync(0xffffffffu, ss, off);
    if ((tid & 31) == 0) sh[tid >> 5] = ss;
    __syncthreads();
    ss = sh[tid & 7];
#pragma unroll
    for (int off = 4; off; off >>= 1) ss += __shfl_xor_sync(0xffffffffu, ss, off);
    float inv = rsqrtf(ss / (float)H + 1e-6f);
    for (int i = tid; i < H; i += 256) {
        float v = w[i] * xr[i] * inv;
        oh[(long long)s * H + i] = __float2half_rn(v);
        if (of) of[(long long)s * H + i] = v;
    }
}

// ---------------- RoPE on half ----------------
__global__ void rope_kernel(__half* __restrict__ q, __half* __restrict__ k) {
    int s = blockIdx.x, h = blockIdx.y, d = threadIdx.x;
    double invd = exp(-((double)(2 * d) / 128.0) * 13.815510557964274);
    float inv = (float)invd;
    float ang = (float)s * inv;
    float c = cosf(ang), sn = sinf(ang);
    long long base = ((long long)s * NH + h) * D;
    float q1 = __half2float(q[base + d]), q2 = __half2float(q[base + d + 64]);
    q[base + d] = __float2half_rn(q1 * c - q2 * sn);
    q[base + d + 64] = __float2half_rn(q2 * c + q1 * sn);
    float k1 = __half2float(k[base + d]), k2 = __half2float(k[base + d + 64]);
    k[base + d] = __float2half_rn(k1 * c - k2 * sn);
    k[base + d + 64] = __float2half_rn(k2 * c + k1 * sn);
}

// ---------------- zero counters ----------------
__global__ void zero_cnt_kernel(int* cnt) {
    if (threadIdx.x < NE) cnt[threadIdx.x] = 0;
}

// ---------------- router + top-k compaction ----------------
__global__ void router_kernel(const float* __restrict__ h2, const float* __restrict__ gw,
                              const float* __restrict__ sgate, float* __restrict__ rl,
                              float* __restrict__ sgl, int* __restrict__ cnt,
                              int* __restrict__ glist, int* __restrict__ slot,
                              float* __restrict__ wt4) {
    int s = blockIdx.x;
    int tid = threadIdx.x;
    const float* hr = h2 + (long long)s * H;
    float acc[9];
#pragma unroll
    for (int j = 0; j < 9; j++) acc[j] = 0.f;
    for (int i = tid; i < H; i += 256) {
        float hv = hr[i];
        const float* gr = gw + (long long)i * NE;
#pragma unroll
        for (int e = 0; e < NE; e++) acc[e] += hv * gr[e];
        acc[8] += hv * sgate[i];
    }
    __shared__ float sh[8][9];
    int warp = tid >> 5, lane = tid & 31;
#pragma unroll
    for (int j = 0; j < 9; j++) {
        float v = acc[j];
#pragma unroll
        for (int o = 16; o; o >>= 1) v += __shfl_xor_sync(0xffffffffu, v, o);
        if (lane == 0) sh[warp][j] = v;
    }
    __syncthreads();
    if (tid == 0) {
        float t[9];
#pragma unroll
        for (int j = 0; j < 9; j++) {
            float v = 0.f;
            for (int wi = 0; wi < 8; wi++) v += sh[wi][j];
            t[j] = v;
        }
        float mx = t[0];
        for (int e = 1; e < NE; e++) mx = fmaxf(mx, t[e]);
        float p[NE], sum = 0.f;
        for (int e = 0; e < NE; e++) { p[e] = expf(t[e] - mx); sum += p[e]; }
        for (int e = 0; e < NE; e++) p[e] /= sum;
        for (int kI = 0; kI < TOPK; kI++) {
            int bi = 0;
            float bv = p[0];
            for (int e = 1; e < NE; e++)
                if (p[e] > bv) { bv = p[e]; bi = e; }
            int pos = atomicAdd(&cnt[bi], 1);
            glist[bi * S + pos] = s;
            slot[s * TOPK + kI] = bi * S + pos;
            wt4[s * TOPK + kI] = bv;
            p[bi] = -1.f;
        }
        for (int e = 0; e < NE; e++) rl[s * NE + e] = t[e];
        sgl[s] = t[8];
    }
}

// ---------------- final combine ----------------
__global__ void final_kernel(const float* __restrict__ x2, const float* __restrict__ eo,
                             const int* __restrict__ slot, const float* __restrict__ wt4,
                             const float* __restrict__ sm, const float* __restrict__ sgl,
                             float* __restrict__ out) {
    int i = blockIdx.x * 256 + threadIdx.x;
    int s = i >> 11, c = i & 2047;
    float mo = 0.f;
#pragma unroll
    for (int kI = 0; kI < TOPK; kI++)
        mo += wt4[s * TOPK + kI] * eo[(long long)slot[s * TOPK + kI] * H + c];
    float gg = 1.f / (1.f + expf(-sgl[s]));
    out[i] = x2[i] + mo + gg * sm[i];
}

// ---------------- host ----------------
extern "C" void kernel_launch(void* const* d_in, const int* in_sizes, int n_in,
                              void* d_out, int out_size) {
    const float* x = (const float*)d_in[0];
    const float* ln1 = (const float*)d_in[1];
    const float* ln2 = (const float*)d_in[2];
    const float* wq = (const float*)d_in[3];
    const float* bq = (const float*)d_in[4];
    const float* wk = (const float*)d_in[5];
    const float* bk = (const float*)d_in[6];
    const float* wv = (const float*)d_in[7];
    const float* bv = (const float*)d_in[8];
    const float* wo = (const float*)d_in[9];
    const float* gw = (const float*)d_in[10];
    const float* eg = (const float*)d_in[11];
    const float* eu = (const float*)d_in[12];
    const float* ed = (const float*)d_in[13];
    const float* sg = (const float*)d_in[14];
    const float* su = (const float*)d_in[15];
    const float* sd = (const float*)d_in[16];
    const float* sgate = (const float*)d_in[17];
    float* out = (float*)d_out;

    float *x2, *h2f, *eo, *sm, *sgl, *rls, *wt4;
    int *cnt, *glist, *slot;
    __half *h1h, *qh, *kh, *vh, *ath, *h2h, *ghh, *uhh, *ssg, *ssh;
    __half *wqh, *wkh, *wvh, *woh, *egh, *euh, *edh, *sgw, *suw, *sdw;
    cudaGetSymbolAddress((void**)&x2, g_x2);
    cudaGetSymbolAddress((void**)&h2f, g_h2f);
    cudaGetSymbolAddress((void**)&eo, g_eo);
    cudaGetSymbolAddress((void**)&sm, g_sm);
    cudaGetSymbolAddress((void**)&sgl, g_sgl);
    cudaGetSymbolAddress((void**)&rls, g_rl);
    cudaGetSymbolAddress((void**)&wt4, g_wt4);
    cudaGetSymbolAddress((void**)&cnt, g_cnt);
    cudaGetSymbolAddress((void**)&glist, g_glist);
    cudaGetSymbolAddress((void**)&slot, g_slot);
    cudaGetSymbolAddress((void**)&h1h, g_h1h);
    cudaGetSymbolAddress((void**)&qh, g_qh);
    cudaGetSymbolAddress((void**)&kh, g_kh);
    cudaGetSymbolAddress((void**)&vh, g_vh);
    cudaGetSymbolAddress((void**)&ath, g_ath);
    cudaGetSymbolAddress((void**)&h2h, g_h2h);
    cudaGetSymbolAddress((void**)&ghh, g_ghh);
    cudaGetSymbolAddress((void**)&uhh, g_uhh);
    cudaGetSymbolAddress((void**)&ssg, g_ssg);
    cudaGetSymbolAddress((void**)&ssh, g_ssh);
    cudaGetSymbolAddress((void**)&wqh, g_wqh);
    cudaGetSymbolAddress((void**)&wkh, g_wkh);
    cudaGetSymbolAddress((void**)&wvh, g_wvh);
    cudaGetSymbolAddress((void**)&woh, g_woh);
    cudaGetSymbolAddress((void**)&egh, g_egh);
    cudaGetSymbolAddress((void**)&euh, g_euh);
    cudaGetSymbolAddress((void**)&edh, g_edh);
    cudaGetSymbolAddress((void**)&sgw, g_sgw);
    cudaGetSymbolAddress((void**)&suw, g_suw);
    cudaGetSymbolAddress((void**)&sdw, g_sdw);

    cudaFuncSetAttribute(flash_kernel, cudaFuncAttributeMaxDynamicSharedMemorySize, FLASH_SMEM);

    float* rl_dst = (out_size >= S * H + S * NE) ? (out + (size_t)S * H) : rls;

    // 0) weight conversion
    f2h_kernel<<<2048, 256>>>(wq, wqh, (long long)H * H);
    f2h_kernel<<<2048, 256>>>(wk, wkh, (long long)H * H);
    f2h_kernel<<<2048, 256>>>(wv, wvh, (long long)H * H);
    f2h_kernel<<<2048, 256>>>(wo, woh, (long long)H * H);
    f2h_kernel<<<4096, 256>>>(eg, egh, (long long)NE * H * IE);
    f2h_kernel<<<4096, 256>>>(eu, euh, (long long)NE * H * IE);
    f2h_kernel<<<4096, 256>>>(ed, edh, (long long)NE * IE * H);
    f2h_kernel<<<4096, 256>>>(sg, sgw, (long long)H * IS);
    f2h_kernel<<<4096, 256>>>(su, suw, (long long)H * IS);
    f2h_kernel<<<4096, 256>>>(sd, sdw, (long long)IS * H);

    // 1) h1 = rmsnorm(x, ln1)
    rmsnorm_kernel<<<S, 256>>>(x, ln1, h1h, (float*)0);

    // 2) q,k,v
    {
        dim3 g(16, 16, 1);
        hgemm<false, 1, true, 0><<<g, 256>>>(h1h, wqh, qh, bq, (const __half*)0, 0, 0, H, H, H, H, 0, 0, 0);
        hgemm<false, 1, true, 0><<<g, 256>>>(h1h, wkh, kh, bk, (const __half*)0, 0, 0, H, H, H, H, 0, 0, 0);
        hgemm<false, 1, true, 0><<<g, 256>>>(h1h, wvh, vh, bv, (const __half*)0, 0, 0, H, H, H, H, 0, 0, 0);
    }

    // 3) RoPE
    rope_kernel<<<dim3(S, NH), 64>>>(qh, kh);

    // 4) fused attention -> ath
    flash_kernel<<<dim3(16, NH), 256, FLASH_SMEM>>>(qh, kh, vh, ath);

    // 5) x2 = x + at @ wo
    hgemm<false, 2, false, 0><<<dim3(16, 16, 1), 256>>>(
        ath, woh, x2, x, (const __half*)0, 0, 0, H, H, H, H, 0, 0, 0);

    // 6) h2 = rmsnorm(x2, ln2)
    rmsnorm_kernel<<<S, 256>>>(x2, ln2, h2h, h2f);

    // 7) router + compaction
    zero_cnt_kernel<<<1, 32>>>(cnt);
    router_kernel<<<S, 256>>>(h2f, gw, sgate, rl_dst, sgl, cnt, glist, slot, wt4);

    // 8) sparse MoE: gate -> silu-fused up -> down
    {
        dim3 g(IE / 128, 16, NE);
        hgemm<false, 0, true, 1><<<g, 256>>>(h2h, egh, ghh, (const float*)0, (const __half*)0,
            glist, cnt, H, H, IE, IE, 0LL, (long long)H * IE, (long long)S * IE);
        hgemm<false, 3, true, 1><<<g, 256>>>(h2h, euh, uhh, (const float*)0, ghh,
            glist, cnt, H, H, IE, IE, 0LL, (long long)H * IE, (long long)S * IE);
    }
    hgemm<false, 0, false, 2><<<dim3(16, 16, NE), 256>>>(uhh, edh, eo, (const float*)0,
        (const __half*)0, (const int*)0, cnt, IE, IE, H, H,
        (long long)S * IE, (long long)IE * H, (long long)S * H);

    // 9) shared MLP: gate -> silu-fused up -> down
    {
        dim3 g(IS / 128, 16, 1);
        hgemm<false, 0, true, 0><<<g, 256>>>(h2h, sgw, ssg, (const float*)0, (const __half*)0,
            0, 0, H, H, IS, IS, 0, 0, 0);
        hgemm<false, 3, true, 0><<<g, 256>>>(h2h, suw, ssh, (const float*)0, ssg,
            0, 0, H, H, IS, IS, 0, 0, 0);
    }
    hgemm<false, 0, false, 0><<<dim3(16, 16, 1), 256>>>(ssh, sdw, sm, (const float*)0,
        (const __half*)0, 0, 0, IS, IS, H, H, 0, 0, 0);

    // 10) combine
    final_kernel<<<(S * H) / 256, 256>>>(x2, eo, slot, wt4, sm, sgl, out);
}

// round 8
// speedup vs baseline: 2.8421x; 1.1087x over previous
#include <cuda_runtime.h>
#include <cuda_fp16.h>
#include <cstdint>
#include <math.h>

#define S 2048
#define H 2048
#define NH 16
#define D 128
#define NE 8
#define TOPK 4
#define IE 1408
#define IS 5632

// ---------------- fp32 scratch ----------------
static __device__ float g_x2[S * H];
static __device__ float g_h2f[S * H];
static __device__ float g_eo[(long long)NE * S * H];
static __device__ float g_sm[S * H];
static __device__ float g_sgl[S];
static __device__ float g_rl[S * NE];
static __device__ float g_wt4[S * TOPK];
static __device__ int g_cnt[NE];
static __device__ int g_glist[NE * S];
static __device__ int g_slot[S * TOPK];
// ---------------- half scratch ----------------
static __device__ __half g_h1h[S * H];
static __device__ __half g_qh[S * H];
static __device__ __half g_kh[S * H];
static __device__ __half g_vh[S * H];
static __device__ __half g_ath[S * H];
static __device__ __half g_h2h[S * H];
static __device__ __half g_ghh[(long long)NE * S * IE];
static __device__ __half g_uhh[(long long)NE * S * IE];
static __device__ __half g_ssg[(long long)S * IS];
static __device__ __half g_ssh[(long long)S * IS];
// half weights
static __device__ __half g_wqh[H * H];
static __device__ __half g_wkh[H * H];
static __device__ __half g_wvh[H * H];
static __device__ __half g_woh[H * H];
static __device__ __half g_egh[(long long)NE * H * IE];
static __device__ __half g_euh[(long long)NE * H * IE];
static __device__ __half g_edh[(long long)NE * IE * H];
static __device__ __half g_sgw[(long long)H * IS];
static __device__ __half g_suw[(long long)H * IS];
static __device__ __half g_sdw[(long long)IS * H];

// ---------------- helpers ----------------
__device__ __forceinline__ uint32_t smem_u32(const void* p) {
    uint32_t a;
    asm("{ .reg .u64 t; cvta.to.shared.u64 t, %1; cvt.u32.u64 %0, t; }" : "=r"(a) : "l"(p));
    return a;
}
__device__ __forceinline__ void cp16(uint32_t dst, const void* src) {
    asm volatile("cp.async.cg.shared.global [%0], [%1], 16;" :: "r"(dst), "l"(src));
}
#define CP_COMMIT() asm volatile("cp.async.commit_group;" ::: "memory")
#define CP_WAIT1() asm volatile("cp.async.wait_group 1;" ::: "memory")
#define CP_WAIT0() asm volatile("cp.async.wait_group 0;" ::: "memory")

__device__ __forceinline__ void ldsm_x4(uint32_t* r, uint32_t addr) {
    asm volatile("ldmatrix.sync.aligned.m8n8.x4.shared.b16 {%0,%1,%2,%3}, [%4];"
        : "=r"(r[0]), "=r"(r[1]), "=r"(r[2]), "=r"(r[3]) : "r"(addr));
}
__device__ __forceinline__ void ldsm_x4_t(uint32_t* r, uint32_t addr) {
    asm volatile("ldmatrix.sync.aligned.m8n8.x4.trans.shared.b16 {%0,%1,%2,%3}, [%4];"
        : "=r"(r[0]), "=r"(r[1]), "=r"(r[2]), "=r"(r[3]) : "r"(addr));
}
__device__ __forceinline__ void mma_f16(float* d, const uint32_t* a, const uint32_t* b) {
    asm volatile(
        "mma.sync.aligned.m16n8k16.row.col.f32.f16.f16.f32 "
        "{%0,%1,%2,%3}, {%4,%5,%6,%7}, {%8,%9}, {%0,%1,%2,%3};"
        : "+f"(d[0]), "+f"(d[1]), "+f"(d[2]), "+f"(d[3])
        : "r"(a[0]), "r"(a[1]), "r"(a[2]), "r"(a[3]), "r"(b[0]), "r"(b[1]));
}
__device__ __forceinline__ uint32_t pack_h2(float a, float b) {
    half2 h = __floats2half2_rn(a, b);
    return *(uint32_t*)&h;
}

// ---------------- fp16 mma GEMM (128x128 CTA, 8 warps 64x32, K-stage 32) ----------------
template <bool TB, int EPI, bool OUTH, int IDX>
__global__ void __launch_bounds__(256, 2)
hgemm(const __half* __restrict__ A, const __half* __restrict__ B,
      void* __restrict__ Cv, const float* __restrict__ X, const __half* __restrict__ Xh,
      const int* __restrict__ glist, const int* __restrict__ cnt,
      int K, int lda, int ldb, int ldc,
      long long sA, long long sB, long long sC) {
    int cbound = 0x7fffffff;
    if (IDX) {
        cbound = cnt[blockIdx.z];
        if ((int)blockIdx.y * 128 >= cbound) return;
    }

    constexpr int BR = TB ? 128 : 32;
    constexpr int BCOL = TB ? 40 : 136;
    __shared__ __align__(16) __half As[2][128][40];
    __shared__ __align__(16) __half Bs[2][BR][BCOL];

    int tid = threadIdx.x, lane = tid & 31, wid = tid >> 5;
    int row0 = blockIdx.y * 128, col0 = blockIdx.x * 128;

    A += (long long)blockIdx.z * sA;
    if (IDX != 1) A += (long long)row0 * lda;
    B += (long long)blockIdx.z * sB + (TB ? (long long)col0 * ldb : (long long)col0);

    int nstg = K >> 5;

    int arow = tid >> 2, acol = (tid & 3) * 8;
    int nrow = tid >> 4, ncol = (tid & 15) * 8;

    const __half* aptr[2];
#pragma unroll
    for (int i = 0; i < 2; i++) {
        int r = arow + i * 64;
        if (IDX == 1) {
            int gr = row0 + r;
            int ti = glist[blockIdx.z * S + (gr < cbound ? gr : 0)];
            aptr[i] = A + (long long)ti * lda;
        } else {
            aptr[i] = A + (long long)r * lda;
        }
    }

    auto loadA = [&](int buf, int k0) {
#pragma unroll
        for (int i = 0; i < 2; i++)
            cp16(smem_u32(&As[buf][arow + i * 64][acol]), aptr[i] + k0 + acol);
    };
    auto loadB = [&](int buf, int k0) {
        if (TB) {
#pragma unroll
            for (int i = 0; i < 2; i++)
                cp16(smem_u32(&Bs[buf][arow + i * 64][acol]),
                     B + (long long)(arow + i * 64) * ldb + k0 + acol);
        } else {
#pragma unroll
            for (int i = 0; i < 2; i++)
                cp16(smem_u32(&Bs[buf][nrow + i * 16][ncol]),
                     B + (long long)(k0 + nrow + i * 16) * ldb + ncol);
        }
    };

    float acc[4][4][4];
#pragma unroll
    for (int i = 0; i < 4; i++)
#pragma unroll
        for (int j = 0; j < 4; j++)
#pragma unroll
            for (int u = 0; u < 4; u++) acc[i][j][u] = 0.f;

    int wm = (wid & 1) * 64, wn = (wid >> 1) * 32;
    int fr = lane >> 2, fc = lane & 3;
    int l15 = lane & 15, lhi = (lane >> 4) << 3;

    loadA(0, 0); loadB(0, 0); CP_COMMIT();

    for (int t = 0; t < nstg; t++) {
        if (t + 1 < nstg) {
            loadA((t + 1) & 1, (t + 1) * 32);
            loadB((t + 1) & 1, (t + 1) * 32);
            CP_COMMIT();
            CP_WAIT1();
        } else {
            CP_WAIT0();
        }
        __syncthreads();
        int buf = t & 1;
#pragma unroll
        for (int kk = 0; kk < 32; kk += 16) {
            uint32_t af[4][4];
#pragma unroll
            for (int mt = 0; mt < 4; mt++)
                ldsm_x4(af[mt], smem_u32(&As[buf][wm + mt * 16 + l15][kk + lhi]));
            uint32_t bf[4][2];
            if (TB) {
#pragma unroll
                for (int nt = 0; nt < 4; nt++) {
                    bf[nt][0] = *(const uint32_t*)&Bs[buf][wn + nt * 8 + fr][kk + 2 * fc];
                    bf[nt][1] = *(const uint32_t*)&Bs[buf][wn + nt * 8 + fr][kk + 2 * fc + 8];
                }
            } else {
#pragma unroll
                for (int p = 0; p < 2; p++) {
                    uint32_t tmp[4];
                    ldsm_x4_t(tmp, smem_u32(&Bs[buf][kk + l15][wn + p * 16 + lhi]));
                    bf[2 * p][0] = tmp[0]; bf[2 * p][1] = tmp[1];
                    bf[2 * p + 1][0] = tmp[2]; bf[2 * p + 1][1] = tmp[3];
                }
            }
#pragma unroll
            for (int mt = 0; mt < 4; mt++)
#pragma unroll
                for (int nt = 0; nt < 4; nt++) mma_f16(acc[mt][nt], af[mt], bf[nt]);
        }
        __syncthreads();
    }

    const __half* XhB = (EPI == 3) ? Xh + (long long)blockIdx.z * sC : (const __half*)0;
#pragma unroll
    for (int mt = 0; mt < 4; mt++) {
        int m = row0 + wm + mt * 16 + fr;
#pragma unroll
        for (int nt = 0; nt < 4; nt++) {
            int n = col0 + wn + nt * 8 + fc * 2;
            float2 v0 = make_float2(acc[mt][nt][0], acc[mt][nt][1]);
            float2 v1 = make_float2(acc[mt][nt][2], acc[mt][nt][3]);
            if (EPI == 1) {
                v0.x += X[n]; v0.y += X[n + 1];
                v1.x += X[n]; v1.y += X[n + 1];
            }
            if (EPI == 2) {
                const float2 r0 = *(const float2*)&X[(long long)m * ldc + n];
                const float2 r1 = *(const float2*)&X[(long long)(m + 8) * ldc + n];
                v0.x += r0.x; v0.y += r0.y;
                v1.x += r1.x; v1.y += r1.y;
            }
            if (EPI == 3) {
                bool ok0 = (!IDX || m < cbound), ok1 = (!IDX || m + 8 < cbound);
                if (ok0) {
                    half2 gh = *(const half2*)&XhB[(long long)m * ldc + n];
                    float gx = __half2float(gh.x), gy = __half2float(gh.y);
                    v0.x *= gx / (1.f + expf(-gx));
                    v0.y *= gy / (1.f + expf(-gy));
                }
                if (ok1) {
                    half2 gh = *(const half2*)&XhB[(long long)(m + 8) * ldc + n];
                    float gx = __half2float(gh.x), gy = __half2float(gh.y);
                    v1.x *= gx / (1.f + expf(-gx));
                    v1.y *= gy / (1.f + expf(-gy));
                }
            }
            if (OUTH) {
                __half* C = (__half*)Cv + (long long)blockIdx.z * sC;
                if (!IDX || m < cbound)
                    *(half2*)&C[(long long)m * ldc + n] = __floats2half2_rn(v0.x, v0.y);
                if (!IDX || m + 8 < cbound)
                    *(half2*)&C[(long long)(m + 8) * ldc + n] = __floats2half2_rn(v1.x, v1.y);
            } else {
                float* C = (float*)Cv + (long long)blockIdx.z * sC;
                if (!IDX || m < cbound)
                    *(float2*)&C[(long long)m * ldc + n] = v0;
                if (!IDX || m + 8 < cbound)
                    *(float2*)&C[(long long)(m + 8) * ldc + n] = v1;
            }
        }
    }
}

// ---------------- flash attention ----------------
#define FSC 0.12751744f
__global__ void __launch_bounds__(256, 1)
flash_kernel(const __half* __restrict__ Q, const __half* __restrict__ K,
             const __half* __restrict__ V, __half* __restrict__ O) {
    int qb = 15 - (int)blockIdx.x;
    int h = blockIdx.y;
    extern __shared__ __half fsm[];
    __half* Qs = fsm;
    __half* Ks = fsm + 128 * 136;
    __half* Vs = Ks + 2 * 128 * 136;

    int tid = threadIdx.x, lane = tid & 31, wid = tid >> 5;
    int fr = lane >> 2, fc = lane & 3;
    int l15 = lane & 15, lhi = (lane >> 4) << 3;
    int wm = wid * 16;

    const __half* qg = Q + (long long)(qb * 128) * H + h * D;
    const __half* kg = K + h * D;
    const __half* vg = V + h * D;

    int lr = tid >> 1, lc = (tid & 1) * 64;
#pragma unroll
    for (int j = 0; j < 8; j++)
        cp16(smem_u32(Qs + lr * 136 + lc + j * 8), qg + (long long)lr * H + lc + j * 8);

    auto loadKV = [&](int buf, int kt) {
        const __half* ks = kg + (long long)(kt * 128) * H;
        const __half* vs = vg + (long long)(kt * 128) * H;
        __half* kd = Ks + buf * (128 * 136);
        __half* vd = Vs + buf * (128 * 136);
#pragma unroll
        for (int j = 0; j < 8; j++) {
            cp16(smem_u32(kd + lr * 136 + lc + j * 8), ks + (long long)lr * H + lc + j * 8);
            cp16(smem_u32(vd + lr * 136 + lc + j * 8), vs + (long long)lr * H + lc + j * 8);
        }
    };
    loadKV(0, 0); CP_COMMIT();

    float oacc[16][4];
#pragma unroll
    for (int i = 0; i < 16; i++)
#pragma unroll
        for (int u = 0; u < 4; u++) oacc[i][u] = 0.f;
    float m0 = -1e30f, m1 = -1e30f, l0 = 0.f, l1 = 0.f;

    int ntile = qb + 1;
    for (int t = 0; t < ntile; t++) {
        if (t + 1 < ntile) { loadKV((t + 1) & 1, t + 1); CP_COMMIT(); CP_WAIT1(); }
        else CP_WAIT0();
        __syncthreads();
        const __half* kb = Ks + (t & 1) * (128 * 136);
        const __half* vb = Vs + (t & 1) * (128 * 136);

        float s[16][4];
#pragma unroll
        for (int i = 0; i < 16; i++)
#pragma unroll
            for (int u = 0; u < 4; u++) s[i][u] = 0.f;

#pragma unroll
        for (int kk = 0; kk < 8; kk++) {
            uint32_t aq[4];
            ldsm_x4(aq, smem_u32(Qs + (wm + l15) * 136 + kk * 16 + lhi));
#pragma unroll
            for (int nt = 0; nt < 16; nt++) {
                uint32_t bk[2];
                bk[0] = *(const uint32_t*)(kb + (nt * 8 + fr) * 136 + kk * 16 + 2 * fc);
                bk[1] = *(const uint32_t*)(kb + (nt * 8 + fr) * 136 + kk * 16 + 2 * fc + 8);
                mma_f16(s[nt], aq, bk);
            }
        }

        if (t == qb) {
            int r0 = wm + fr, r1 = r0 + 8;
#pragma unroll
            for (int nt = 0; nt < 16; nt++) {
                int c0 = nt * 8 + 2 * fc;
                if (c0 > r0) s[nt][0] = -1e30f;
                if (c0 + 1 > r0) s[nt][1] = -1e30f;
                if (c0 > r1) s[nt][2] = -1e30f;
                if (c0 + 1 > r1) s[nt][3] = -1e30f;
            }
        }

        float mx0 = -1e30f, mx1 = -1e30f;
#pragma unroll
        for (int nt = 0; nt < 16; nt++) {
            mx0 = fmaxf(mx0, fmaxf(s[nt][0], s[nt][1]));
            mx1 = fmaxf(mx1, fmaxf(s[nt][2], s[nt][3]));
        }
        mx0 = fmaxf(mx0, __shfl_xor_sync(0xffffffffu, mx0, 1));
        mx0 = fmaxf(mx0, __shfl_xor_sync(0xffffffffu, mx0, 2));
        mx1 = fmaxf(mx1, __shfl_xor_sync(0xffffffffu, mx1, 1));
        mx1 = fmaxf(mx1, __shfl_xor_sync(0xffffffffu, mx1, 2));

        float mn0 = fmaxf(m0, mx0), mn1 = fmaxf(m1, mx1);
        float rs0 = exp2f((m0 - mn0) * FSC), rs1 = exp2f((m1 - mn1) * FSC);
        m0 = mn0; m1 = mn1;

        float sm0 = 0.f, sm1 = 0.f;
#pragma unroll
        for (int nt = 0; nt < 16; nt++) {
            s[nt][0] = exp2f((s[nt][0] - m0) * FSC);
            s[nt][1] = exp2f((s[nt][1] - m0) * FSC);
            s[nt][2] = exp2f((s[nt][2] - m1) * FSC);
            s[nt][3] = exp2f((s[nt][3] - m1) * FSC);
            sm0 += s[nt][0] + s[nt][1];
            sm1 += s[nt][2] + s[nt][3];
        }
        sm0 += __shfl_xor_sync(0xffffffffu, sm0, 1);
        sm0 += __shfl_xor_sync(0xffffffffu, sm0, 2);
        sm1 += __shfl_xor_sync(0xffffffffu, sm1, 1);
        sm1 += __shfl_xor_sync(0xffffffffu, sm1, 2);
        l0 = l0 * rs0 + sm0;
        l1 = l1 * rs1 + sm1;
#pragma unroll
        for (int nt = 0; nt < 16; nt++) {
            oacc[nt][0] *= rs0; oacc[nt][1] *= rs0;
            oacc[nt][2] *= rs1; oacc[nt][3] *= rs1;
        }

#pragma unroll
        for (int kc = 0; kc < 8; kc++) {
            uint32_t pa[4];
            pa[0] = pack_h2(s[2 * kc][0], s[2 * kc][1]);
            pa[1] = pack_h2(s[2 * kc][2], s[2 * kc][3]);
            pa[2] = pack_h2(s[2 * kc + 1][0], s[2 * kc + 1][1]);
            pa[3] = pack_h2(s[2 * kc + 1][2], s[2 * kc + 1][3]);
#pragma unroll
            for (int p = 0; p < 8; p++) {
                uint32_t tmp[4];
                ldsm_x4_t(tmp, smem_u32(vb + (kc * 16 + l15) * 136 + p * 16 + lhi));
                mma_f16(oacc[2 * p], pa, tmp);
                mma_f16(oacc[2 * p + 1], pa, tmp + 2);
            }
        }
        __syncthreads();
    }

    float inv0 = 1.f / l0, inv1 = 1.f / l1;
    __half* og = O + (long long)(qb * 128) * H + h * D;
    int r0 = wm + fr, r1 = r0 + 8;
#pragma unroll
    for (int nt = 0; nt < 16; nt++) {
        int col = nt * 8 + 2 * fc;
        *(half2*)(og + (long long)r0 * H + col) =
            __floats2half2_rn(oacc[nt][0] * inv0, oacc[nt][1] * inv0);
        *(half2*)(og + (long long)r1 * H + col) =
            __floats2half2_rn(oacc[nt][2] * inv1, oacc[nt][3] * inv1);
    }
}
#define FLASH_SMEM ((128 + 256 + 256) * 136 * 2)

// ---------------- fp32 -> fp16 ----------------
__global__ void f2h_kernel(const float* __restrict__ in, __half* __restrict__ out, long long n) {
    long long i = (long long)blockIdx.x * 1024 + threadIdx.x * 4;
    for (; i + 3 < n; i += (long long)gridDim.x * 1024) {
        float4 v = *(const float4*)&in[i];
        *(half2*)&out[i] = __floats2half2_rn(v.x, v.y);
        *(half2*)&out[i + 2] = __floats2half2_rn(v.z, v.w);
    }
}

// ---------------- RMSNorm ----------------
__global__ void rmsnorm_kernel(const float* __restrict__ x, const float* __restrict__ w,
                               __half* __restrict__ oh, float* __restrict__ of) {
    int s = blockIdx.x;
    const float* xr = x + (long long)s * H;
    int tid = threadIdx.x;
    float ss = 0.f;
    for (int i = tid; i < H; i += 256) { float v = xr[i]; ss += v * v; }
    __shared__ float sh[8];
#pragma unroll
    for (int off = 16; off; off >>= 1) ss += __shfl_xor_sync(0xffffffffu, ss, off);
    if ((tid & 31) == 0) sh[tid >> 5] = ss;
    __syncthreads();
    ss = sh[tid & 7];
#pragma unroll
    for (int off = 4; off; off >>= 1) ss += __shfl_xor_sync(0xffffffffu, ss, off);
    float inv = rsqrtf(ss / (float)H + 1e-6f);
    for (int i = tid; i < H; i += 256) {
        float v = w[i] * xr[i] * inv;
        oh[(long long)s * H + i] = __float2half_rn(v);
        if (of) of[(long long)s * H + i] = v;
    }
}

// ---------------- RoPE ----------------
__global__ void rope_kernel(__half* __restrict__ q, __half* __restrict__ k) {
    int s = blockIdx.x, h = blockIdx.y, d = threadIdx.x;
    double invd = exp(-((double)(2 * d) / 128.0) * 13.815510557964274);
    float inv = (float)invd;
    float ang = (float)s * inv;
    float c = cosf(ang), sn = sinf(ang);
    long long base = ((long long)s * NH + h) * D;
    float q1 = __half2float(q[base + d]), q2 = __half2float(q[base + d + 64]);
    q[base + d] = __float2half_rn(q1 * c - q2 * sn);
    q[base + d + 64] = __float2half_rn(q2 * c + q1 * sn);
    float k1 = __half2float(k[base + d]), k2 = __half2float(k[base + d + 64]);
    k[base + d] = __float2half_rn(k1 * c - k2 * sn);
    k[base + d + 64] = __float2half_rn(k2 * c + k1 * sn);
}

// ---------------- zero counters ----------------
__global__ void zero_cnt_kernel(int* cnt) {
    if (threadIdx.x < NE) cnt[threadIdx.x] = 0;
}

// ---------------- router + top-k compaction ----------------
__global__ void router_kernel(const float* __restrict__ h2, const float* __restrict__ gw,
                              const float* __restrict__ sgate, float* __restrict__ rl,
                              float* __restrict__ sgl, int* __restrict__ cnt,
                              int* __restrict__ glist, int* __restrict__ slot,
                              float* __restrict__ wt4) {
    int s = blockIdx.x;
    int tid = threadIdx.x;
    const float* hr = h2 + (long long)s * H;
    float acc[9];
#pragma unroll
    for (int j = 0; j < 9; j++) acc[j] = 0.f;
    for (int i = tid; i < H; i += 256) {
        float hv = hr[i];
        const float* gr = gw + (long long)i * NE;
#pragma unroll
        for (int e = 0; e < NE; e++) acc[e] += hv * gr[e];
        acc[8] += hv * sgate[i];
    }
    __shared__ float sh[8][9];
    int warp = tid >> 5, lane = tid & 31;
#pragma unroll
    for (int j = 0; j < 9; j++) {
        float v = acc[j];
#pragma unroll
        for (int o = 16; o; o >>= 1) v += __shfl_xor_sync(0xffffffffu, v, o);
        if (lane == 0) sh[warp][j] = v;
    }
    __syncthreads();
    if (tid == 0) {
        float t[9];
#pragma unroll
        for (int j = 0; j < 9; j++) {
            float v = 0.f;
            for (int wi = 0; wi < 8; wi++) v += sh[wi][j];
            t[j] = v;
        }
        float mx = t[0];
        for (int e = 1; e < NE; e++) mx = fmaxf(mx, t[e]);
        float p[NE], sum = 0.f;
        for (int e = 0; e < NE; e++) { p[e] = expf(t[e] - mx); sum += p[e]; }
        for (int e = 0; e < NE; e++) p[e] /= sum;
        for (int kI = 0; kI < TOPK; kI++) {
            int bi = 0;
            float bv = p[0];
            for (int e = 1; e < NE; e++)
                if (p[e] > bv) { bv = p[e]; bi = e; }
            int pos = atomicAdd(&cnt[bi], 1);
            glist[bi * S + pos] = s;
            slot[s * TOPK + kI] = bi * S + pos;
            wt4[s * TOPK + kI] = bv;
            p[bi] = -1.f;
        }
        for (int e = 0; e < NE; e++) rl[s * NE + e] = t[e];
        sgl[s] = t[8];
    }
}

// ---------------- final combine ----------------
__global__ void final_kernel(const float* __restrict__ x2, const float* __restrict__ eo,
                             const int* __restrict__ slot, const float* __restrict__ wt4,
                             const float* __restrict__ sm, const float* __restrict__ sgl,
                             float* __restrict__ out) {
    int i = blockIdx.x * 256 + threadIdx.x;
    int s = i >> 11, c = i & 2047;
    float mo = 0.f;
#pragma unroll
    for (int kI = 0; kI < TOPK; kI++)
        mo += wt4[s * TOPK + kI] * eo[(long long)slot[s * TOPK + kI] * H + c];
    float gg = 1.f / (1.f + expf(-sgl[s]));
    out[i] = x2[i] + mo + gg * sm[i];
}

// ---------------- host ----------------
extern "C" void kernel_launch(void* const* d_in, const int* in_sizes, int n_in,
                              void* d_out, int out_size) {
    const float* x = (const float*)d_in[0];
    const float* ln1 = (const float*)d_in[1];
    const float* ln2 = (const float*)d_in[2];
    const float* wq = (const float*)d_in[3];
    const float* bq = (const float*)d_in[4];
    const float* wk = (const float*)d_in[5];
    const float* bk = (const float*)d_in[6];
    const float* wv = (const float*)d_in[7];
    const float* bv = (const float*)d_in[8];
    const float* wo = (const float*)d_in[9];
    const float* gw = (const float*)d_in[10];
    const float* eg = (const float*)d_in[11];
    const float* eu = (const float*)d_in[12];
    const float* ed = (const float*)d_in[13];
    const float* sg = (const float*)d_in[14];
    const float* su = (const float*)d_in[15];
    const float* sd = (const float*)d_in[16];
    const float* sgate = (const float*)d_in[17];
    float* out = (float*)d_out;

    float *x2, *h2f, *eo, *sm, *sgl, *rls, *wt4;
    int *cnt, *glist, *slot;
    __half *h1h, *qh, *kh, *vh, *ath, *h2h, *ghh, *uhh, *ssg, *ssh;
    __half *wqh, *wkh, *wvh, *woh, *egh, *euh, *edh, *sgw, *suw, *sdw;
    cudaGetSymbolAddress((void**)&x2, g_x2);
    cudaGetSymbolAddress((void**)&h2f, g_h2f);
    cudaGetSymbolAddress((void**)&eo, g_eo);
    cudaGetSymbolAddress((void**)&sm, g_sm);
    cudaGetSymbolAddress((void**)&sgl, g_sgl);
    cudaGetSymbolAddress((void**)&rls, g_rl);
    cudaGetSymbolAddress((void**)&wt4, g_wt4);
    cudaGetSymbolAddress((void**)&cnt, g_cnt);
    cudaGetSymbolAddress((void**)&glist, g_glist);
    cudaGetSymbolAddress((void**)&slot, g_slot);
    cudaGetSymbolAddress((void**)&h1h, g_h1h);
    cudaGetSymbolAddress((void**)&qh, g_qh);
    cudaGetSymbolAddress((void**)&kh, g_kh);
    cudaGetSymbolAddress((void**)&vh, g_vh);
    cudaGetSymbolAddress((void**)&ath, g_ath);
    cudaGetSymbolAddress((void**)&h2h, g_h2h);
    cudaGetSymbolAddress((void**)&ghh, g_ghh);
    cudaGetSymbolAddress((void**)&uhh, g_uhh);
    cudaGetSymbolAddress((void**)&ssg, g_ssg);
    cudaGetSymbolAddress((void**)&ssh, g_ssh);
    cudaGetSymbolAddress((void**)&wqh, g_wqh);
    cudaGetSymbolAddress((void**)&wkh, g_wkh);
    cudaGetSymbolAddress((void**)&wvh, g_wvh);
    cudaGetSymbolAddress((void**)&woh, g_woh);
    cudaGetSymbolAddress((void**)&egh, g_egh);
    cudaGetSymbolAddress((void**)&euh, g_euh);
    cudaGetSymbolAddress((void**)&edh, g_edh);
    cudaGetSymbolAddress((void**)&sgw, g_sgw);
    cudaGetSymbolAddress((void**)&suw, g_suw);
    cudaGetSymbolAddress((void**)&sdw, g_sdw);

    cudaFuncSetAttribute(flash_kernel, cudaFuncAttributeMaxDynamicSharedMemorySize, FLASH_SMEM);

    // lazy-init side streams/events (host objects only; identical launch
    // pattern every call, so captured graphs are deterministic)
    static cudaStream_t s2 = 0, s3 = 0;
    static cudaEvent_t evFork = 0, evW0 = 0, evW = 0, evH2 = 0, evSh = 0;
    if (!s2) {
        cudaStreamCreateWithFlags(&s2, cudaStreamNonBlocking);
        cudaStreamCreateWithFlags(&s3, cudaStreamNonBlocking);
        cudaEventCreateWithFlags(&evFork, cudaEventDisableTiming);
        cudaEventCreateWithFlags(&evW0, cudaEventDisableTiming);
        cudaEventCreateWithFlags(&evW, cudaEventDisableTiming);
        cudaEventCreateWithFlags(&evH2, cudaEventDisableTiming);
        cudaEventCreateWithFlags(&evSh, cudaEventDisableTiming);
    }

    float* rl_dst = (out_size >= S * H + S * NE) ? (out + (size_t)S * H) : rls;

    // ---- fork conversion stream ----
    cudaEventRecord(evFork, 0);
    cudaStreamWaitEvent(s2, evFork, 0);
    // small weights first (QKV/wo path needs them soon)
    f2h_kernel<<<2048, 256, 0, s2>>>(wq, wqh, (long long)H * H);
    f2h_kernel<<<2048, 256, 0, s2>>>(wk, wkh, (long long)H * H);
    f2h_kernel<<<2048, 256, 0, s2>>>(wv, wvh, (long long)H * H);
    f2h_kernel<<<2048, 256, 0, s2>>>(wo, woh, (long long)H * H);
    cudaEventRecord(evW0, s2);
    // big weights (needed only after router / for shared MLP)
    f2h_kernel<<<4096, 256, 0, s2>>>(eg, egh, (long long)NE * H * IE);
    f2h_kernel<<<4096, 256, 0, s2>>>(eu, euh, (long long)NE * H * IE);
    f2h_kernel<<<4096, 256, 0, s2>>>(sg, sgw, (long long)H * IS);
    f2h_kernel<<<4096, 256, 0, s2>>>(su, suw, (long long)H * IS);
    f2h_kernel<<<4096, 256, 0, s2>>>(ed, edh, (long long)NE * IE * H);
    f2h_kernel<<<4096, 256, 0, s2>>>(sd, sdw, (long long)IS * H);
    cudaEventRecord(evW, s2);

    // ---- main stream: attention path ----
    rmsnorm_kernel<<<S, 256>>>(x, ln1, h1h, (float*)0);
    cudaStreamWaitEvent(0, evW0, 0);
    {
        dim3 g(16, 16, 1);
        hgemm<false, 1, true, 0><<<g, 256>>>(h1h, wqh, qh, bq, (const __half*)0, 0, 0, H, H, H, H, 0, 0, 0);
        hgemm<false, 1, true, 0><<<g, 256>>>(h1h, wkh, kh, bk, (const __half*)0, 0, 0, H, H, H, H, 0, 0, 0);
        hgemm<false, 1, true, 0><<<g, 256>>>(h1h, wvh, vh, bv, (const __half*)0, 0, 0, H, H, H, H, 0, 0, 0);
    }
    rope_kernel<<<dim3(S, NH), 64>>>(qh, kh);
    flash_kernel<<<dim3(16, NH), 256, FLASH_SMEM>>>(qh, kh, vh, ath);
    hgemm<false, 2, false, 0><<<dim3(16, 16, 1), 256>>>(
        ath, woh, x2, x, (const __half*)0, 0, 0, H, H, H, H, 0, 0, 0);
    rmsnorm_kernel<<<S, 256>>>(x2, ln2, h2h, h2f);
    zero_cnt_kernel<<<1, 32>>>(cnt);
    router_kernel<<<S, 256>>>(h2f, gw, sgate, rl_dst, sgl, cnt, glist, slot, wt4);
    cudaEventRecord(evH2, 0);

    // ---- stream s3: shared MLP branch (needs h2h + sgw/suw/sdw) ----
    cudaStreamWaitEvent(s3, evH2, 0);
    cudaStreamWaitEvent(s3, evW, 0);
    {
        dim3 g(IS / 128, 16, 1);
        hgemm<false, 0, true, 0><<<g, 256, 0, s3>>>(h2h, sgw, ssg, (const float*)0, (const __half*)0,
            0, 0, H, H, IS, IS, 0, 0, 0);
        hgemm<false, 3, true, 0><<<g, 256, 0, s3>>>(h2h, suw, ssh, (const float*)0, ssg,
            0, 0, H, H, IS, IS, 0, 0, 0);
        hgemm<false, 0, false, 0><<<dim3(16, 16, 1), 256, 0, s3>>>(ssh, sdw, sm, (const float*)0,
            (const __half*)0, 0, 0, IS, IS, H, H, 0, 0, 0);
    }
    cudaEventRecord(evSh, s3);

    // ---- main stream: sparse MoE branch ----
    cudaStreamWaitEvent(0, evW, 0);
    {
        dim3 g(IE / 128, 16, NE);
        hgemm<false, 0, true, 1><<<g, 256>>>(h2h, egh, ghh, (const float*)0, (const __half*)0,
            glist, cnt, H, H, IE, IE, 0LL, (long long)H * IE, (long long)S * IE);
        hgemm<false, 3, true, 1><<<g, 256>>>(h2h, euh, uhh, (const float*)0, ghh,
            glist, cnt, H, H, IE, IE, 0LL, (long long)H * IE, (long long)S * IE);
    }
    hgemm<false, 0, false, 2><<<dim3(16, 16, NE), 256>>>(uhh, edh, eo, (const float*)0,
        (const __half*)0, (const int*)0, cnt, IE, IE, H, H,
        (long long)S * IE, (long long)IE * H, (long long)S * H);

    // ---- join + combine ----
    cudaStreamWaitEvent(0, evSh, 0);
    final_kernel<<<(S * H) / 256, 256>>>(x2, eo, slot, wt4, sm, sgl, out);
}

// round 9
// speedup vs baseline: 2.8573x; 1.0053x over previous
#include <cuda_runtime.h>
#include <cuda_fp16.h>
#include <cstdint>
#include <math.h>

#define S 2048
#define H 2048
#define NH 16
#define D 128
#define NE 8
#define TOPK 4
#define IE 1408
#define IS 5632

// ---------------- fp32 scratch ----------------
static __device__ float g_x2[S * H];
static __device__ float g_h2f[S * H];
static __device__ float g_eo[(long long)NE * S * H];
static __device__ float g_sm[S * H];
static __device__ float g_sgl[S];
static __device__ float g_rl[S * NE];
static __device__ float g_wt4[S * TOPK];
static __device__ int g_cnt[NE];
static __device__ int g_glist[NE * S];
static __device__ int g_slot[S * TOPK];
// ---------------- half scratch ----------------
static __device__ __half g_h1h[S * H];
static __device__ __half g_qh[S * H];
static __device__ __half g_kh[S * H];
static __device__ __half g_vh[S * H];
static __device__ __half g_ath[S * H];
static __device__ __half g_h2h[S * H];
static __device__ __half g_ghh[(long long)NE * S * IE];
static __device__ __half g_uhh[(long long)NE * S * IE];
static __device__ __half g_ssg[(long long)S * IS];
static __device__ __half g_ssh[(long long)S * IS];
// half weights
static __device__ __half g_wqh[H * H];
static __device__ __half g_wkh[H * H];
static __device__ __half g_wvh[H * H];
static __device__ __half g_woh[H * H];
static __device__ __half g_egh[(long long)NE * H * IE];
static __device__ __half g_euh[(long long)NE * H * IE];
static __device__ __half g_edh[(long long)NE * IE * H];
static __device__ __half g_sgw[(long long)H * IS];
static __device__ __half g_suw[(long long)H * IS];
static __device__ __half g_sdw[(long long)IS * H];

// ---------------- helpers ----------------
__device__ __forceinline__ uint32_t smem_u32(const void* p) {
    uint32_t a;
    asm("{ .reg .u64 t; cvta.to.shared.u64 t, %1; cvt.u32.u64 %0, t; }" : "=r"(a) : "l"(p));
    return a;
}
__device__ __forceinline__ void cp16(uint32_t dst, const void* src) {
    asm volatile("cp.async.cg.shared.global [%0], [%1], 16;" :: "r"(dst), "l"(src));
}
#define CP_COMMIT() asm volatile("cp.async.commit_group;" ::: "memory")
#define CP_WAIT2() asm volatile("cp.async.wait_group 2;" ::: "memory")
#define CP_WAIT1() asm volatile("cp.async.wait_group 1;" ::: "memory")
#define CP_WAIT0() asm volatile("cp.async.wait_group 0;" ::: "memory")

__device__ __forceinline__ void ldsm_x4(uint32_t* r, uint32_t addr) {
    asm volatile("ldmatrix.sync.aligned.m8n8.x4.shared.b16 {%0,%1,%2,%3}, [%4];"
        : "=r"(r[0]), "=r"(r[1]), "=r"(r[2]), "=r"(r[3]) : "r"(addr));
}
__device__ __forceinline__ void ldsm_x4_t(uint32_t* r, uint32_t addr) {
    asm volatile("ldmatrix.sync.aligned.m8n8.x4.trans.shared.b16 {%0,%1,%2,%3}, [%4];"
        : "=r"(r[0]), "=r"(r[1]), "=r"(r[2]), "=r"(r[3]) : "r"(addr));
}
__device__ __forceinline__ void mma_f16(float* d, const uint32_t* a, const uint32_t* b) {
    asm volatile(
        "mma.sync.aligned.m16n8k16.row.col.f32.f16.f16.f32 "
        "{%0,%1,%2,%3}, {%4,%5,%6,%7}, {%8,%9}, {%0,%1,%2,%3};"
        : "+f"(d[0]), "+f"(d[1]), "+f"(d[2]), "+f"(d[3])
        : "r"(a[0]), "r"(a[1]), "r"(a[2]), "r"(a[3]), "r"(b[0]), "r"(b[1]));
}
__device__ __forceinline__ uint32_t pack_h2(float a, float b) {
    half2 h = __floats2half2_rn(a, b);
    return *(uint32_t*)&h;
}

// ---------------- fp16 mma GEMM (128x128 CTA, 8 warps 64x32, K-stage 32, 3-deep pipe) ---
// B is [K][N] row-major only (NN). Dynamic smem.
// EPI: 0 none, 1 +bias[col], 2 +resid, 3 silu(Xh)*acc. OUTH: half out.
// IDX: 0 none, 1 gather A via glist+bound, 2 bound only.
#define A_ELT 5120     // 128*40 halfs per stage
#define B_ELT 4352     // 32*136 halfs per stage
#define SMEM_G ((3 * (A_ELT + B_ELT)) * 2)

template <int EPI, bool OUTH, int IDX>
__global__ void __launch_bounds__(256, 2)
hgemm(const __half* __restrict__ A, const __half* __restrict__ B,
      void* __restrict__ Cv, const float* __restrict__ X, const __half* __restrict__ Xh,
      const int* __restrict__ glist, const int* __restrict__ cnt,
      int K, int lda, int ldb, int ldc,
      long long sA, long long sB, long long sC) {
    int cbound = 0x7fffffff;
    if (IDX) {
        cbound = cnt[blockIdx.z];
        if ((int)blockIdx.y * 128 >= cbound) return;
    }
    extern __shared__ __half dsm[];
    __half* const AS = dsm;               // 3 stages, pitch 40
    __half* const BS = dsm + 3 * A_ELT;   // 3 stages, pitch 136

    int tid = threadIdx.x, lane = tid & 31, wid = tid >> 5;
    int row0 = blockIdx.y * 128, col0 = blockIdx.x * 128;

    A += (long long)blockIdx.z * sA;
    if (IDX != 1) A += (long long)row0 * lda;
    B += (long long)blockIdx.z * sB + col0;

    int nstg = K >> 5;

    int arow = tid >> 2, acol = (tid & 3) * 8;
    int nrow = tid >> 4, ncol = (tid & 15) * 8;

    const __half* aptr[2];
#pragma unroll
    for (int i = 0; i < 2; i++) {
        int r = arow + i * 64;
        if (IDX == 1) {
            int gr = row0 + r;
            int ti = glist[blockIdx.z * S + (gr < cbound ? gr : 0)];
            aptr[i] = A + (long long)ti * lda;
        } else {
            aptr[i] = A + (long long)r * lda;
        }
    }

    auto fill = [&](int s, int k0) {
        __half* ad = AS + s * A_ELT;
        __half* bd = BS + s * B_ELT;
#pragma unroll
        for (int i = 0; i < 2; i++)
            cp16(smem_u32(ad + (arow + i * 64) * 40 + acol), aptr[i] + k0 + acol);
#pragma unroll
        for (int i = 0; i < 2; i++)
            cp16(smem_u32(bd + (nrow + i * 16) * 136 + ncol),
                 B + (long long)(k0 + nrow + i * 16) * ldb + ncol);
        CP_COMMIT();
    };

    float acc[4][4][4];
#pragma unroll
    for (int i = 0; i < 4; i++)
#pragma unroll
        for (int j = 0; j < 4; j++)
#pragma unroll
            for (int u = 0; u < 4; u++) acc[i][j][u] = 0.f;

    int wm = (wid & 1) * 64, wn = (wid >> 1) * 32;
    int fr = lane >> 2, fc = lane & 3;
    int l15 = lane & 15, lhi = (lane >> 4) << 3;

    fill(0, 0);
    if (nstg > 1) fill(1, 32);

    for (int t = 0; t < nstg; t++) {
        if (t + 2 < nstg) { fill((t + 2) % 3, (t + 2) * 32); CP_WAIT2(); }
        else if (t + 1 < nstg) CP_WAIT1();
        else CP_WAIT0();
        __syncthreads();
        const __half* as = AS + (t % 3) * A_ELT;
        const __half* bs = BS + (t % 3) * B_ELT;
#pragma unroll
        for (int kk = 0; kk < 32; kk += 16) {
            uint32_t af[4][4];
#pragma unroll
            for (int mt = 0; mt < 4; mt++)
                ldsm_x4(af[mt], smem_u32(as + (wm + mt * 16 + l15) * 40 + kk + lhi));
            uint32_t bf[4][2];
#pragma unroll
            for (int p = 0; p < 2; p++) {
                uint32_t tmp[4];
                ldsm_x4_t(tmp, smem_u32(bs + (kk + l15) * 136 + wn + p * 16 + lhi));
                bf[2 * p][0] = tmp[0]; bf[2 * p][1] = tmp[1];
                bf[2 * p + 1][0] = tmp[2]; bf[2 * p + 1][1] = tmp[3];
            }
#pragma unroll
            for (int mt = 0; mt < 4; mt++)
#pragma unroll
                for (int nt = 0; nt < 4; nt++) mma_f16(acc[mt][nt], af[mt], bf[nt]);
        }
        __syncthreads();
    }

    const __half* XhB = (EPI == 3) ? Xh + (long long)blockIdx.z * sC : (const __half*)0;
#pragma unroll
    for (int mt = 0; mt < 4; mt++) {
        int m = row0 + wm + mt * 16 + fr;
#pragma unroll
        for (int nt = 0; nt < 4; nt++) {
            int n = col0 + wn + nt * 8 + fc * 2;
            float2 v0 = make_float2(acc[mt][nt][0], acc[mt][nt][1]);
            float2 v1 = make_float2(acc[mt][nt][2], acc[mt][nt][3]);
            if (EPI == 1) {
                v0.x += X[n]; v0.y += X[n + 1];
                v1.x += X[n]; v1.y += X[n + 1];
            }
            if (EPI == 2) {
                const float2 r0 = *(const float2*)&X[(long long)m * ldc + n];
                const float2 r1 = *(const float2*)&X[(long long)(m + 8) * ldc + n];
                v0.x += r0.x; v0.y += r0.y;
                v1.x += r1.x; v1.y += r1.y;
            }
            if (EPI == 3) {
                bool ok0 = (!IDX || m < cbound), ok1 = (!IDX || m + 8 < cbound);
                if (ok0) {
                    half2 gh = *(const half2*)&XhB[(long long)m * ldc + n];
                    float gx = __half2float(gh.x), gy = __half2float(gh.y);
                    v0.x *= gx / (1.f + expf(-gx));
                    v0.y *= gy / (1.f + expf(-gy));
                }
                if (ok1) {
                    half2 gh = *(const half2*)&XhB[(long long)(m + 8) * ldc + n];
                    float gx = __half2float(gh.x), gy = __half2float(gh.y);
                    v1.x *= gx / (1.f + expf(-gx));
                    v1.y *= gy / (1.f + expf(-gy));
                }
            }
            if (OUTH) {
                __half* C = (__half*)Cv + (long long)blockIdx.z * sC;
                if (!IDX || m < cbound)
                    *(half2*)&C[(long long)m * ldc + n] = __floats2half2_rn(v0.x, v0.y);
                if (!IDX || m + 8 < cbound)
                    *(half2*)&C[(long long)(m + 8) * ldc + n] = __floats2half2_rn(v1.x, v1.y);
            } else {
                float* C = (float*)Cv + (long long)blockIdx.z * sC;
                if (!IDX || m < cbound)
                    *(float2*)&C[(long long)m * ldc + n] = v0;
                if (!IDX || m + 8 < cbound)
                    *(float2*)&C[(long long)(m + 8) * ldc + n] = v1;
            }
        }
    }
}

// ---------------- flash attention ----------------
#define FSC 0.12751744f
__global__ void __launch_bounds__(256, 1)
flash_kernel(const __half* __restrict__ Q, const __half* __restrict__ K,
             const __half* __restrict__ V, __half* __restrict__ O) {
    int qb = 15 - (int)blockIdx.x;
    int h = blockIdx.y;
    extern __shared__ __half fsm[];
    __half* Qs = fsm;
    __half* Ks = fsm + 128 * 136;
    __half* Vs = Ks + 2 * 128 * 136;

    int tid = threadIdx.x, lane = tid & 31, wid = tid >> 5;
    int fr = lane >> 2, fc = lane & 3;
    int l15 = lane & 15, lhi = (lane >> 4) << 3;
    int wm = wid * 16;

    const __half* qg = Q + (long long)(qb * 128) * H + h * D;
    const __half* kg = K + h * D;
    const __half* vg = V + h * D;

    int lr = tid >> 1, lc = (tid & 1) * 64;
#pragma unroll
    for (int j = 0; j < 8; j++)
        cp16(smem_u32(Qs + lr * 136 + lc + j * 8), qg + (long long)lr * H + lc + j * 8);

    auto loadKV = [&](int buf, int kt) {
        const __half* ks = kg + (long long)(kt * 128) * H;
        const __half* vs = vg + (long long)(kt * 128) * H;
        __half* kd = Ks + buf * (128 * 136);
        __half* vd = Vs + buf * (128 * 136);
#pragma unroll
        for (int j = 0; j < 8; j++) {
            cp16(smem_u32(kd + lr * 136 + lc + j * 8), ks + (long long)lr * H + lc + j * 8);
            cp16(smem_u32(vd + lr * 136 + lc + j * 8), vs + (long long)lr * H + lc + j * 8);
        }
    };
    loadKV(0, 0); CP_COMMIT();

    float oacc[16][4];
#pragma unroll
    for (int i = 0; i < 16; i++)
#pragma unroll
        for (int u = 0; u < 4; u++) oacc[i][u] = 0.f;
    float m0 = -1e30f, m1 = -1e30f, l0 = 0.f, l1 = 0.f;

    int ntile = qb + 1;
    for (int t = 0; t < ntile; t++) {
        if (t + 1 < ntile) { loadKV((t + 1) & 1, t + 1); CP_COMMIT(); CP_WAIT1(); }
        else CP_WAIT0();
        __syncthreads();
        const __half* kb = Ks + (t & 1) * (128 * 136);
        const __half* vb = Vs + (t & 1) * (128 * 136);

        float s[16][4];
#pragma unroll
        for (int i = 0; i < 16; i++)
#pragma unroll
            for (int u = 0; u < 4; u++) s[i][u] = 0.f;

#pragma unroll
        for (int kk = 0; kk < 8; kk++) {
            uint32_t aq[4];
            ldsm_x4(aq, smem_u32(Qs + (wm + l15) * 136 + kk * 16 + lhi));
#pragma unroll
            for (int nt = 0; nt < 16; nt++) {
                uint32_t bk[2];
                bk[0] = *(const uint32_t*)(kb + (nt * 8 + fr) * 136 + kk * 16 + 2 * fc);
                bk[1] = *(const uint32_t*)(kb + (nt * 8 + fr) * 136 + kk * 16 + 2 * fc + 8);
                mma_f16(s[nt], aq, bk);
            }
        }

        if (t == qb) {
            int r0 = wm + fr, r1 = r0 + 8;
#pragma unroll
            for (int nt = 0; nt < 16; nt++) {
                int c0 = nt * 8 + 2 * fc;
                if (c0 > r0) s[nt][0] = -1e30f;
                if (c0 + 1 > r0) s[nt][1] = -1e30f;
                if (c0 > r1) s[nt][2] = -1e30f;
                if (c0 + 1 > r1) s[nt][3] = -1e30f;
            }
        }

        float mx0 = -1e30f, mx1 = -1e30f;
#pragma unroll
        for (int nt = 0; nt < 16; nt++) {
            mx0 = fmaxf(mx0, fmaxf(s[nt][0], s[nt][1]));
            mx1 = fmaxf(mx1, fmaxf(s[nt][2], s[nt][3]));
        }
        mx0 = fmaxf(mx0, __shfl_xor_sync(0xffffffffu, mx0, 1));
        mx0 = fmaxf(mx0, __shfl_xor_sync(0xffffffffu, mx0, 2));
        mx1 = fmaxf(mx1, __shfl_xor_sync(0xffffffffu, mx1, 1));
        mx1 = fmaxf(mx1, __shfl_xor_sync(0xffffffffu, mx1, 2));

        float mn0 = fmaxf(m0, mx0), mn1 = fmaxf(m1, mx1);
        float rs0 = exp2f((m0 - mn0) * FSC), rs1 = exp2f((m1 - mn1) * FSC);
        m0 = mn0; m1 = mn1;

        float sm0 = 0.f, sm1 = 0.f;
#pragma unroll
        for (int nt = 0; nt < 16; nt++) {
            s[nt][0] = exp2f((s[nt][0] - m0) * FSC);
            s[nt][1] = exp2f((s[nt][1] - m0) * FSC);
            s[nt][2] = exp2f((s[nt][2] - m1) * FSC);
            s[nt][3] = exp2f((s[nt][3] - m1) * FSC);
            sm0 += s[nt][0] + s[nt][1];
            sm1 += s[nt][2] + s[nt][3];
        }
        sm0 += __shfl_xor_sync(0xffffffffu, sm0, 1);
        sm0 += __shfl_xor_sync(0xffffffffu, sm0, 2);
        sm1 += __shfl_xor_sync(0xffffffffu, sm1, 1);
        sm1 += __shfl_xor_sync(0xffffffffu, sm1, 2);
        l0 = l0 * rs0 + sm0;
        l1 = l1 * rs1 + sm1;
#pragma unroll
        for (int nt = 0; nt < 16; nt++) {
            oacc[nt][0] *= rs0; oacc[nt][1] *= rs0;
            oacc[nt][2] *= rs1; oacc[nt][3] *= rs1;
        }

#pragma unroll
        for (int kc = 0; kc < 8; kc++) {
            uint32_t pa[4];
            pa[0] = pack_h2(s[2 * kc][0], s[2 * kc][1]);
            pa[1] = pack_h2(s[2 * kc][2], s[2 * kc][3]);
            pa[2] = pack_h2(s[2 * kc + 1][0], s[2 * kc + 1][1]);
            pa[3] = pack_h2(s[2 * kc + 1][2], s[2 * kc + 1][3]);
#pragma unroll
            for (int p = 0; p < 8; p++) {
                uint32_t tmp[4];
                ldsm_x4_t(tmp, smem_u32(vb + (kc * 16 + l15) * 136 + p * 16 + lhi));
                mma_f16(oacc[2 * p], pa, tmp);
                mma_f16(oacc[2 * p + 1], pa, tmp + 2);
            }
        }
        __syncthreads();
    }

    float inv0 = 1.f / l0, inv1 = 1.f / l1;
    __half* og = O + (long long)(qb * 128) * H + h * D;
    int r0 = wm + fr, r1 = r0 + 8;
#pragma unroll
    for (int nt = 0; nt < 16; nt++) {
        int col = nt * 8 + 2 * fc;
        *(half2*)(og + (long long)r0 * H + col) =
            __floats2half2_rn(oacc[nt][0] * inv0, oacc[nt][1] * inv0);
        *(half2*)(og + (long long)r1 * H + col) =
            __floats2half2_rn(oacc[nt][2] * inv1, oacc[nt][3] * inv1);
    }
}
#define FLASH_SMEM ((128 + 256 + 256) * 136 * 2)

// ---------------- fp32 -> fp16 ----------------
__global__ void f2h_kernel(const float* __restrict__ in, __half* __restrict__ out, long long n) {
    long long i = (long long)blockIdx.x * 1024 + threadIdx.x * 4;
    for (; i + 3 < n; i += (long long)gridDim.x * 1024) {
        float4 v = *(const float4*)&in[i];
        *(half2*)&out[i] = __floats2half2_rn(v.x, v.y);
        *(half2*)&out[i + 2] = __floats2half2_rn(v.z, v.w);
    }
}

// ---------------- RMSNorm ----------------
__global__ void rmsnorm_kernel(const float* __restrict__ x, const float* __restrict__ w,
                               __half* __restrict__ oh, float* __restrict__ of) {
    int s = blockIdx.x;
    const float* xr = x + (long long)s * H;
    int tid = threadIdx.x;
    float ss = 0.f;
    for (int i = tid; i < H; i += 256) { float v = xr[i]; ss += v * v; }
    __shared__ float sh[8];
#pragma unroll
    for (int off = 16; off; off >>= 1) ss += __shfl_xor_sync(0xffffffffu, ss, off);
    if ((tid & 31) == 0) sh[tid >> 5] = ss;
    __syncthreads();
    ss = sh[tid & 7];
#pragma unroll
    for (int off = 4; off; off >>= 1) ss += __shfl_xor_sync(0xffffffffu, ss, off);
    float inv = rsqrtf(ss / (float)H + 1e-6f);
    for (int i = tid; i < H; i += 256) {
        float v = w[i] * xr[i] * inv;
        oh[(long long)s * H + i] = __float2half_rn(v);
        if (of) of[(long long)s * H + i] = v;
    }
}

// ---------------- RoPE ----------------
__global__ void rope_kernel(__half* __restrict__ q, __half* __restrict__ k) {
    int s = blockIdx.x, h = blockIdx.y, d = threadIdx.x;
    double invd = exp(-((double)(2 * d) / 128.0) * 13.815510557964274);
    float inv = (float)invd;
    float ang = (float)s * inv;
    float c = cosf(ang), sn = sinf(ang);
    long long base = ((long long)s * NH + h) * D;
    float q1 = __half2float(q[base + d]), q2 = __half2float(q[base + d + 64]);
    q[base + d] = __float2half_rn(q1 * c - q2 * sn);
    q[base + d + 64] = __float2half_rn(q2 * c + q1 * sn);
    float k1 = __half2float(k[base + d]), k2 = __half2float(k[base + d + 64]);
    k[base + d] = __float2half_rn(k1 * c - k2 * sn);
    k[base + d + 64] = __float2half_rn(k2 * c + k1 * sn);
}

// ---------------- zero counters ----------------
__global__ void zero_cnt_kernel(int* cnt) {
    if (threadIdx.x < NE) cnt[threadIdx.x] = 0;
}

// ---------------- router + top-k compaction ----------------
__global__ void router_kernel(const float* __restrict__ h2, const float* __restrict__ gw,
                              const float* __restrict__ sgate, float* __restrict__ rl,
                              float* __restrict__ sgl, int* __restrict__ cnt,
                              int* __restrict__ glist, int* __restrict__ slot,
                              float* __restrict__ wt4) {
    int s = blockIdx.x;
    int tid = threadIdx.x;
    const float* hr = h2 + (long long)s * H;
    float acc[9];
#pragma unroll
    for (int j = 0; j < 9; j++) acc[j] = 0.f;
    for (int i = tid; i < H; i += 256) {
        float hv = hr[i];
        const float* gr = gw + (long long)i * NE;
#pragma unroll
        for (int e = 0; e < NE; e++) acc[e] += hv * gr[e];
        acc[8] += hv * sgate[i];
    }
    __shared__ float sh[8][9];
    int warp = tid >> 5, lane = tid & 31;
#pragma unroll
    for (int j = 0; j < 9; j++) {
        float v = acc[j];
#pragma unroll
        for (int o = 16; o; o >>= 1) v += __shfl_xor_sync(0xffffffffu, v, o);
        if (lane == 0) sh[warp][j] = v;
    }
    __syncthreads();
    if (tid == 0) {
        float t[9];
#pragma unroll
        for (int j = 0; j < 9; j++) {
            float v = 0.f;
            for (int wi = 0; wi < 8; wi++) v += sh[wi][j];
            t[j] = v;
        }
        float mx = t[0];
        for (int e = 1; e < NE; e++) mx = fmaxf(mx, t[e]);
        float p[NE], sum = 0.f;
        for (int e = 0; e < NE; e++) { p[e] = expf(t[e] - mx); sum += p[e]; }
        for (int e = 0; e < NE; e++) p[e] /= sum;
        for (int kI = 0; kI < TOPK; kI++) {
            int bi = 0;
            float bv = p[0];
            for (int e = 1; e < NE; e++)
                if (p[e] > bv) { bv = p[e]; bi = e; }
            int pos = atomicAdd(&cnt[bi], 1);
            glist[bi * S + pos] = s;
            slot[s * TOPK + kI] = bi * S + pos;
            wt4[s * TOPK + kI] = bv;
            p[bi] = -1.f;
        }
        for (int e = 0; e < NE; e++) rl[s * NE + e] = t[e];
        sgl[s] = t[8];
    }
}

// ---------------- final combine ----------------
__global__ void final_kernel(const float* __restrict__ x2, const float* __restrict__ eo,
                             const int* __restrict__ slot, const float* __restrict__ wt4,
                             const float* __restrict__ sm, const float* __restrict__ sgl,
                             float* __restrict__ out) {
    int i = blockIdx.x * 256 + threadIdx.x;
    int s = i >> 11, c = i & 2047;
    float mo = 0.f;
#pragma unroll
    for (int kI = 0; kI < TOPK; kI++)
        mo += wt4[s * TOPK + kI] * eo[(long long)slot[s * TOPK + kI] * H + c];
    float gg = 1.f / (1.f + expf(-sgl[s]));
    out[i] = x2[i] + mo + gg * sm[i];
}

// ---------------- host ----------------
extern "C" void kernel_launch(void* const* d_in, const int* in_sizes, int n_in,
                              void* d_out, int out_size) {
    const float* x = (const float*)d_in[0];
    const float* ln1 = (const float*)d_in[1];
    const float* ln2 = (const float*)d_in[2];
    const float* wq = (const float*)d_in[3];
    const float* bq = (const float*)d_in[4];
    const float* wk = (const float*)d_in[5];
    const float* bk = (const float*)d_in[6];
    const float* wv = (const float*)d_in[7];
    const float* bv = (const float*)d_in[8];
    const float* wo = (const float*)d_in[9];
    const float* gw = (const float*)d_in[10];
    const float* eg = (const float*)d_in[11];
    const float* eu = (const float*)d_in[12];
    const float* ed = (const float*)d_in[13];
    const float* sg = (const float*)d_in[14];
    const float* su = (const float*)d_in[15];
    const float* sd = (const float*)d_in[16];
    const float* sgate = (const float*)d_in[17];
    float* out = (float*)d_out;

    float *x2, *h2f, *eo, *sm, *sgl, *rls, *wt4;
    int *cnt, *glist, *slot;
    __half *h1h, *qh, *kh, *vh, *ath, *h2h, *ghh, *uhh, *ssg, *ssh;
    __half *wqh, *wkh, *wvh, *woh, *egh, *euh, *edh, *sgw, *suw, *sdw;
    cudaGetSymbolAddress((void**)&x2, g_x2);
    cudaGetSymbolAddress((void**)&h2f, g_h2f);
    cudaGetSymbolAddress((void**)&eo, g_eo);
    cudaGetSymbolAddress((void**)&sm, g_sm);
    cudaGetSymbolAddress((void**)&sgl, g_sgl);
    cudaGetSymbolAddress((void**)&rls, g_rl);
    cudaGetSymbolAddress((void**)&wt4, g_wt4);
    cudaGetSymbolAddress((void**)&cnt, g_cnt);
    cudaGetSymbolAddress((void**)&glist, g_glist);
    cudaGetSymbolAddress((void**)&slot, g_slot);
    cudaGetSymbolAddress((void**)&h1h, g_h1h);
    cudaGetSymbolAddress((void**)&qh, g_qh);
    cudaGetSymbolAddress((void**)&kh, g_kh);
    cudaGetSymbolAddress((void**)&vh, g_vh);
    cudaGetSymbolAddress((void**)&ath, g_ath);
    cudaGetSymbolAddress((void**)&h2h, g_h2h);
    cudaGetSymbolAddress((void**)&ghh, g_ghh);
    cudaGetSymbolAddress((void**)&uhh, g_uhh);
    cudaGetSymbolAddress((void**)&ssg, g_ssg);
    cudaGetSymbolAddress((void**)&ssh, g_ssh);
    cudaGetSymbolAddress((void**)&wqh, g_wqh);
    cudaGetSymbolAddress((void**)&wkh, g_wkh);
    cudaGetSymbolAddress((void**)&wvh, g_wvh);
    cudaGetSymbolAddress((void**)&woh, g_woh);
    cudaGetSymbolAddress((void**)&egh, g_egh);
    cudaGetSymbolAddress((void**)&euh, g_euh);
    cudaGetSymbolAddress((void**)&edh, g_edh);
    cudaGetSymbolAddress((void**)&sgw, g_sgw);
    cudaGetSymbolAddress((void**)&suw, g_suw);
    cudaGetSymbolAddress((void**)&sdw, g_sdw);

    cudaFuncSetAttribute(flash_kernel, cudaFuncAttributeMaxDynamicSharedMemorySize, FLASH_SMEM);
    cudaFuncSetAttribute(hgemm<1, true, 0>, cudaFuncAttributeMaxDynamicSharedMemorySize, SMEM_G);
    cudaFuncSetAttribute(hgemm<2, false, 0>, cudaFuncAttributeMaxDynamicSharedMemorySize, SMEM_G);
    cudaFuncSetAttribute(hgemm<0, true, 1>, cudaFuncAttributeMaxDynamicSharedMemorySize, SMEM_G);
    cudaFuncSetAttribute(hgemm<3, true, 1>, cudaFuncAttributeMaxDynamicSharedMemorySize, SMEM_G);
    cudaFuncSetAttribute(hgemm<0, false, 2>, cudaFuncAttributeMaxDynamicSharedMemorySize, SMEM_G);
    cudaFuncSetAttribute(hgemm<0, true, 0>, cudaFuncAttributeMaxDynamicSharedMemorySize, SMEM_G);
    cudaFuncSetAttribute(hgemm<3, true, 0>, cudaFuncAttributeMaxDynamicSharedMemorySize, SMEM_G);
    cudaFuncSetAttribute(hgemm<0, false, 0>, cudaFuncAttributeMaxDynamicSharedMemorySize, SMEM_G);

    static cudaStream_t s2 = 0, s3 = 0;
    static cudaEvent_t evFork = 0, evW0 = 0, evW = 0, evH2 = 0, evSh = 0;
    if (!s2) {
        cudaStreamCreateWithFlags(&s2, cudaStreamNonBlocking);
        cudaStreamCreateWithFlags(&s3, cudaStreamNonBlocking);
        cudaEventCreateWithFlags(&evFork, cudaEventDisableTiming);
        cudaEventCreateWithFlags(&evW0, cudaEventDisableTiming);
        cudaEventCreateWithFlags(&evW, cudaEventDisableTiming);
        cudaEventCreateWithFlags(&evH2, cudaEventDisableTiming);
        cudaEventCreateWithFlags(&evSh, cudaEventDisableTiming);
    }

    float* rl_dst = (out_size >= S * H + S * NE) ? (out + (size_t)S * H) : rls;

    // ---- fork conversion stream ----
    cudaEventRecord(evFork, 0);
    cudaStreamWaitEvent(s2, evFork, 0);
    f2h_kernel<<<2048, 256, 0, s2>>>(wq, wqh, (long long)H * H);
    f2h_kernel<<<2048, 256, 0, s2>>>(wk, wkh, (long long)H * H);
    f2h_kernel<<<2048, 256, 0, s2>>>(wv, wvh, (long long)H * H);
    f2h_kernel<<<2048, 256, 0, s2>>>(wo, woh, (long long)H * H);
    cudaEventRecord(evW0, s2);
    f2h_kernel<<<4096, 256, 0, s2>>>(eg, egh, (long long)NE * H * IE);
    f2h_kernel<<<4096, 256, 0, s2>>>(eu, euh, (long long)NE * H * IE);
    f2h_kernel<<<4096, 256, 0, s2>>>(sg, sgw, (long long)H * IS);
    f2h_kernel<<<4096, 256, 0, s2>>>(su, suw, (long long)H * IS);
    f2h_kernel<<<4096, 256, 0, s2>>>(ed, edh, (long long)NE * IE * H);
    f2h_kernel<<<4096, 256, 0, s2>>>(sd, sdw, (long long)IS * H);
    cudaEventRecord(evW, s2);

    // ---- main stream: attention path ----
    rmsnorm_kernel<<<S, 256>>>(x, ln1, h1h, (float*)0);
    cudaStreamWaitEvent(0, evW0, 0);
    {
        dim3 g(16, 16, 1);
        hgemm<1, true, 0><<<g, 256, SMEM_G>>>(h1h, wqh, qh, bq, (const __half*)0, 0, 0, H, H, H, H, 0, 0, 0);
        hgemm<1, true, 0><<<g, 256, SMEM_G>>>(h1h, wkh, kh, bk, (const __half*)0, 0, 0, H, H, H, H, 0, 0, 0);
        hgemm<1, true, 0><<<g, 256, SMEM_G>>>(h1h, wvh, vh, bv, (const __half*)0, 0, 0, H, H, H, H, 0, 0, 0);
    }
    rope_kernel<<<dim3(S, NH), 64>>>(qh, kh);
    flash_kernel<<<dim3(16, NH), 256, FLASH_SMEM>>>(qh, kh, vh, ath);
    hgemm<2, false, 0><<<dim3(16, 16, 1), 256, SMEM_G>>>(
        ath, woh, x2, x, (const __half*)0, 0, 0, H, H, H, H, 0, 0, 0);
    rmsnorm_kernel<<<S, 256>>>(x2, ln2, h2h, h2f);
    cudaEventRecord(evH2, 0);   // h2h ready — shared branch can start now
    zero_cnt_kernel<<<1, 32>>>(cnt);
    router_kernel<<<S, 256>>>(h2f, gw, sgate, rl_dst, sgl, cnt, glist, slot, wt4);

    // ---- stream s3: shared MLP branch ----
    cudaStreamWaitEvent(s3, evH2, 0);
    cudaStreamWaitEvent(s3, evW, 0);
    {
        dim3 g(IS / 128, 16, 1);
        hgemm<0, true, 0><<<g, 256, SMEM_G, s3>>>(h2h, sgw, ssg, (const float*)0, (const __half*)0,
            0, 0, H, H, IS, IS, 0, 0, 0);
        hgemm<3, true, 0><<<g, 256, SMEM_G, s3>>>(h2h, suw, ssh, (const float*)0, ssg,
            0, 0, H, H, IS, IS, 0, 0, 0);
        hgemm<0, false, 0><<<dim3(16, 16, 1), 256, SMEM_G, s3>>>(ssh, sdw, sm, (const float*)0,
            (const __half*)0, 0, 0, IS, IS, H, H, 0, 0, 0);
    }
    cudaEventRecord(evSh, s3);

    // ---- main stream: sparse MoE branch ----
    cudaStreamWaitEvent(0, evW, 0);
    {
        dim3 g(IE / 128, 16, NE);
        hgemm<0, true, 1><<<g, 256, SMEM_G>>>(h2h, egh, ghh, (const float*)0, (const __half*)0,
            glist, cnt, H, H, IE, IE, 0LL, (long long)H * IE, (long long)S * IE);
        hgemm<3, true, 1><<<g, 256, SMEM_G>>>(h2h, euh, uhh, (const float*)0, ghh,
            glist, cnt, H, H, IE, IE, 0LL, (long long)H * IE, (long long)S * IE);
    }
    hgemm<0, false, 2><<<dim3(16, 16, NE), 256, SMEM_G>>>(uhh, edh, eo, (const float*)0,
        (const __half*)0, (const int*)0, cnt, IE, IE, H, H,
        (long long)S * IE, (long long)IE * H, (long long)S * H);

    // ---- join + combine ----
    cudaStreamWaitEvent(0, evSh, 0);
    final_kernel<<<(S * H) / 256, 256>>>(x2, eo, slot, wt4, sm, sgl, out);
}

// round 10
// speedup vs baseline: 3.0526x; 1.0683x over previous
#include <cuda_runtime.h>
#include <cuda_fp16.h>
#include <cstdint>
#include <math.h>

#define S 2048
#define H 2048
#define NH 16
#define D 128
#define NE 8
#define TOPK 4
#define IE 1408
#define IS 5632

// ---------------- fp32 scratch ----------------
static __device__ float g_x2[S * H];
static __device__ float g_h2f[S * H];
static __device__ float g_sm[S * H];
static __device__ float g_sgl[S];
static __device__ float g_rl[S * NE];
static __device__ float g_wsl[NE * S];
static __device__ float g_bqkv[3 * H];
static __device__ int g_cnt[NE];
static __device__ int g_glist[NE * S];
static __device__ int g_slot[S * TOPK];
// ---------------- half scratch ----------------
static __device__ __half g_h1h[S * H];
static __device__ __half g_qkvh[(long long)3 * S * H];
static __device__ __half g_ath[S * H];
static __device__ __half g_h2h[S * H];
static __device__ __half g_ghh[(long long)NE * S * IE];
static __device__ __half g_uhh[(long long)NE * S * IE];
static __device__ __half g_eoh[(long long)NE * S * H];
static __device__ __half g_ssg[(long long)S * IS];
static __device__ __half g_ssh[(long long)S * IS];
// half weights
static __device__ __half g_wqkvh[(long long)3 * H * H];
static __device__ __half g_woh[H * H];
static __device__ __half g_egh[(long long)NE * H * IE];
static __device__ __half g_euh[(long long)NE * H * IE];
static __device__ __half g_edh[(long long)NE * IE * H];
static __device__ __half g_sgw[(long long)H * IS];
static __device__ __half g_suw[(long long)H * IS];
static __device__ __half g_sdw[(long long)IS * H];

// ---------------- helpers ----------------
__device__ __forceinline__ uint32_t smem_u32(const void* p) {
    uint32_t a;
    asm("{ .reg .u64 t; cvta.to.shared.u64 t, %1; cvt.u32.u64 %0, t; }" : "=r"(a) : "l"(p));
    return a;
}
__device__ __forceinline__ void cp16(uint32_t dst, const void* src) {
    asm volatile("cp.async.cg.shared.global [%0], [%1], 16;" :: "r"(dst), "l"(src));
}
#define CP_COMMIT() asm volatile("cp.async.commit_group;" ::: "memory")
#define CP_WAIT2() asm volatile("cp.async.wait_group 2;" ::: "memory")
#define CP_WAIT1() asm volatile("cp.async.wait_group 1;" ::: "memory")
#define CP_WAIT0() asm volatile("cp.async.wait_group 0;" ::: "memory")

__device__ __forceinline__ void ldsm_x4(uint32_t* r, uint32_t addr) {
    asm volatile("ldmatrix.sync.aligned.m8n8.x4.shared.b16 {%0,%1,%2,%3}, [%4];"
        : "=r"(r[0]), "=r"(r[1]), "=r"(r[2]), "=r"(r[3]) : "r"(addr));
}
__device__ __forceinline__ void ldsm_x4_t(uint32_t* r, uint32_t addr) {
    asm volatile("ldmatrix.sync.aligned.m8n8.x4.trans.shared.b16 {%0,%1,%2,%3}, [%4];"
        : "=r"(r[0]), "=r"(r[1]), "=r"(r[2]), "=r"(r[3]) : "r"(addr));
}
__device__ __forceinline__ void mma_f16(float* d, const uint32_t* a, const uint32_t* b) {
    asm volatile(
        "mma.sync.aligned.m16n8k16.row.col.f32.f16.f16.f32 "
        "{%0,%1,%2,%3}, {%4,%5,%6,%7}, {%8,%9}, {%0,%1,%2,%3};"
        : "+f"(d[0]), "+f"(d[1]), "+f"(d[2]), "+f"(d[3])
        : "r"(a[0]), "r"(a[1]), "r"(a[2]), "r"(a[3]), "r"(b[0]), "r"(b[1]));
}
__device__ __forceinline__ uint32_t pack_h2(float a, float b) {
    half2 h = __floats2half2_rn(a, b);
    return *(uint32_t*)&h;
}

// ---------------- fp16 mma GEMM (128x128 CTA, 8 warps 64x32, K-stage 32, 3-deep pipe) ---
// EPI: 0 none, 1 +bias[z*2048+col], 2 +resid, 3 silu(Xh)*acc, 4 acc*X[z*S+row] (wsl).
// OUTH: half out. IDX: 0 none, 1 gather A via glist+bound, 2 bound only.
#define A_ELT 5120
#define B_ELT 4352
#define SMEM_G ((3 * (A_ELT + B_ELT)) * 2)

template <int EPI, bool OUTH, int IDX>
__global__ void __launch_bounds__(256, 2)
hgemm(const __half* __restrict__ A, const __half* __restrict__ B,
      void* __restrict__ Cv, const float* __restrict__ X, const __half* __restrict__ Xh,
      const int* __restrict__ glist, const int* __restrict__ cnt,
      int K, int lda, int ldb, int ldc,
      long long sA, long long sB, long long sC) {
    int cbound = 0x7fffffff;
    if (IDX) {
        cbound = cnt[blockIdx.z];
        if ((int)blockIdx.y * 128 >= cbound) return;
    }
    extern __shared__ __half dsm[];
    __half* const AS = dsm;
    __half* const BS = dsm + 3 * A_ELT;

    int tid = threadIdx.x, lane = tid & 31, wid = tid >> 5;
    int row0 = blockIdx.y * 128, col0 = blockIdx.x * 128;

    A += (long long)blockIdx.z * sA;
    if (IDX != 1) A += (long long)row0 * lda;
    B += (long long)blockIdx.z * sB + col0;

    int nstg = K >> 5;

    int arow = tid >> 2, acol = (tid & 3) * 8;
    int nrow = tid >> 4, ncol = (tid & 15) * 8;

    const __half* aptr[2];
#pragma unroll
    for (int i = 0; i < 2; i++) {
        int r = arow + i * 64;
        if (IDX == 1) {
            int gr = row0 + r;
            int ti = glist[blockIdx.z * S + (gr < cbound ? gr : 0)];
            aptr[i] = A + (long long)ti * lda;
        } else {
            aptr[i] = A + (long long)r * lda;
        }
    }

    auto fill = [&](int s, int k0) {
        __half* ad = AS + s * A_ELT;
        __half* bd = BS + s * B_ELT;
#pragma unroll
        for (int i = 0; i < 2; i++)
            cp16(smem_u32(ad + (arow + i * 64) * 40 + acol), aptr[i] + k0 + acol);
#pragma unroll
        for (int i = 0; i < 2; i++)
            cp16(smem_u32(bd + (nrow + i * 16) * 136 + ncol),
                 B + (long long)(k0 + nrow + i * 16) * ldb + ncol);
        CP_COMMIT();
    };

    float acc[4][4][4];
#pragma unroll
    for (int i = 0; i < 4; i++)
#pragma unroll
        for (int j = 0; j < 4; j++)
#pragma unroll
            for (int u = 0; u < 4; u++) acc[i][j][u] = 0.f;

    int wm = (wid & 1) * 64, wn = (wid >> 1) * 32;
    int fr = lane >> 2, fc = lane & 3;
    int l15 = lane & 15, lhi = (lane >> 4) << 3;

    fill(0, 0);
    if (nstg > 1) fill(1, 32);

    for (int t = 0; t < nstg; t++) {
        if (t + 2 < nstg) { fill((t + 2) % 3, (t + 2) * 32); CP_WAIT2(); }
        else if (t + 1 < nstg) CP_WAIT1();
        else CP_WAIT0();
        __syncthreads();
        const __half* as = AS + (t % 3) * A_ELT;
        const __half* bs = BS + (t % 3) * B_ELT;
#pragma unroll
        for (int kk = 0; kk < 32; kk += 16) {
            uint32_t af[4][4];
#pragma unroll
            for (int mt = 0; mt < 4; mt++)
                ldsm_x4(af[mt], smem_u32(as + (wm + mt * 16 + l15) * 40 + kk + lhi));
            uint32_t bf[4][2];
#pragma unroll
            for (int p = 0; p < 2; p++) {
                uint32_t tmp[4];
                ldsm_x4_t(tmp, smem_u32(bs + (kk + l15) * 136 + wn + p * 16 + lhi));
                bf[2 * p][0] = tmp[0]; bf[2 * p][1] = tmp[1];
                bf[2 * p + 1][0] = tmp[2]; bf[2 * p + 1][1] = tmp[3];
            }
#pragma unroll
            for (int mt = 0; mt < 4; mt++)
#pragma unroll
                for (int nt = 0; nt < 4; nt++) mma_f16(acc[mt][nt], af[mt], bf[nt]);
        }
        __syncthreads();
    }

    const __half* XhB = (EPI == 3) ? Xh + (long long)blockIdx.z * sC : (const __half*)0;
#pragma unroll
    for (int mt = 0; mt < 4; mt++) {
        int m = row0 + wm + mt * 16 + fr;
        float w0 = 1.f, w1 = 1.f;
        if (EPI == 4) {
            bool ok0 = (!IDX || m < cbound), ok1 = (!IDX || m + 8 < cbound);
            w0 = ok0 ? X[(long long)blockIdx.z * S + m] : 0.f;
            w1 = ok1 ? X[(long long)blockIdx.z * S + m + 8] : 0.f;
        }
#pragma unroll
        for (int nt = 0; nt < 4; nt++) {
            int n = col0 + wn + nt * 8 + fc * 2;
            float2 v0 = make_float2(acc[mt][nt][0], acc[mt][nt][1]);
            float2 v1 = make_float2(acc[mt][nt][2], acc[mt][nt][3]);
            if (EPI == 1) {
                const float* bz = X + (long long)blockIdx.z * 2048;
                v0.x += bz[n]; v0.y += bz[n + 1];
                v1.x += bz[n]; v1.y += bz[n + 1];
            }
            if (EPI == 2) {
                const float2 r0 = *(const float2*)&X[(long long)m * ldc + n];
                const float2 r1 = *(const float2*)&X[(long long)(m + 8) * ldc + n];
                v0.x += r0.x; v0.y += r0.y;
                v1.x += r1.x; v1.y += r1.y;
            }
            if (EPI == 3) {
                bool ok0 = (!IDX || m < cbound), ok1 = (!IDX || m + 8 < cbound);
                if (ok0) {
                    half2 gh = *(const half2*)&XhB[(long long)m * ldc + n];
                    float gx = __half2float(gh.x), gy = __half2float(gh.y);
                    v0.x *= gx / (1.f + expf(-gx));
                    v0.y *= gy / (1.f + expf(-gy));
                }
                if (ok1) {
                    half2 gh = *(const half2*)&XhB[(long long)(m + 8) * ldc + n];
                    float gx = __half2float(gh.x), gy = __half2float(gh.y);
                    v1.x *= gx / (1.f + expf(-gx));
                    v1.y *= gy / (1.f + expf(-gy));
                }
            }
            if (EPI == 4) {
                v0.x *= w0; v0.y *= w0;
                v1.x *= w1; v1.y *= w1;
            }
            if (OUTH) {
                __half* C = (__half*)Cv + (long long)blockIdx.z * sC;
                if (!IDX || m < cbound)
                    *(half2*)&C[(long long)m * ldc + n] = __floats2half2_rn(v0.x, v0.y);
                if (!IDX || m + 8 < cbound)
                    *(half2*)&C[(long long)(m + 8) * ldc + n] = __floats2half2_rn(v1.x, v1.y);
            } else {
                float* C = (float*)Cv + (long long)blockIdx.z * sC;
                if (!IDX || m < cbound)
                    *(float2*)&C[(long long)m * ldc + n] = v0;
                if (!IDX || m + 8 < cbound)
                    *(float2*)&C[(long long)(m + 8) * ldc + n] = v1;
            }
        }
    }
}

// ---------------- flash attention ----------------
#define FSC 0.12751744f
__global__ void __launch_bounds__(256, 1)
flash_kernel(const __half* __restrict__ Q, const __half* __restrict__ K,
             const __half* __restrict__ V, __half* __restrict__ O) {
    int qb = 15 - (int)blockIdx.x;
    int h = blockIdx.y;
    extern __shared__ __half fsm[];
    __half* Qs = fsm;
    __half* Ks = fsm + 128 * 136;
    __half* Vs = Ks + 2 * 128 * 136;

    int tid = threadIdx.x, lane = tid & 31, wid = tid >> 5;
    int fr = lane >> 2, fc = lane & 3;
    int l15 = lane & 15, lhi = (lane >> 4) << 3;
    int wm = wid * 16;

    const __half* qg = Q + (long long)(qb * 128) * H + h * D;
    const __half* kg = K + h * D;
    const __half* vg = V + h * D;

    int lr = tid >> 1, lc = (tid & 1) * 64;
#pragma unroll
    for (int j = 0; j < 8; j++)
        cp16(smem_u32(Qs + lr * 136 + lc + j * 8), qg + (long long)lr * H + lc + j * 8);

    auto loadKV = [&](int buf, int kt) {
        const __half* ks = kg + (long long)(kt * 128) * H;
        const __half* vs = vg + (long long)(kt * 128) * H;
        __half* kd = Ks + buf * (128 * 136);
        __half* vd = Vs + buf * (128 * 136);
#pragma unroll
        for (int j = 0; j < 8; j++) {
            cp16(smem_u32(kd + lr * 136 + lc + j * 8), ks + (long long)lr * H + lc + j * 8);
            cp16(smem_u32(vd + lr * 136 + lc + j * 8), vs + (long long)lr * H + lc + j * 8);
        }
    };
    loadKV(0, 0); CP_COMMIT();

    float oacc[16][4];
#pragma unroll
    for (int i = 0; i < 16; i++)
#pragma unroll
        for (int u = 0; u < 4; u++) oacc[i][u] = 0.f;
    float m0 = -1e30f, m1 = -1e30f, l0 = 0.f, l1 = 0.f;

    int ntile = qb + 1;
    for (int t = 0; t < ntile; t++) {
        if (t + 1 < ntile) { loadKV((t + 1) & 1, t + 1); CP_COMMIT(); CP_WAIT1(); }
        else CP_WAIT0();
        __syncthreads();
        const __half* kb = Ks + (t & 1) * (128 * 136);
        const __half* vb = Vs + (t & 1) * (128 * 136);

        float s[16][4];
#pragma unroll
        for (int i = 0; i < 16; i++)
#pragma unroll
            for (int u = 0; u < 4; u++) s[i][u] = 0.f;

#pragma unroll
        for (int kk = 0; kk < 8; kk++) {
            uint32_t aq[4];
            ldsm_x4(aq, smem_u32(Qs + (wm + l15) * 136 + kk * 16 + lhi));
#pragma unroll
            for (int nt = 0; nt < 16; nt++) {
                uint32_t bk[2];
                bk[0] = *(const uint32_t*)(kb + (nt * 8 + fr) * 136 + kk * 16 + 2 * fc);
                bk[1] = *(const uint32_t*)(kb + (nt * 8 + fr) * 136 + kk * 16 + 2 * fc + 8);
                mma_f16(s[nt], aq, bk);
            }
        }

        if (t == qb) {
            int r0 = wm + fr, r1 = r0 + 8;
#pragma unroll
            for (int nt = 0; nt < 16; nt++) {
                int c0 = nt * 8 + 2 * fc;
                if (c0 > r0) s[nt][0] = -1e30f;
                if (c0 + 1 > r0) s[nt][1] = -1e30f;
                if (c0 > r1) s[nt][2] = -1e30f;
                if (c0 + 1 > r1) s[nt][3] = -1e30f;
            }
        }

        float mx0 = -1e30f, mx1 = -1e30f;
#pragma unroll
        for (int nt = 0; nt < 16; nt++) {
            mx0 = fmaxf(mx0, fmaxf(s[nt][0], s[nt][1]));
            mx1 = fmaxf(mx1, fmaxf(s[nt][2], s[nt][3]));
        }
        mx0 = fmaxf(mx0, __shfl_xor_sync(0xffffffffu, mx0, 1));
        mx0 = fmaxf(mx0, __shfl_xor_sync(0xffffffffu, mx0, 2));
        mx1 = fmaxf(mx1, __shfl_xor_sync(0xffffffffu, mx1, 1));
        mx1 = fmaxf(mx1, __shfl_xor_sync(0xffffffffu, mx1, 2));

        float mn0 = fmaxf(m0, mx0), mn1 = fmaxf(m1, mx1);
        float rs0 = exp2f((m0 - mn0) * FSC), rs1 = exp2f((m1 - mn1) * FSC);
        m0 = mn0; m1 = mn1;

        float sm0 = 0.f, sm1 = 0.f;
#pragma unroll
        for (int nt = 0; nt < 16; nt++) {
            s[nt][0] = exp2f((s[nt][0] - m0) * FSC);
            s[nt][1] = exp2f((s[nt][1] - m0) * FSC);
            s[nt][2] = exp2f((s[nt][2] - m1) * FSC);
            s[nt][3] = exp2f((s[nt][3] - m1) * FSC);
            sm0 += s[nt][0] + s[nt][1];
            sm1 += s[nt][2] + s[nt][3];
        }
        sm0 += __shfl_xor_sync(0xffffffffu, sm0, 1);
        sm0 += __shfl_xor_sync(0xffffffffu, sm0, 2);
        sm1 += __shfl_xor_sync(0xffffffffu, sm1, 1);
        sm1 += __shfl_xor_sync(0xffffffffu, sm1, 2);
        l0 = l0 * rs0 + sm0;
        l1 = l1 * rs1 + sm1;
#pragma unroll
        for (int nt = 0; nt < 16; nt++) {
            oacc[nt][0] *= rs0; oacc[nt][1] *= rs0;
            oacc[nt][2] *= rs1; oacc[nt][3] *= rs1;
        }

#pragma unroll
        for (int kc = 0; kc < 8; kc++) {
            uint32_t pa[4];
            pa[0] = pack_h2(s[2 * kc][0], s[2 * kc][1]);
            pa[1] = pack_h2(s[2 * kc][2], s[2 * kc][3]);
            pa[2] = pack_h2(s[2 * kc + 1][0], s[2 * kc + 1][1]);
            pa[3] = pack_h2(s[2 * kc + 1][2], s[2 * kc + 1][3]);
#pragma unroll
            for (int p = 0; p < 8; p++) {
                uint32_t tmp[4];
                ldsm_x4_t(tmp, smem_u32(vb + (kc * 16 + l15) * 136 + p * 16 + lhi));
                mma_f16(oacc[2 * p], pa, tmp);
                mma_f16(oacc[2 * p + 1], pa, tmp + 2);
            }
        }
        __syncthreads();
    }

    float inv0 = 1.f / l0, inv1 = 1.f / l1;
    __half* og = O + (long long)(qb * 128) * H + h * D;
    int r0 = wm + fr, r1 = r0 + 8;
#pragma unroll
    for (int nt = 0; nt < 16; nt++) {
        int col = nt * 8 + 2 * fc;
        *(half2*)(og + (long long)r0 * H + col) =
            __floats2half2_rn(oacc[nt][0] * inv0, oacc[nt][1] * inv0);
        *(half2*)(og + (long long)r1 * H + col) =
            __floats2half2_rn(oacc[nt][2] * inv1, oacc[nt][3] * inv1);
    }
}
#define FLASH_SMEM ((128 + 256 + 256) * 136 * 2)

// ---------------- fp32 -> fp16 ----------------
__global__ void f2h_kernel(const float* __restrict__ in, __half* __restrict__ out, long long n) {
    long long i = (long long)blockIdx.x * 1024 + threadIdx.x * 4;
    for (; i + 3 < n; i += (long long)gridDim.x * 1024) {
        float4 v = *(const float4*)&in[i];
        *(half2*)&out[i] = __floats2half2_rn(v.x, v.y);
        *(half2*)&out[i + 2] = __floats2half2_rn(v.z, v.w);
    }
}

// ---------------- pack 3 bias vectors ----------------
__global__ void bcopy_kernel(const float* a, const float* b, const float* c, float* o) {
    int i = blockIdx.x * 1024 + threadIdx.x;  // 6 blocks x 1024
    const float* src[3] = {a, b, c};
    o[i] = src[i >> 11][i & 2047];
}

// ---------------- RMSNorm ----------------
__global__ void rmsnorm_kernel(const float* __restrict__ x, const float* __restrict__ w,
                               __half* __restrict__ oh, float* __restrict__ of,
                               int* __restrict__ zcnt) {
    int s = blockIdx.x;
    if (zcnt && s == 0 && threadIdx.x < NE) zcnt[threadIdx.x] = 0;
    const float* xr = x + (long long)s * H;
    int tid = threadIdx.x;
    float ss = 0.f;
    for (int i = tid; i < H; i += 256) { float v = xr[i]; ss += v * v; }
    __shared__ float sh[8];
#pragma unroll
    for (int off = 16; off; off >>= 1) ss += __shfl_xor_sync(0xffffffffu, ss, off);
    if ((tid & 31) == 0) sh[tid >> 5] = ss;
    __syncthreads();
    ss = sh[tid & 7];
#pragma unroll
    for (int off = 4; off; off >>= 1) ss += __shfl_xor_sync(0xffffffffu, ss, off);
    float inv = rsqrtf(ss / (float)H + 1e-6f);
    for (int i = tid; i < H; i += 256) {
        float v = w[i] * xr[i] * inv;
        oh[(long long)s * H + i] = __float2half_rn(v);
        if (of) of[(long long)s * H + i] = v;
    }
}

// ---------------- RoPE: 1 block per seq position, smem cos/sin ----------------
__global__ void rope_kernel(__half* __restrict__ q, __half* __restrict__ k) {
    int s = blockIdx.x;
    int tid = threadIdx.x;
    __shared__ float cs[64], sn[64];
    if (tid < 64) {
        float inv = (float)exp(-((double)(2 * tid) / 128.0) * 13.815510557964274);
        float ang = (float)s * inv;
        cs[tid] = cosf(ang);
        sn[tid] = sinf(ang);
    }
    __syncthreads();
#pragma unroll
    for (int j = 0; j < 4; j++) {
        int idx = tid + j * 256;           // 1024 pairs: head = idx>>6, d = idx&63
        int h = idx >> 6, d = idx & 63;
        long long base = (long long)s * H + h * D;
        float c = cs[d], ss = sn[d];
        float q1 = __half2float(q[base + d]), q2 = __half2float(q[base + d + 64]);
        q[base + d] = __float2half_rn(q1 * c - q2 * ss);
        q[base + d + 64] = __float2half_rn(q2 * c + q1 * ss);
        float k1 = __half2float(k[base + d]), k2 = __half2float(k[base + d + 64]);
        k[base + d] = __float2half_rn(k1 * c - k2 * ss);
        k[base + d + 64] = __float2half_rn(k2 * c + k1 * ss);
    }
}

// ---------------- router + top-k compaction ----------------
__global__ void router_kernel(const float* __restrict__ h2, const float* __restrict__ gw,
                              const float* __restrict__ sgate, float* __restrict__ rl,
                              float* __restrict__ sgl, int* __restrict__ cnt,
                              int* __restrict__ glist, int* __restrict__ slot,
                              float* __restrict__ wsl) {
    int s = blockIdx.x;
    int tid = threadIdx.x;
    const float* hr = h2 + (long long)s * H;
    float acc[9];
#pragma unroll
    for (int j = 0; j < 9; j++) acc[j] = 0.f;
    for (int i = tid; i < H; i += 256) {
        float hv = hr[i];
        const float* gr = gw + (long long)i * NE;
#pragma unroll
        for (int e = 0; e < NE; e++) acc[e] += hv * gr[e];
        acc[8] += hv * sgate[i];
    }
    __shared__ float sh[8][9];
    int warp = tid >> 5, lane = tid & 31;
#pragma unroll
    for (int j = 0; j < 9; j++) {
        float v = acc[j];
#pragma unroll
        for (int o = 16; o; o >>= 1) v += __shfl_xor_sync(0xffffffffu, v, o);
        if (lane == 0) sh[warp][j] = v;
    }
    __syncthreads();
    if (tid == 0) {
        float t[9];
#pragma unroll
        for (int j = 0; j < 9; j++) {
            float v = 0.f;
            for (int wi = 0; wi < 8; wi++) v += sh[wi][j];
            t[j] = v;
        }
        float mx = t[0];
        for (int e = 1; e < NE; e++) mx = fmaxf(mx, t[e]);
        float p[NE], sum = 0.f;
        for (int e = 0; e < NE; e++) { p[e] = expf(t[e] - mx); sum += p[e]; }
        for (int e = 0; e < NE; e++) p[e] /= sum;
        for (int kI = 0; kI < TOPK; kI++) {
            int bi = 0;
            float bv = p[0];
            for (int e = 1; e < NE; e++)
                if (p[e] > bv) { bv = p[e]; bi = e; }
            int pos = atomicAdd(&cnt[bi], 1);
            glist[bi * S + pos] = s;
            slot[s * TOPK + kI] = bi * S + pos;
            wsl[bi * S + pos] = bv;
            p[bi] = -1.f;
        }
        for (int e = 0; e < NE; e++) rl[s * NE + e] = t[e];
        sgl[s] = t[8];
    }
}

// ---------------- final combine (half eo, weights pre-applied) ----------------
__global__ void final_kernel(const float* __restrict__ x2, const __half* __restrict__ eoh,
                             const int* __restrict__ slot,
                             const float* __restrict__ sm, const float* __restrict__ sgl,
                             float* __restrict__ out) {
    int i = blockIdx.x * 256 + threadIdx.x;
    int s = i >> 11, c = i & 2047;
    float mo = 0.f;
#pragma unroll
    for (int kI = 0; kI < TOPK; kI++)
        mo += __half2float(eoh[(long long)slot[s * TOPK + kI] * H + c]);
    float gg = 1.f / (1.f + expf(-sgl[s]));
    out[i] = x2[i] + mo + gg * sm[i];
}

// ---------------- host ----------------
extern "C" void kernel_launch(void* const* d_in, const int* in_sizes, int n_in,
                              void* d_out, int out_size) {
    const float* x = (const float*)d_in[0];
    const float* ln1 = (const float*)d_in[1];
    const float* ln2 = (const float*)d_in[2];
    const float* wq = (const float*)d_in[3];
    const float* bq = (const float*)d_in[4];
    const float* wk = (const float*)d_in[5];
    const float* bk = (const float*)d_in[6];
    const float* wv = (const float*)d_in[7];
    const float* bv = (const float*)d_in[8];
    const float* wo = (const float*)d_in[9];
    const float* gw = (const float*)d_in[10];
    const float* eg = (const float*)d_in[11];
    const float* eu = (const float*)d_in[12];
    const float* ed = (const float*)d_in[13];
    const float* sg = (const float*)d_in[14];
    const float* su = (const float*)d_in[15];
    const float* sd = (const float*)d_in[16];
    const float* sgate = (const float*)d_in[17];
    float* out = (float*)d_out;

    float *x2, *h2f, *sm, *sgl, *rls, *wsl, *bqkv;
    int *cnt, *glist, *slot;
    __half *h1h, *qkvh, *ath, *h2h, *ghh, *uhh, *eoh, *ssg, *ssh;
    __half *wqkvh, *woh, *egh, *euh, *edh, *sgw, *suw, *sdw;
    cudaGetSymbolAddress((void**)&x2, g_x2);
    cudaGetSymbolAddress((void**)&h2f, g_h2f);
    cudaGetSymbolAddress((void**)&sm, g_sm);
    cudaGetSymbolAddress((void**)&sgl, g_sgl);
    cudaGetSymbolAddress((void**)&rls, g_rl);
    cudaGetSymbolAddress((void**)&wsl, g_wsl);
    cudaGetSymbolAddress((void**)&bqkv, g_bqkv);
    cudaGetSymbolAddress((void**)&cnt, g_cnt);
    cudaGetSymbolAddress((void**)&glist, g_glist);
    cudaGetSymbolAddress((void**)&slot, g_slot);
    cudaGetSymbolAddress((void**)&h1h, g_h1h);
    cudaGetSymbolAddress((void**)&qkvh, g_qkvh);
    cudaGetSymbolAddress((void**)&ath, g_ath);
    cudaGetSymbolAddress((void**)&h2h, g_h2h);
    cudaGetSymbolAddress((void**)&ghh, g_ghh);
    cudaGetSymbolAddress((void**)&uhh, g_uhh);
    cudaGetSymbolAddress((void**)&eoh, g_eoh);
    cudaGetSymbolAddress((void**)&ssg, g_ssg);
    cudaGetSymbolAddress((void**)&ssh, g_ssh);
    cudaGetSymbolAddress((void**)&wqkvh, g_wqkvh);
    cudaGetSymbolAddress((void**)&woh, g_woh);
    cudaGetSymbolAddress((void**)&egh, g_egh);
    cudaGetSymbolAddress((void**)&euh, g_euh);
    cudaGetSymbolAddress((void**)&edh, g_edh);
    cudaGetSymbolAddress((void**)&sgw, g_sgw);
    cudaGetSymbolAddress((void**)&suw, g_suw);
    cudaGetSymbolAddress((void**)&sdw, g_sdw);

    __half* qh = qkvh;
    __half* kh = qkvh + (long long)S * H;
    __half* vh = qkvh + (long long)2 * S * H;

    cudaFuncSetAttribute(flash_kernel, cudaFuncAttributeMaxDynamicSharedMemorySize, FLASH_SMEM);
    cudaFuncSetAttribute(hgemm<1, true, 0>, cudaFuncAttributeMaxDynamicSharedMemorySize, SMEM_G);
    cudaFuncSetAttribute(hgemm<2, false, 0>, cudaFuncAttributeMaxDynamicSharedMemorySize, SMEM_G);
    cudaFuncSetAttribute(hgemm<0, true, 1>, cudaFuncAttributeMaxDynamicSharedMemorySize, SMEM_G);
    cudaFuncSetAttribute(hgemm<3, true, 1>, cudaFuncAttributeMaxDynamicSharedMemorySize, SMEM_G);
    cudaFuncSetAttribute(hgemm<4, true, 2>, cudaFuncAttributeMaxDynamicSharedMemorySize, SMEM_G);
    cudaFuncSetAttribute(hgemm<0, true, 0>, cudaFuncAttributeMaxDynamicSharedMemorySize, SMEM_G);
    cudaFuncSetAttribute(hgemm<3, true, 0>, cudaFuncAttributeMaxDynamicSharedMemorySize, SMEM_G);
    cudaFuncSetAttribute(hgemm<0, false, 0>, cudaFuncAttributeMaxDynamicSharedMemorySize, SMEM_G);

    static cudaStream_t s2 = 0, s3 = 0;
    static cudaEvent_t evFork = 0, evW0 = 0, evW = 0, evH2 = 0, evSh = 0;
    if (!s2) {
        cudaStreamCreateWithFlags(&s2, cudaStreamNonBlocking);
        cudaStreamCreateWithFlags(&s3, cudaStreamNonBlocking);
        cudaEventCreateWithFlags(&evFork, cudaEventDisableTiming);
        cudaEventCreateWithFlags(&evW0, cudaEventDisableTiming);
        cudaEventCreateWithFlags(&evW, cudaEventDisableTiming);
        cudaEventCreateWithFlags(&evH2, cudaEventDisableTiming);
        cudaEventCreateWithFlags(&evSh, cudaEventDisableTiming);
    }

    float* rl_dst = (out_size >= S * H + S * NE) ? (out + (size_t)S * H) : rls;

    // ---- fork conversion stream ----
    cudaEventRecord(evFork, 0);
    cudaStreamWaitEvent(s2, evFork, 0);
    bcopy_kernel<<<6, 1024, 0, s2>>>(bq, bk, bv, bqkv);
    f2h_kernel<<<2048, 256, 0, s2>>>(wq, wqkvh, (long long)H * H);
    f2h_kernel<<<2048, 256, 0, s2>>>(wk, wqkvh + (long long)H * H, (long long)H * H);
    f2h_kernel<<<2048, 256, 0, s2>>>(wv, wqkvh + (long long)2 * H * H, (long long)H * H);
    f2h_kernel<<<2048, 256, 0, s2>>>(wo, woh, (long long)H * H);
    cudaEventRecord(evW0, s2);
    f2h_kernel<<<4096, 256, 0, s2>>>(eg, egh, (long long)NE * H * IE);
    f2h_kernel<<<4096, 256, 0, s2>>>(eu, euh, (long long)NE * H * IE);
    f2h_kernel<<<4096, 256, 0, s2>>>(sg, sgw, (long long)H * IS);
    f2h_kernel<<<4096, 256, 0, s2>>>(su, suw, (long long)H * IS);
    f2h_kernel<<<4096, 256, 0, s2>>>(ed, edh, (long long)NE * IE * H);
    f2h_kernel<<<4096, 256, 0, s2>>>(sd, sdw, (long long)IS * H);
    cudaEventRecord(evW, s2);

    // ---- main stream: attention path ----
    rmsnorm_kernel<<<S, 256>>>(x, ln1, h1h, (float*)0, (int*)0);
    cudaStreamWaitEvent(0, evW0, 0);
    // merged QKV: one launch, z in {q,k,v}
    hgemm<1, true, 0><<<dim3(16, 16, 3), 256, SMEM_G>>>(
        h1h, wqkvh, qkvh, bqkv, (const __half*)0, 0, 0,
        H, H, H, H, 0LL, (long long)H * H, (long long)S * H);
    rope_kernel<<<S, 256>>>(qh, kh);
    flash_kernel<<<dim3(16, NH), 256, FLASH_SMEM>>>(qh, kh, vh, ath);
    hgemm<2, false, 0><<<dim3(16, 16, 1), 256, SMEM_G>>>(
        ath, woh, x2, x, (const __half*)0, 0, 0, H, H, H, H, 0, 0, 0);
    rmsnorm_kernel<<<S, 256>>>(x2, ln2, h2h, h2f, cnt);
    cudaEventRecord(evH2, 0);
    router_kernel<<<S, 256>>>(h2f, gw, sgate, rl_dst, sgl, cnt, glist, slot, wsl);

    // ---- stream s3: shared MLP branch ----
    cudaStreamWaitEvent(s3, evH2, 0);
    cudaStreamWaitEvent(s3, evW, 0);
    {
        dim3 g(IS / 128, 16, 1);
        hgemm<0, true, 0><<<g, 256, SMEM_G, s3>>>(h2h, sgw, ssg, (const float*)0, (const __half*)0,
            0, 0, H, H, IS, IS, 0, 0, 0);
        hgemm<3, true, 0><<<g, 256, SMEM_G, s3>>>(h2h, suw, ssh, (const float*)0, ssg,
            0, 0, H, H, IS, IS, 0, 0, 0);
        hgemm<0, false, 0><<<dim3(16, 16, 1), 256, SMEM_G, s3>>>(ssh, sdw, sm, (const float*)0,
            (const __half*)0, 0, 0, IS, IS, H, H, 0, 0, 0);
    }
    cudaEventRecord(evSh, s3);

    // ---- main stream: sparse MoE branch ----
    cudaStreamWaitEvent(0, evW, 0);
    {
        dim3 g(IE / 128, 16, NE);
        hgemm<0, true, 1><<<g, 256, SMEM_G>>>(h2h, egh, ghh, (const float*)0, (const __half*)0,
            glist, cnt, H, H, IE, IE, 0LL, (long long)H * IE, (long long)S * IE);
        hgemm<3, true, 1><<<g, 256, SMEM_G>>>(h2h, euh, uhh, (const float*)0, ghh,
            glist, cnt, H, H, IE, IE, 0LL, (long long)H * IE, (long long)S * IE);
    }
    hgemm<4, true, 2><<<dim3(16, 16, NE), 256, SMEM_G>>>(uhh, edh, eoh, wsl,
        (const __half*)0, (const int*)0, cnt, IE, IE, H, H,
        (long long)S * IE, (long long)IE * H, (long long)S * H);

    // ---- join + combine ----
    cudaStreamWaitEvent(0, evSh, 0);
    final_kernel<<<(S * H) / 256, 256>>>(x2, eoh, slot, sm, sgl, out);
}

// round 11
// speedup vs baseline: 3.1791x; 1.0414x over previous
#include <cuda_runtime.h>
#include <cuda_fp16.h>
#include <cstdint>
#include <math.h>

#define S 2048
#define H 2048
#define NH 16
#define D 128
#define NE 8
#define TOPK 4
#define IE 1408
#define IS 5632

// ---------------- fp32 scratch ----------------
static __device__ float g_x2[S * H];
static __device__ float g_h2f[S * H];
static __device__ float g_sm[S * H];
static __device__ float g_sgl[S];
static __device__ float g_rl[S * NE];
static __device__ float g_wsl[NE * S];
static __device__ float g_bqkv[3 * H];
static __device__ int g_cnt[NE];
static __device__ int g_glist[NE * S];
static __device__ int g_slot[S * TOPK];
// ---------------- half scratch ----------------
static __device__ __half g_h1h[S * H];
static __device__ __half g_qkvh[(long long)3 * S * H];
static __device__ __half g_ath[S * H];
static __device__ __half g_h2h[S * H];
static __device__ __half g_ghh[(long long)NE * S * IE];
static __device__ __half g_uhh[(long long)NE * S * IE];
static __device__ __half g_eoh[(long long)NE * S * H];
static __device__ __half g_ssg[(long long)S * IS];
static __device__ __half g_ssh[(long long)S * IS];
// half weights
static __device__ __half g_wqkvh[(long long)3 * H * H];
static __device__ __half g_woh[H * H];
static __device__ __half g_egh[(long long)NE * H * IE];
static __device__ __half g_euh[(long long)NE * H * IE];
static __device__ __half g_edh[(long long)NE * IE * H];
static __device__ __half g_sgw[(long long)H * IS];
static __device__ __half g_suw[(long long)H * IS];
static __device__ __half g_sdw[(long long)IS * H];

// ---------------- helpers ----------------
__device__ __forceinline__ uint32_t smem_u32(const void* p) {
    uint32_t a;
    asm("{ .reg .u64 t; cvta.to.shared.u64 t, %1; cvt.u32.u64 %0, t; }" : "=r"(a) : "l"(p));
    return a;
}
__device__ __forceinline__ void cp16(uint32_t dst, const void* src) {
    asm volatile("cp.async.cg.shared.global [%0], [%1], 16;" :: "r"(dst), "l"(src));
}
#define CP_COMMIT() asm volatile("cp.async.commit_group;" ::: "memory")
#define CP_WAIT2() asm volatile("cp.async.wait_group 2;" ::: "memory")
#define CP_WAIT1() asm volatile("cp.async.wait_group 1;" ::: "memory")
#define CP_WAIT0() asm volatile("cp.async.wait_group 0;" ::: "memory")

__device__ __forceinline__ void ldsm_x4(uint32_t* r, uint32_t addr) {
    asm volatile("ldmatrix.sync.aligned.m8n8.x4.shared.b16 {%0,%1,%2,%3}, [%4];"
        : "=r"(r[0]), "=r"(r[1]), "=r"(r[2]), "=r"(r[3]) : "r"(addr));
}
__device__ __forceinline__ void ldsm_x4_t(uint32_t* r, uint32_t addr) {
    asm volatile("ldmatrix.sync.aligned.m8n8.x4.trans.shared.b16 {%0,%1,%2,%3}, [%4];"
        : "=r"(r[0]), "=r"(r[1]), "=r"(r[2]), "=r"(r[3]) : "r"(addr));
}
__device__ __forceinline__ void mma_f16(float* d, const uint32_t* a, const uint32_t* b) {
    asm volatile(
        "mma.sync.aligned.m16n8k16.row.col.f32.f16.f16.f32 "
        "{%0,%1,%2,%3}, {%4,%5,%6,%7}, {%8,%9}, {%0,%1,%2,%3};"
        : "+f"(d[0]), "+f"(d[1]), "+f"(d[2]), "+f"(d[3])
        : "r"(a[0]), "r"(a[1]), "r"(a[2]), "r"(a[3]), "r"(b[0]), "r"(b[1]));
}
__device__ __forceinline__ uint32_t pack_h2(float a, float b) {
    half2 h = __floats2half2_rn(a, b);
    return *(uint32_t*)&h;
}

// ---------------- fp16 mma GEMM (128x128 CTA, 8 warps 64x32, K-stage 32, 4-deep pipe,
//                  ONE __syncthreads per stage) ----------------
// EPI: 0 none, 1 +bias[z*2048+col], 2 +resid, 3 silu(Xh)*acc, 4 acc*X[z*S+row].
// OUTH: half out. IDX: 0 none, 1 gather A via glist+bound, 2 bound only.
// ROPE: for z<2, rotate (d,d+64) pairs per head in-epilogue (QKV only).
#define A_ELT 5120
#define B_ELT 4352
#define SMEM_G (4 * (A_ELT + B_ELT) * 2)

template <int EPI, bool OUTH, int IDX, bool ROPE>
__global__ void __launch_bounds__(256, 2)
hgemm(const __half* __restrict__ A, const __half* __restrict__ B,
      void* __restrict__ Cv, const float* __restrict__ X, const __half* __restrict__ Xh,
      const int* __restrict__ glist, const int* __restrict__ cnt,
      int K, int lda, int ldb, int ldc,
      long long sA, long long sB, long long sC) {
    int cbound = 0x7fffffff;
    if (IDX) {
        cbound = cnt[blockIdx.z];
        if ((int)blockIdx.y * 128 >= cbound) return;
    }
    extern __shared__ __half dsm[];
    __half* const AS = dsm;
    __half* const BS = dsm + 4 * A_ELT;
    __shared__ float s_inv[64];

    int tid = threadIdx.x, lane = tid & 31, wid = tid >> 5;
    int row0 = blockIdx.y * 128, col0 = blockIdx.x * 128;

    if (ROPE && tid < 64)
        s_inv[tid] = (float)exp(-((double)(2 * tid) / 128.0) * 13.815510557964274);

    A += (long long)blockIdx.z * sA;
    if (IDX != 1) A += (long long)row0 * lda;
    B += (long long)blockIdx.z * sB + col0;

    int nstg = K >> 5;

    int arow = tid >> 2, acol = (tid & 3) * 8;
    int nrow = tid >> 4, ncol = (tid & 15) * 8;

    const __half* aptr[2];
#pragma unroll
    for (int i = 0; i < 2; i++) {
        int r = arow + i * 64;
        if (IDX == 1) {
            int gr = row0 + r;
            int ti = glist[blockIdx.z * S + (gr < cbound ? gr : 0)];
            aptr[i] = A + (long long)ti * lda;
        } else {
            aptr[i] = A + (long long)r * lda;
        }
    }

    auto fill = [&](int s, int k0) {
        __half* ad = AS + s * A_ELT;
        __half* bd = BS + s * B_ELT;
#pragma unroll
        for (int i = 0; i < 2; i++)
            cp16(smem_u32(ad + (arow + i * 64) * 40 + acol), aptr[i] + k0 + acol);
#pragma unroll
        for (int i = 0; i < 2; i++)
            cp16(smem_u32(bd + (nrow + i * 16) * 136 + ncol),
                 B + (long long)(k0 + nrow + i * 16) * ldb + ncol);
        CP_COMMIT();
    };

    float acc[4][4][4];
#pragma unroll
    for (int i = 0; i < 4; i++)
#pragma unroll
        for (int j = 0; j < 4; j++)
#pragma unroll
            for (int u = 0; u < 4; u++) acc[i][j][u] = 0.f;

    int wm = (wid & 1) * 64, wn = (wid >> 1) * 32;
    int fr = lane >> 2, fc = lane & 3;
    int l15 = lane & 15, lhi = (lane >> 4) << 3;

    fill(0, 0);
    if (nstg > 1) fill(1, 32);
    if (nstg > 2) fill(2, 64);

    for (int t = 0; t < nstg; t++) {
        if (t + 2 < nstg) CP_WAIT2();
        else if (t + 1 < nstg) CP_WAIT1();
        else CP_WAIT0();
        __syncthreads();               // readers of stage (t-1)%4 are all past here
        if (t + 3 < nstg) fill((t + 3) & 3, (t + 3) * 32);
        const __half* as = AS + (t & 3) * A_ELT;
        const __half* bs = BS + (t & 3) * B_ELT;
#pragma unroll
        for (int kk = 0; kk < 32; kk += 16) {
            uint32_t af[4][4];
#pragma unroll
            for (int mt = 0; mt < 4; mt++)
                ldsm_x4(af[mt], smem_u32(as + (wm + mt * 16 + l15) * 40 + kk + lhi));
            uint32_t bf[4][2];
#pragma unroll
            for (int p = 0; p < 2; p++) {
                uint32_t tmp[4];
                ldsm_x4_t(tmp, smem_u32(bs + (kk + l15) * 136 + wn + p * 16 + lhi));
                bf[2 * p][0] = tmp[0]; bf[2 * p][1] = tmp[1];
                bf[2 * p + 1][0] = tmp[2]; bf[2 * p + 1][1] = tmp[3];
            }
#pragma unroll
            for (int mt = 0; mt < 4; mt++)
#pragma unroll
                for (int nt = 0; nt < 4; nt++) mma_f16(acc[mt][nt], af[mt], bf[nt]);
        }
    }

    bool doRope = ROPE && (blockIdx.z < 2);
    if (doRope) __syncthreads();   // protect dsm reuse below vs. other warps' compute

    const __half* XhB = (EPI == 3) ? Xh + (long long)blockIdx.z * sC : (const __half*)0;
#pragma unroll
    for (int mt = 0; mt < 4; mt++) {
        int m = row0 + wm + mt * 16 + fr;
        float w0 = 1.f, w1 = 1.f;
        if (EPI == 4) {
            bool ok0 = (!IDX || m < cbound), ok1 = (!IDX || m + 8 < cbound);
            w0 = ok0 ? X[(long long)blockIdx.z * S + m] : 0.f;
            w1 = ok1 ? X[(long long)blockIdx.z * S + m + 8] : 0.f;
        }
#pragma unroll
        for (int nt = 0; nt < 4; nt++) {
            int nl = wn + nt * 8 + fc * 2;
            int n = col0 + nl;
            float2 v0 = make_float2(acc[mt][nt][0], acc[mt][nt][1]);
            float2 v1 = make_float2(acc[mt][nt][2], acc[mt][nt][3]);
            if (EPI == 1) {
                const float* bz = X + (long long)blockIdx.z * 2048;
                v0.x += bz[n]; v0.y += bz[n + 1];
                v1.x += bz[n]; v1.y += bz[n + 1];
            }
            if (EPI == 2) {
                const float2 r0 = *(const float2*)&X[(long long)m * ldc + n];
                const float2 r1 = *(const float2*)&X[(long long)(m + 8) * ldc + n];
                v0.x += r0.x; v0.y += r0.y;
                v1.x += r1.x; v1.y += r1.y;
            }
            if (EPI == 3) {
                bool ok0 = (!IDX || m < cbound), ok1 = (!IDX || m + 8 < cbound);
                if (ok0) {
                    half2 gh = *(const half2*)&XhB[(long long)m * ldc + n];
                    float gx = __half2float(gh.x), gy = __half2float(gh.y);
                    v0.x *= gx / (1.f + expf(-gx));
                    v0.y *= gy / (1.f + expf(-gy));
                }
                if (ok1) {
                    half2 gh = *(const half2*)&XhB[(long long)(m + 8) * ldc + n];
                    float gx = __half2float(gh.x), gy = __half2float(gh.y);
                    v1.x *= gx / (1.f + expf(-gx));
                    v1.y *= gy / (1.f + expf(-gy));
                }
            }
            if (EPI == 4) {
                v0.x *= w0; v0.y *= w0;
                v1.x *= w1; v1.y *= w1;
            }
            if (doRope) {
                int rl0 = wm + mt * 16 + fr;
                *(half2*)&dsm[rl0 * 136 + nl] = __floats2half2_rn(v0.x, v0.y);
                *(half2*)&dsm[(rl0 + 8) * 136 + nl] = __floats2half2_rn(v1.x, v1.y);
            } else if (OUTH) {
                __half* C = (__half*)Cv + (long long)blockIdx.z * sC;
                if (!IDX || m < cbound)
                    *(half2*)&C[(long long)m * ldc + n] = __floats2half2_rn(v0.x, v0.y);
                if (!IDX || m + 8 < cbound)
                    *(half2*)&C[(long long)(m + 8) * ldc + n] = __floats2half2_rn(v1.x, v1.y);
            } else {
                float* C = (float*)Cv + (long long)blockIdx.z * sC;
                if (!IDX || m < cbound)
                    *(float2*)&C[(long long)m * ldc + n] = v0;
                if (!IDX || m + 8 < cbound)
                    *(float2*)&C[(long long)(m + 8) * ldc + n] = v1;
            }
        }
    }

    if (doRope) {
        __syncthreads();
        __half* C = (__half*)Cv + (long long)blockIdx.z * sC;
        for (int it = tid; it < 128 * 64; it += 256) {
            int row = it >> 6, d = it & 63;
            int sg = row0 + row;
            float ang = (float)sg * s_inv[d];
            float cc = cosf(ang), ssn = sinf(ang);
            float a = __half2float(dsm[row * 136 + d]);
            float b = __half2float(dsm[row * 136 + d + 64]);
            C[(long long)sg * ldc + col0 + d] = __float2half_rn(a * cc - b * ssn);
            C[(long long)sg * ldc + col0 + d + 64] = __float2half_rn(b * cc + a * ssn);
        }
    }
}

// ---------------- flash attention ----------------
#define FSC 0.12751744f
__global__ void __launch_bounds__(256, 1)
flash_kernel(const __half* __restrict__ Q, const __half* __restrict__ K,
             const __half* __restrict__ V, __half* __restrict__ O) {
    int qb = 15 - (int)blockIdx.x;
    int h = blockIdx.y;
    extern __shared__ __half fsm[];
    __half* Qs = fsm;
    __half* Ks = fsm + 128 * 136;
    __half* Vs = Ks + 2 * 128 * 136;

    int tid = threadIdx.x, lane = tid & 31, wid = tid >> 5;
    int fr = lane >> 2, fc = lane & 3;
    int l15 = lane & 15, lhi = (lane >> 4) << 3;
    int wm = wid * 16;

    const __half* qg = Q + (long long)(qb * 128) * H + h * D;
    const __half* kg = K + h * D;
    const __half* vg = V + h * D;

    int lr = tid >> 1, lc = (tid & 1) * 64;
#pragma unroll
    for (int j = 0; j < 8; j++)
        cp16(smem_u32(Qs + lr * 136 + lc + j * 8), qg + (long long)lr * H + lc + j * 8);

    auto loadKV = [&](int buf, int kt) {
        const __half* ks = kg + (long long)(kt * 128) * H;
        const __half* vs = vg + (long long)(kt * 128) * H;
        __half* kd = Ks + buf * (128 * 136);
        __half* vd = Vs + buf * (128 * 136);
#pragma unroll
        for (int j = 0; j < 8; j++) {
            cp16(smem_u32(kd + lr * 136 + lc + j * 8), ks + (long long)lr * H + lc + j * 8);
            cp16(smem_u32(vd + lr * 136 + lc + j * 8), vs + (long long)lr * H + lc + j * 8);
        }
    };
    loadKV(0, 0); CP_COMMIT();

    float oacc[16][4];
#pragma unroll
    for (int i = 0; i < 16; i++)
#pragma unroll
        for (int u = 0; u < 4; u++) oacc[i][u] = 0.f;
    float m0 = -1e30f, m1 = -1e30f, l0 = 0.f, l1 = 0.f;

    int ntile = qb + 1;
    for (int t = 0; t < ntile; t++) {
        if (t + 1 < ntile) { loadKV((t + 1) & 1, t + 1); CP_COMMIT(); CP_WAIT1(); }
        else CP_WAIT0();
        __syncthreads();
        const __half* kb = Ks + (t & 1) * (128 * 136);
        const __half* vb = Vs + (t & 1) * (128 * 136);

        float s[16][4];
#pragma unroll
        for (int i = 0; i < 16; i++)
#pragma unroll
            for (int u = 0; u < 4; u++) s[i][u] = 0.f;

#pragma unroll
        for (int kk = 0; kk < 8; kk++) {
            uint32_t aq[4];
            ldsm_x4(aq, smem_u32(Qs + (wm + l15) * 136 + kk * 16 + lhi));
#pragma unroll
            for (int nt = 0; nt < 16; nt++) {
                uint32_t bk[2];
                bk[0] = *(const uint32_t*)(kb + (nt * 8 + fr) * 136 + kk * 16 + 2 * fc);
                bk[1] = *(const uint32_t*)(kb + (nt * 8 + fr) * 136 + kk * 16 + 2 * fc + 8);
                mma_f16(s[nt], aq, bk);
            }
        }

        if (t == qb) {
            int r0 = wm + fr, r1 = r0 + 8;
#pragma unroll
            for (int nt = 0; nt < 16; nt++) {
                int c0 = nt * 8 + 2 * fc;
                if (c0 > r0) s[nt][0] = -1e30f;
                if (c0 + 1 > r0) s[nt][1] = -1e30f;
                if (c0 > r1) s[nt][2] = -1e30f;
                if (c0 + 1 > r1) s[nt][3] = -1e30f;
            }
        }

        float mx0 = -1e30f, mx1 = -1e30f;
#pragma unroll
        for (int nt = 0; nt < 16; nt++) {
            mx0 = fmaxf(mx0, fmaxf(s[nt][0], s[nt][1]));
            mx1 = fmaxf(mx1, fmaxf(s[nt][2], s[nt][3]));
        }
        mx0 = fmaxf(mx0, __shfl_xor_sync(0xffffffffu, mx0, 1));
        mx0 = fmaxf(mx0, __shfl_xor_sync(0xffffffffu, mx0, 2));
        mx1 = fmaxf(mx1, __shfl_xor_sync(0xffffffffu, mx1, 1));
        mx1 = fmaxf(mx1, __shfl_xor_sync(0xffffffffu, mx1, 2));

        float mn0 = fmaxf(m0, mx0), mn1 = fmaxf(m1, mx1);
        float rs0 = exp2f((m0 - mn0) * FSC), rs1 = exp2f((m1 - mn1) * FSC);
        m0 = mn0; m1 = mn1;

        float sm0 = 0.f, sm1 = 0.f;
#pragma unroll
        for (int nt = 0; nt < 16; nt++) {
            s[nt][0] = exp2f((s[nt][0] - m0) * FSC);
            s[nt][1] = exp2f((s[nt][1] - m0) * FSC);
            s[nt][2] = exp2f((s[nt][2] - m1) * FSC);
            s[nt][3] = exp2f((s[nt][3] - m1) * FSC);
            sm0 += s[nt][0] + s[nt][1];
            sm1 += s[nt][2] + s[nt][3];
        }
        sm0 += __shfl_xor_sync(0xffffffffu, sm0, 1);
        sm0 += __shfl_xor_sync(0xffffffffu, sm0, 2);
        sm1 += __shfl_xor_sync(0xffffffffu, sm1, 1);
        sm1 += __shfl_xor_sync(0xffffffffu, sm1, 2);
        l0 = l0 * rs0 + sm0;
        l1 = l1 * rs1 + sm1;
#pragma unroll
        for (int nt = 0; nt < 16; nt++) {
            oacc[nt][0] *= rs0; oacc[nt][1] *= rs0;
            oacc[nt][2] *= rs1; oacc[nt][3] *= rs1;
        }

#pragma unroll
        for (int kc = 0; kc < 8; kc++) {
            uint32_t pa[4];
            pa[0] = pack_h2(s[2 * kc][0], s[2 * kc][1]);
            pa[1] = pack_h2(s[2 * kc][2], s[2 * kc][3]);
            pa[2] = pack_h2(s[2 * kc + 1][0], s[2 * kc + 1][1]);
            pa[3] = pack_h2(s[2 * kc + 1][2], s[2 * kc + 1][3]);
#pragma unroll
            for (int p = 0; p < 8; p++) {
                uint32_t tmp[4];
                ldsm_x4_t(tmp, smem_u32(vb + (kc * 16 + l15) * 136 + p * 16 + lhi));
                mma_f16(oacc[2 * p], pa, tmp);
                mma_f16(oacc[2 * p + 1], pa, tmp + 2);
            }
        }
        __syncthreads();
    }

    float inv0 = 1.f / l0, inv1 = 1.f / l1;
    __half* og = O + (long long)(qb * 128) * H + h * D;
    int r0 = wm + fr, r1 = r0 + 8;
#pragma unroll
    for (int nt = 0; nt < 16; nt++) {
        int col = nt * 8 + 2 * fc;
        *(half2*)(og + (long long)r0 * H + col) =
            __floats2half2_rn(oacc[nt][0] * inv0, oacc[nt][1] * inv0);
        *(half2*)(og + (long long)r1 * H + col) =
            __floats2half2_rn(oacc[nt][2] * inv1, oacc[nt][3] * inv1);
    }
}
#define FLASH_SMEM ((128 + 256 + 256) * 136 * 2)

// ---------------- fp32 -> fp16 ----------------
__global__ void f2h_kernel(const float* __restrict__ in, __half* __restrict__ out, long long n) {
    long long i = (long long)blockIdx.x * 1024 + threadIdx.x * 4;
    for (; i + 3 < n; i += (long long)gridDim.x * 1024) {
        float4 v = *(const float4*)&in[i];
        *(half2*)&out[i] = __floats2half2_rn(v.x, v.y);
        *(half2*)&out[i + 2] = __floats2half2_rn(v.z, v.w);
    }
}

// ---------------- pack 3 bias vectors ----------------
__global__ void bcopy_kernel(const float* a, const float* b, const float* c, float* o) {
    int i = blockIdx.x * 1024 + threadIdx.x;
    const float* src[3] = {a, b, c};
    o[i] = src[i >> 11][i & 2047];
}

// ---------------- RMSNorm ----------------
__global__ void rmsnorm_kernel(const float* __restrict__ x, const float* __restrict__ w,
                               __half* __restrict__ oh, float* __restrict__ of,
                               int* __restrict__ zcnt) {
    int s = blockIdx.x;
    if (zcnt && s == 0 && threadIdx.x < NE) zcnt[threadIdx.x] = 0;
    const float* xr = x + (long long)s * H;
    int tid = threadIdx.x;
    float ss = 0.f;
    for (int i = tid; i < H; i += 256) { float v = xr[i]; ss += v * v; }
    __shared__ float sh[8];
#pragma unroll
    for (int off = 16; off; off >>= 1) ss += __shfl_xor_sync(0xffffffffu, ss, off);
    if ((tid & 31) == 0) sh[tid >> 5] = ss;
    __syncthreads();
    ss = sh[tid & 7];
#pragma unroll
    for (int off = 4; off; off >>= 1) ss += __shfl_xor_sync(0xffffffffu, ss, off);
    float inv = rsqrtf(ss / (float)H + 1e-6f);
    for (int i = tid; i < H; i += 256) {
        float v = w[i] * xr[i] * inv;
        oh[(long long)s * H + i] = __float2half_rn(v);
        if (of) of[(long long)s * H + i] = v;
    }
}

// ---------------- router + top-k compaction ----------------
__global__ void router_kernel(const float* __restrict__ h2, const float* __restrict__ gw,
                              const float* __restrict__ sgate, float* __restrict__ rl,
                              float* __restrict__ sgl, int* __restrict__ cnt,
                              int* __restrict__ glist, int* __restrict__ slot,
                              float* __restrict__ wsl) {
    int s = blockIdx.x;
    int tid = threadIdx.x;
    const float* hr = h2 + (long long)s * H;
    float acc[9];
#pragma unroll
    for (int j = 0; j < 9; j++) acc[j] = 0.f;
    for (int i = tid; i < H; i += 256) {
        float hv = hr[i];
        const float* gr = gw + (long long)i * NE;
#pragma unroll
        for (int e = 0; e < NE; e++) acc[e] += hv * gr[e];
        acc[8] += hv * sgate[i];
    }
    __shared__ float sh[8][9];
    int warp = tid >> 5, lane = tid & 31;
#pragma unroll
    for (int j = 0; j < 9; j++) {
        float v = acc[j];
#pragma unroll
        for (int o = 16; o; o >>= 1) v += __shfl_xor_sync(0xffffffffu, v, o);
        if (lane == 0) sh[warp][j] = v;
    }
    __syncthreads();
    if (tid == 0) {
        float t[9];
#pragma unroll
        for (int j = 0; j < 9; j++) {
            float v = 0.f;
            for (int wi = 0; wi < 8; wi++) v += sh[wi][j];
            t[j] = v;
        }
        float mx = t[0];
        for (int e = 1; e < NE; e++) mx = fmaxf(mx, t[e]);
        float p[NE], sum = 0.f;
        for (int e = 0; e < NE; e++) { p[e] = expf(t[e] - mx); sum += p[e]; }
        for (int e = 0; e < NE; e++) p[e] /= sum;
        for (int kI = 0; kI < TOPK; kI++) {
            int bi = 0;
            float bv = p[0];
            for (int e = 1; e < NE; e++)
                if (p[e] > bv) { bv = p[e]; bi = e; }
            int pos = atomicAdd(&cnt[bi], 1);
            glist[bi * S + pos] = s;
            slot[s * TOPK + kI] = bi * S + pos;
            wsl[bi * S + pos] = bv;
            p[bi] = -1.f;
        }
        for (int e = 0; e < NE; e++) rl[s * NE + e] = t[e];
        sgl[s] = t[8];
    }
}

// ---------------- final combine ----------------
__global__ void final_kernel(const float* __restrict__ x2, const __half* __restrict__ eoh,
                             const int* __restrict__ slot,
                             const float* __restrict__ sm, const float* __restrict__ sgl,
                             float* __restrict__ out) {
    int i = blockIdx.x * 256 + threadIdx.x;
    int s = i >> 11, c = i & 2047;
    float mo = 0.f;
#pragma unroll
    for (int kI = 0; kI < TOPK; kI++)
        mo += __half2float(eoh[(long long)slot[s * TOPK + kI] * H + c]);
    float gg = 1.f / (1.f + expf(-sgl[s]));
    out[i] = x2[i] + mo + gg * sm[i];
}

// ---------------- host ----------------
extern "C" void kernel_launch(void* const* d_in, const int* in_sizes, int n_in,
                              void* d_out, int out_size) {
    const float* x = (const float*)d_in[0];
    const float* ln1 = (const float*)d_in[1];
    const float* ln2 = (const float*)d_in[2];
    const float* wq = (const float*)d_in[3];
    const float* bq = (const float*)d_in[4];
    const float* wk = (const float*)d_in[5];
    const float* bk = (const float*)d_in[6];
    const float* wv = (const float*)d_in[7];
    const float* bv = (const float*)d_in[8];
    const float* wo = (const float*)d_in[9];
    const float* gw = (const float*)d_in[10];
    const float* eg = (const float*)d_in[11];
    const float* eu = (const float*)d_in[12];
    const float* ed = (const float*)d_in[13];
    const float* sg = (const float*)d_in[14];
    const float* su = (const float*)d_in[15];
    const float* sd = (const float*)d_in[16];
    const float* sgate = (const float*)d_in[17];
    float* out = (float*)d_out;

    float *x2, *h2f, *sm, *sgl, *rls, *wsl, *bqkv;
    int *cnt, *glist, *slot;
    __half *h1h, *qkvh, *ath, *h2h, *ghh, *uhh, *eoh, *ssg, *ssh;
    __half *wqkvh, *woh, *egh, *euh, *edh, *sgw, *suw, *sdw;
    cudaGetSymbolAddress((void**)&x2, g_x2);
    cudaGetSymbolAddress((void**)&h2f, g_h2f);
    cudaGetSymbolAddress((void**)&sm, g_sm);
    cudaGetSymbolAddress((void**)&sgl, g_sgl);
    cudaGetSymbolAddress((void**)&rls, g_rl);
    cudaGetSymbolAddress((void**)&wsl, g_wsl);
    cudaGetSymbolAddress((void**)&bqkv, g_bqkv);
    cudaGetSymbolAddress((void**)&cnt, g_cnt);
    cudaGetSymbolAddress((void**)&glist, g_glist);
    cudaGetSymbolAddress((void**)&slot, g_slot);
    cudaGetSymbolAddress((void**)&h1h, g_h1h);
    cudaGetSymbolAddress((void**)&qkvh, g_qkvh);
    cudaGetSymbolAddress((void**)&ath, g_ath);
    cudaGetSymbolAddress((void**)&h2h, g_h2h);
    cudaGetSymbolAddress((void**)&ghh, g_ghh);
    cudaGetSymbolAddress((void**)&uhh, g_uhh);
    cudaGetSymbolAddress((void**)&eoh, g_eoh);
    cudaGetSymbolAddress((void**)&ssg, g_ssg);
    cudaGetSymbolAddress((void**)&ssh, g_ssh);
    cudaGetSymbolAddress((void**)&wqkvh, g_wqkvh);
    cudaGetSymbolAddress((void**)&woh, g_woh);
    cudaGetSymbolAddress((void**)&egh, g_egh);
    cudaGetSymbolAddress((void**)&euh, g_euh);
    cudaGetSymbolAddress((void**)&edh, g_edh);
    cudaGetSymbolAddress((void**)&sgw, g_sgw);
    cudaGetSymbolAddress((void**)&suw, g_suw);
    cudaGetSymbolAddress((void**)&sdw, g_sdw);

    __half* qh = qkvh;
    __half* kh = qkvh + (long long)S * H;
    __half* vh = qkvh + (long long)2 * S * H;

    cudaFuncSetAttribute(flash_kernel, cudaFuncAttributeMaxDynamicSharedMemorySize, FLASH_SMEM);
    cudaFuncSetAttribute(hgemm<1, true, 0, true>, cudaFuncAttributeMaxDynamicSharedMemorySize, SMEM_G);
    cudaFuncSetAttribute(hgemm<2, false, 0, false>, cudaFuncAttributeMaxDynamicSharedMemorySize, SMEM_G);
    cudaFuncSetAttribute(hgemm<0, true, 1, false>, cudaFuncAttributeMaxDynamicSharedMemorySize, SMEM_G);
    cudaFuncSetAttribute(hgemm<3, true, 1, false>, cudaFuncAttributeMaxDynamicSharedMemorySize, SMEM_G);
    cudaFuncSetAttribute(hgemm<4, true, 2, false>, cudaFuncAttributeMaxDynamicSharedMemorySize, SMEM_G);
    cudaFuncSetAttribute(hgemm<0, true, 0, false>, cudaFuncAttributeMaxDynamicSharedMemorySize, SMEM_G);
    cudaFuncSetAttribute(hgemm<3, true, 0, false>, cudaFuncAttributeMaxDynamicSharedMemorySize, SMEM_G);
    cudaFuncSetAttribute(hgemm<0, false, 0, false>, cudaFuncAttributeMaxDynamicSharedMemorySize, SMEM_G);

    static cudaStream_t s2 = 0, s3 = 0;
    static cudaEvent_t evFork = 0, evW0 = 0, evW = 0, evH2 = 0, evSh = 0;
    if (!s2) {
        cudaStreamCreateWithFlags(&s2, cudaStreamNonBlocking);
        cudaStreamCreateWithFlags(&s3, cudaStreamNonBlocking);
        cudaEventCreateWithFlags(&evFork, cudaEventDisableTiming);
        cudaEventCreateWithFlags(&evW0, cudaEventDisableTiming);
        cudaEventCreateWithFlags(&evW, cudaEventDisableTiming);
        cudaEventCreateWithFlags(&evH2, cudaEventDisableTiming);
        cudaEventCreateWithFlags(&evSh, cudaEventDisableTiming);
    }

    float* rl_dst = (out_size >= S * H + S * NE) ? (out + (size_t)S * H) : rls;

    // ---- fork conversion stream ----
    cudaEventRecord(evFork, 0);
    cudaStreamWaitEvent(s2, evFork, 0);
    bcopy_kernel<<<6, 1024, 0, s2>>>(bq, bk, bv, bqkv);
    f2h_kernel<<<2048, 256, 0, s2>>>(wq, wqkvh, (long long)H * H);
    f2h_kernel<<<2048, 256, 0, s2>>>(wk, wqkvh + (long long)H * H, (long long)H * H);
    f2h_kernel<<<2048, 256, 0, s2>>>(wv, wqkvh + (long long)2 * H * H, (long long)H * H);
    f2h_kernel<<<2048, 256, 0, s2>>>(wo, woh, (long long)H * H);
    cudaEventRecord(evW0, s2);
    f2h_kernel<<<4096, 256, 0, s2>>>(eg, egh, (long long)NE * H * IE);
    f2h_kernel<<<4096, 256, 0, s2>>>(eu, euh, (long long)NE * H * IE);
    f2h_kernel<<<4096, 256, 0, s2>>>(sg, sgw, (long long)H * IS);
    f2h_kernel<<<4096, 256, 0, s2>>>(su, suw, (long long)H * IS);
    f2h_kernel<<<4096, 256, 0, s2>>>(ed, edh, (long long)NE * IE * H);
    f2h_kernel<<<4096, 256, 0, s2>>>(sd, sdw, (long long)IS * H);
    cudaEventRecord(evW, s2);

    // ---- main stream: attention path ----
    rmsnorm_kernel<<<S, 256>>>(x, ln1, h1h, (float*)0, (int*)0);
    cudaStreamWaitEvent(0, evW0, 0);
    // merged QKV with fused RoPE on q,k
    hgemm<1, true, 0, true><<<dim3(16, 16, 3), 256, SMEM_G>>>(
        h1h, wqkvh, qkvh, bqkv, (const __half*)0, 0, 0,
        H, H, H, H, 0LL, (long long)H * H, (long long)S * H);
    flash_kernel<<<dim3(16, NH), 256, FLASH_SMEM>>>(qh, kh, vh, ath);
    hgemm<2, false, 0, false><<<dim3(16, 16, 1), 256, SMEM_G>>>(
        ath, woh, x2, x, (const __half*)0, 0, 0, H, H, H, H, 0, 0, 0);
    rmsnorm_kernel<<<S, 256>>>(x2, ln2, h2h, h2f, cnt);
    cudaEventRecord(evH2, 0);
    router_kernel<<<S, 256>>>(h2f, gw, sgate, rl_dst, sgl, cnt, glist, slot, wsl);

    // ---- stream s3: shared MLP branch ----
    cudaStreamWaitEvent(s3, evH2, 0);
    cudaStreamWaitEvent(s3, evW, 0);
    {
        dim3 g(IS / 128, 16, 1);
        hgemm<0, true, 0, false><<<g, 256, SMEM_G, s3>>>(h2h, sgw, ssg, (const float*)0, (const __half*)0,
            0, 0, H, H, IS, IS, 0, 0, 0);
        hgemm<3, true, 0, false><<<g, 256, SMEM_G, s3>>>(h2h, suw, ssh, (const float*)0, ssg,
            0, 0, H, H, IS, IS, 0, 0, 0);
        hgemm<0, false, 0, false><<<dim3(16, 16, 1), 256, SMEM_G, s3>>>(ssh, sdw, sm, (const float*)0,
            (const __half*)0, 0, 0, IS, IS, H, H, 0, 0, 0);
    }
    cudaEventRecord(evSh, s3);

    // ---- main stream: sparse MoE branch ----
    cudaStreamWaitEvent(0, evW, 0);
    {
        dim3 g(IE / 128, 16, NE);
        hgemm<0, true, 1, false><<<g, 256, SMEM_G>>>(h2h, egh, ghh, (const float*)0, (const __half*)0,
            glist, cnt, H, H, IE, IE, 0LL, (long long)H * IE, (long long)S * IE);
        hgemm<3, true, 1, false><<<g, 256, SMEM_G>>>(h2h, euh, uhh, (const float*)0, ghh,
            glist, cnt, H, H, IE, IE, 0LL, (long long)H * IE, (long long)S * IE);
    }
    hgemm<4, true, 2, false><<<dim3(16, 16, NE), 256, SMEM_G>>>(uhh, edh, eoh, wsl,
        (const __half*)0, (const int*)0, cnt, IE, IE, H, H,
        (long long)S * IE, (long long)IE * H, (long long)S * H);

    // ---- join + combine ----
    cudaStreamWaitEvent(0, evSh, 0);
    final_kernel<<<(S * H) / 256, 256>>>(x2, eoh, slot, sm, sgl, out);
}

// round 13
// speedup vs baseline: 3.2616x; 1.0260x over previous
#include <cuda_runtime.h>
#include <cuda_fp16.h>
#include <cstdint>
#include <math.h>

#define S 2048
#define H 2048
#define NH 16
#define D 128
#define NE 8
#define TOPK 4
#define IE 1408
#define IS 5632

// ---------------- fp32 scratch ----------------
static __device__ float g_x2[S * H];
static __device__ float g_h2f[S * H];
static __device__ float g_sm[S * H];
static __device__ float g_sgl[S];
static __device__ float g_rl[S * NE];
static __device__ float g_wsl[NE * S];
static __device__ float g_bqkv[3 * H];
static __device__ int g_cnt[NE];
static __device__ int g_glist[NE * S];
static __device__ int g_slot[S * TOPK];
// ---------------- half scratch ----------------
static __device__ __half g_h1h[S * H];
static __device__ __half g_qkvh[(long long)3 * S * H];
static __device__ __half g_ath[S * H];
static __device__ __half g_h2h[S * H];
static __device__ __half g_uhh[(long long)NE * S * IE];
static __device__ __half g_eoh[(long long)NE * S * H];
static __device__ __half g_ssh[(long long)S * IS];
// half weights
static __device__ __half g_wqkvh[(long long)3 * H * H];
static __device__ __half g_woh[H * H];
static __device__ __half g_egh[(long long)NE * H * IE];
static __device__ __half g_euh[(long long)NE * H * IE];
static __device__ __half g_edh[(long long)NE * IE * H];
static __device__ __half g_sgw[(long long)H * IS];
static __device__ __half g_suw[(long long)H * IS];
static __device__ __half g_sdw[(long long)IS * H];

// ---------------- helpers ----------------
__device__ __forceinline__ uint32_t smem_u32(const void* p) {
    uint32_t a;
    asm("{ .reg .u64 t; cvta.to.shared.u64 t, %1; cvt.u32.u64 %0, t; }" : "=r"(a) : "l"(p));
    return a;
}
__device__ __forceinline__ void cp16(uint32_t dst, const void* src) {
    asm volatile("cp.async.cg.shared.global [%0], [%1], 16;" :: "r"(dst), "l"(src));
}
#define CP_COMMIT() asm volatile("cp.async.commit_group;" ::: "memory")
#define CP_WAIT2() asm volatile("cp.async.wait_group 2;" ::: "memory")
#define CP_WAIT1() asm volatile("cp.async.wait_group 1;" ::: "memory")
#define CP_WAIT0() asm volatile("cp.async.wait_group 0;" ::: "memory")

__device__ __forceinline__ void ldsm_x4(uint32_t* r, uint32_t addr) {
    asm volatile("ldmatrix.sync.aligned.m8n8.x4.shared.b16 {%0,%1,%2,%3}, [%4];"
        : "=r"(r[0]), "=r"(r[1]), "=r"(r[2]), "=r"(r[3]) : "r"(addr));
}
__device__ __forceinline__ void ldsm_x4_t(uint32_t* r, uint32_t addr) {
    asm volatile("ldmatrix.sync.aligned.m8n8.x4.trans.shared.b16 {%0,%1,%2,%3}, [%4];"
        : "=r"(r[0]), "=r"(r[1]), "=r"(r[2]), "=r"(r[3]) : "r"(addr));
}
__device__ __forceinline__ void mma_f16(float* d, const uint32_t* a, const uint32_t* b) {
    asm volatile(
        "mma.sync.aligned.m16n8k16.row.col.f32.f16.f16.f32 "
        "{%0,%1,%2,%3}, {%4,%5,%6,%7}, {%8,%9}, {%0,%1,%2,%3};"
        : "+f"(d[0]), "+f"(d[1]), "+f"(d[2]), "+f"(d[3])
        : "r"(a[0]), "r"(a[1]), "r"(a[2]), "r"(a[3]), "r"(b[0]), "r"(b[1]));
}
__device__ __forceinline__ uint32_t pack_h2(float a, float b) {
    half2 h = __floats2half2_rn(a, b);
    return *(uint32_t*)&h;
}
__device__ __forceinline__ float siluf(float x) { return x / (1.f + expf(-x)); }

// ---------------- fp16 mma GEMM (128x128 CTA, 8 warps 64x32, K-stage 32, 4-deep pipe,
//                  ONE __syncthreads per stage; optional dual-pass gate+up) -------------
// EPI: 0 none, 1 +bias[z*2048+col], 2 +resid, 4 acc*X[z*S+row].
// OUTH: half out. IDX: 0 none, 1 gather A via glist+bound, 2 bound only.
// ROPE: for z<2, rotate (d,d+64) per head in-epilogue. DUAL: pass1 B (gate), pass2 B2
// (up), output silu(gate)*up.
#define A_ELT 5120
#define B_ELT 4352
#define SMEM_BASE (4 * (A_ELT + B_ELT) * 2)
#define SMEM_DUAL (SMEM_BASE + 256 * 32 * 4)

template <int EPI, bool OUTH, int IDX, bool ROPE, bool DUAL>
__global__ void __launch_bounds__(256, 2)
hgemm(const __half* __restrict__ A, const __half* __restrict__ B,
      const __half* __restrict__ B2,
      void* __restrict__ Cv, const float* __restrict__ X,
      const int* __restrict__ glist, const int* __restrict__ cnt,
      int K, int lda, int ldb, int ldc,
      long long sA, long long sB, long long sC) {
    int cbound = 0x7fffffff;
    if (IDX) {
        cbound = cnt[blockIdx.z];
        if ((int)blockIdx.y * 128 >= cbound) return;
    }
    extern __shared__ __half dsm[];
    __half* const AS = dsm;
    __half* const BS = dsm + 4 * A_ELT;
    __shared__ float s_inv[64];

    int tid = threadIdx.x, lane = tid & 31, wid = tid >> 5;
    int row0 = blockIdx.y * 128, col0 = blockIdx.x * 128;

    if (ROPE && tid < 64)
        s_inv[tid] = (float)exp(-((double)(2 * tid) / 128.0) * 13.815510557964274);

    A += (long long)blockIdx.z * sA;
    if (IDX != 1) A += (long long)row0 * lda;
    const __half* Bp = B + (long long)blockIdx.z * sB + col0;
    const __half* B2p = DUAL ? B2 + (long long)blockIdx.z * sB + col0 : (const __half*)0;

    int nstg = K >> 5;

    int arow = tid >> 2, acol = (tid & 3) * 8;
    int nrow = tid >> 4, ncol = (tid & 15) * 8;

    const __half* aptr[2];
#pragma unroll
    for (int i = 0; i < 2; i++) {
        int r = arow + i * 64;
        if (IDX == 1) {
            int gr = row0 + r;
            int ti = glist[blockIdx.z * S + (gr < cbound ? gr : 0)];
            aptr[i] = A + (long long)ti * lda;
        } else {
            aptr[i] = A + (long long)r * lda;
        }
    }

    const __half* Bcur = Bp;
    auto fill = [&](int s, int k0) {
        __half* ad = AS + s * A_ELT;
        __half* bd = BS + s * B_ELT;
#pragma unroll
        for (int i = 0; i < 2; i++)
            cp16(smem_u32(ad + (arow + i * 64) * 40 + acol), aptr[i] + k0 + acol);
#pragma unroll
        for (int i = 0; i < 2; i++)
            cp16(smem_u32(bd + (nrow + i * 16) * 136 + ncol),
                 Bcur + (long long)(k0 + nrow + i * 16) * ldb + ncol);
        CP_COMMIT();
    };

    float acc[4][4][4];
#pragma unroll
    for (int i = 0; i < 4; i++)
#pragma unroll
        for (int j = 0; j < 4; j++)
#pragma unroll
            for (int u = 0; u < 4; u++) acc[i][j][u] = 0.f;

    int wm = (wid & 1) * 64, wn = (wid >> 1) * 32;
    int fr = lane >> 2, fc = lane & 3;
    int l15 = lane & 15, lhi = (lane >> 4) << 3;

    uint32_t* stash = (uint32_t*)(dsm + SMEM_BASE / 2) + tid * 32;

    int npass = DUAL ? 2 : 1;
    for (int pass = 0; pass < npass; pass++) {
        if (pass == 1) Bcur = B2p;
        fill(0, 0);
        if (nstg > 1) fill(1, 32);
        if (nstg > 2) fill(2, 64);
        for (int t = 0; t < nstg; t++) {
            if (t + 2 < nstg) CP_WAIT2();
            else if (t + 1 < nstg) CP_WAIT1();
            else CP_WAIT0();
            __syncthreads();
            if (t + 3 < nstg) fill((t + 3) & 3, (t + 3) * 32);
            const __half* as = AS + (t & 3) * A_ELT;
            const __half* bs = BS + (t & 3) * B_ELT;
#pragma unroll
            for (int kk = 0; kk < 32; kk += 16) {
                uint32_t af[4][4];
#pragma unroll
                for (int mt = 0; mt < 4; mt++)
                    ldsm_x4(af[mt], smem_u32(as + (wm + mt * 16 + l15) * 40 + kk + lhi));
                uint32_t bf[4][2];
#pragma unroll
                for (int p = 0; p < 2; p++) {
                    uint32_t tmp[4];
                    ldsm_x4_t(tmp, smem_u32(bs + (kk + l15) * 136 + wn + p * 16 + lhi));
                    bf[2 * p][0] = tmp[0]; bf[2 * p][1] = tmp[1];
                    bf[2 * p + 1][0] = tmp[2]; bf[2 * p + 1][1] = tmp[3];
                }
#pragma unroll
                for (int mt = 0; mt < 4; mt++)
#pragma unroll
                    for (int nt = 0; nt < 4; nt++) mma_f16(acc[mt][nt], af[mt], bf[nt]);
            }
        }
        if (DUAL && pass == 0) {
            // stash gate accumulators (per-thread private) and reset
#pragma unroll
            for (int mt = 0; mt < 4; mt++)
#pragma unroll
                for (int nt = 0; nt < 4; nt++) {
                    stash[(mt * 4 + nt) * 2] = pack_h2(acc[mt][nt][0], acc[mt][nt][1]);
                    stash[(mt * 4 + nt) * 2 + 1] = pack_h2(acc[mt][nt][2], acc[mt][nt][3]);
                    acc[mt][nt][0] = acc[mt][nt][1] = acc[mt][nt][2] = acc[mt][nt][3] = 0.f;
                }
            __syncthreads();   // all warps done reading pass-1 stages before refill
        }
    }

    bool doRope = ROPE && (blockIdx.z < 2);
    if (doRope) __syncthreads();

#pragma unroll
    for (int mt = 0; mt < 4; mt++) {
        int m = row0 + wm + mt * 16 + fr;
        float w0 = 1.f, w1 = 1.f;
        if (EPI == 4) {
            bool ok0 = (!IDX || m < cbound), ok1 = (!IDX || m + 8 < cbound);
            w0 = ok0 ? X[(long long)blockIdx.z * S + m] : 0.f;
            w1 = ok1 ? X[(long long)blockIdx.z * S + m + 8] : 0.f;
        }
#pragma unroll
        for (int nt = 0; nt < 4; nt++) {
            int nl = wn + nt * 8 + fc * 2;
            int n = col0 + nl;
            float2 v0 = make_float2(acc[mt][nt][0], acc[mt][nt][1]);
            float2 v1 = make_float2(acc[mt][nt][2], acc[mt][nt][3]);
            if (EPI == 1) {
                const float* bz = X + (long long)blockIdx.z * 2048;
                v0.x += bz[n]; v0.y += bz[n + 1];
                v1.x += bz[n]; v1.y += bz[n + 1];
            }
            if (EPI == 2) {
                const float2 r0 = *(const float2*)&X[(long long)m * ldc + n];
                const float2 r1 = *(const float2*)&X[(long long)(m + 8) * ldc + n];
                v0.x += r0.x; v0.y += r0.y;
                v1.x += r1.x; v1.y += r1.y;
            }
            if (DUAL) {
                half2 g0 = *(half2*)&stash[(mt * 4 + nt) * 2];
                half2 g1 = *(half2*)&stash[(mt * 4 + nt) * 2 + 1];
                v0.x *= siluf(__half2float(g0.x));
                v0.y *= siluf(__half2float(g0.y));
                v1.x *= siluf(__half2float(g1.x));
                v1.y *= siluf(__half2float(g1.y));
            }
            if (EPI == 4) {
                v0.x *= w0; v0.y *= w0;
                v1.x *= w1; v1.y *= w1;
            }
            if (doRope) {
                int rl0 = wm + mt * 16 + fr;
                *(half2*)&dsm[rl0 * 136 + nl] = __floats2half2_rn(v0.x, v0.y);
                *(half2*)&dsm[(rl0 + 8) * 136 + nl] = __floats2half2_rn(v1.x, v1.y);
            } else if (OUTH) {
                __half* C = (__half*)Cv + (long long)blockIdx.z * sC;
                if (!IDX || m < cbound)
                    *(half2*)&C[(long long)m * ldc + n] = __floats2half2_rn(v0.x, v0.y);
                if (!IDX || m + 8 < cbound)
                    *(half2*)&C[(long long)(m + 8) * ldc + n] = __floats2half2_rn(v1.x, v1.y);
            } else {
                float* C = (float*)Cv + (long long)blockIdx.z * sC;
                if (!IDX || m < cbound)
                    *(float2*)&C[(long long)m * ldc + n] = v0;
                if (!IDX || m + 8 < cbound)
                    *(float2*)&C[(long long)(m + 8) * ldc + n] = v1;
            }
        }
    }

    if (doRope) {
        __syncthreads();
        __half* C = (__half*)Cv + (long long)blockIdx.z * sC;
        for (int it = tid; it < 128 * 64; it += 256) {
            int row = it >> 6, d = it & 63;
            int sg = row0 + row;
            float ang = (float)sg * s_inv[d];
            float cc = cosf(ang), ssn = sinf(ang);
            float a = __half2float(dsm[row * 136 + d]);
            float b = __half2float(dsm[row * 136 + d + 64]);
            C[(long long)sg * ldc + col0 + d] = __float2half_rn(a * cc - b * ssn);
            C[(long long)sg * ldc + col0 + d + 64] = __float2half_rn(b * cc + a * ssn);
        }
    }
}

// ---------------- flash attention ----------------
#define FSC 0.12751744f
__global__ void __launch_bounds__(256, 1)
flash_kernel(const __half* __restrict__ Q, const __half* __restrict__ K,
             const __half* __restrict__ V, __half* __restrict__ O) {
    int qb = 15 - (int)blockIdx.x;
    int h = blockIdx.y;
    extern __shared__ __half fsm[];
    __half* Qs = fsm;
    __half* Ks = fsm + 128 * 136;
    __half* Vs = Ks + 2 * 128 * 136;

    int tid = threadIdx.x, lane = tid & 31, wid = tid >> 5;
    int fr = lane >> 2, fc = lane & 3;
    int l15 = lane & 15, lhi = (lane >> 4) << 3;
    int wm = wid * 16;

    const __half* qg = Q + (long long)(qb * 128) * H + h * D;
    const __half* kg = K + h * D;
    const __half* vg = V + h * D;

    int lr = tid >> 1, lc = (tid & 1) * 64;
#pragma unroll
    for (int j = 0; j < 8; j++)
        cp16(smem_u32(Qs + lr * 136 + lc + j * 8), qg + (long long)lr * H + lc + j * 8);

    auto loadKV = [&](int buf, int kt) {
        const __half* ks = kg + (long long)(kt * 128) * H;
        const __half* vs = vg + (long long)(kt * 128) * H;
        __half* kd = Ks + buf * (128 * 136);
        __half* vd = Vs + buf * (128 * 136);
#pragma unroll
        for (int j = 0; j < 8; j++) {
            cp16(smem_u32(kd + lr * 136 + lc + j * 8), ks + (long long)lr * H + lc + j * 8);
            cp16(smem_u32(vd + lr * 136 + lc + j * 8), vs + (long long)lr * H + lc + j * 8);
        }
    };
    loadKV(0, 0); CP_COMMIT();

    float oacc[16][4];
#pragma unroll
    for (int i = 0; i < 16; i++)
#pragma unroll
        for (int u = 0; u < 4; u++) oacc[i][u] = 0.f;
    float m0 = -1e30f, m1 = -1e30f, l0 = 0.f, l1 = 0.f;

    int ntile = qb + 1;
    for (int t = 0; t < ntile; t++) {
        if (t + 1 < ntile) { loadKV((t + 1) & 1, t + 1); CP_COMMIT(); CP_WAIT1(); }
        else CP_WAIT0();
        __syncthreads();
        const __half* kb = Ks + (t & 1) * (128 * 136);
        const __half* vb = Vs + (t & 1) * (128 * 136);

        float s[16][4];
#pragma unroll
        for (int i = 0; i < 16; i++)
#pragma unroll
            for (int u = 0; u < 4; u++) s[i][u] = 0.f;

#pragma unroll
        for (int kk = 0; kk < 8; kk++) {
            uint32_t aq[4];
            ldsm_x4(aq, smem_u32(Qs + (wm + l15) * 136 + kk * 16 + lhi));
#pragma unroll
            for (int nt = 0; nt < 16; nt++) {
                uint32_t bk[2];
                bk[0] = *(const uint32_t*)(kb + (nt * 8 + fr) * 136 + kk * 16 + 2 * fc);
                bk[1] = *(const uint32_t*)(kb + (nt * 8 + fr) * 136 + kk * 16 + 2 * fc + 8);
                mma_f16(s[nt], aq, bk);
            }
        }

        if (t == qb) {
            int r0 = wm + fr, r1 = r0 + 8;
#pragma unroll
            for (int nt = 0; nt < 16; nt++) {
                int c0 = nt * 8 + 2 * fc;
                if (c0 > r0) s[nt][0] = -1e30f;
                if (c0 + 1 > r0) s[nt][1] = -1e30f;
                if (c0 > r1) s[nt][2] = -1e30f;
                if (c0 + 1 > r1) s[nt][3] = -1e30f;
            }
        }

        float mx0 = -1e30f, mx1 = -1e30f;
#pragma unroll
        for (int nt = 0; nt < 16; nt++) {
            mx0 = fmaxf(mx0, fmaxf(s[nt][0], s[nt][1]));
            mx1 = fmaxf(mx1, fmaxf(s[nt][2], s[nt][3]));
        }
        mx0 = fmaxf(mx0, __shfl_xor_sync(0xffffffffu, mx0, 1));
        mx0 = fmaxf(mx0, __shfl_xor_sync(0xffffffffu, mx0, 2));
        mx1 = fmaxf(mx1, __shfl_xor_sync(0xffffffffu, mx1, 1));
        mx1 = fmaxf(mx1, __shfl_xor_sync(0xffffffffu, mx1, 2));

        float mn0 = fmaxf(m0, mx0), mn1 = fmaxf(m1, mx1);
        float rs0 = exp2f((m0 - mn0) * FSC), rs1 = exp2f((m1 - mn1) * FSC);
        m0 = mn0; m1 = mn1;

        float sm0 = 0.f, sm1 = 0.f;
#pragma unroll
        for (int nt = 0; nt < 16; nt++) {
            s[nt][0] = exp2f((s[nt][0] - m0) * FSC);
            s[nt][1] = exp2f((s[nt][1] - m0) * FSC);
            s[nt][2] = exp2f((s[nt][2] - m1) * FSC);
            s[nt][3] = exp2f((s[nt][3] - m1) * FSC);
            sm0 += s[nt][0] + s[nt][1];
            sm1 += s[nt][2] + s[nt][3];
        }
        sm0 += __shfl_xor_sync(0xffffffffu, sm0, 1);
        sm0 += __shfl_xor_sync(0xffffffffu, sm0, 2);
        sm1 += __shfl_xor_sync(0xffffffffu, sm1, 1);
        sm1 += __shfl_xor_sync(0xffffffffu, sm1, 2);
        l0 = l0 * rs0 + sm0;
        l1 = l1 * rs1 + sm1;
#pragma unroll
        for (int nt = 0; nt < 16; nt++) {
            oacc[nt][0] *= rs0; oacc[nt][1] *= rs0;
            oacc[nt][2] *= rs1; oacc[nt][3] *= rs1;
        }

#pragma unroll
        for (int kc = 0; kc < 8; kc++) {
            uint32_t pa[4];
            pa[0] = pack_h2(s[2 * kc][0], s[2 * kc][1]);
            pa[1] = pack_h2(s[2 * kc][2], s[2 * kc][3]);
            pa[2] = pack_h2(s[2 * kc + 1][0], s[2 * kc + 1][1]);
            pa[3] = pack_h2(s[2 * kc + 1][2], s[2 * kc + 1][3]);
#pragma unroll
            for (int p = 0; p < 8; p++) {
                uint32_t tmp[4];
                ldsm_x4_t(tmp, smem_u32(vb + (kc * 16 + l15) * 136 + p * 16 + lhi));
                mma_f16(oacc[2 * p], pa, tmp);
                mma_f16(oacc[2 * p + 1], pa, tmp + 2);
            }
        }
        __syncthreads();
    }

    float inv0 = 1.f / l0, inv1 = 1.f / l1;
    __half* og = O + (long long)(qb * 128) * H + h * D;
    int r0 = wm + fr, r1 = r0 + 8;
#pragma unroll
    for (int nt = 0; nt < 16; nt++) {
        int col = nt * 8 + 2 * fc;
        *(half2*)(og + (long long)r0 * H + col) =
            __floats2half2_rn(oacc[nt][0] * inv0, oacc[nt][1] * inv0);
        *(half2*)(og + (long long)r1 * H + col) =
            __floats2half2_rn(oacc[nt][2] * inv1, oacc[nt][3] * inv1);
    }
}
#define FLASH_SMEM ((128 + 256 + 256) * 136 * 2)

// ---------------- fp32 -> fp16 ----------------
__global__ void f2h_kernel(const float* __restrict__ in, __half* __restrict__ out, long long n) {
    long long i = (long long)blockIdx.x * 1024 + threadIdx.x * 4;
    for (; i + 3 < n; i += (long long)gridDim.x * 1024) {
        float4 v = *(const float4*)&in[i];
        *(half2*)&out[i] = __floats2half2_rn(v.x, v.y);
        *(half2*)&out[i + 2] = __floats2half2_rn(v.z, v.w);
    }
}

// ---------------- pack 3 bias vectors ----------------
__global__ void bcopy_kernel(const float* a, const float* b, const float* c, float* o) {
    int i = blockIdx.x * 1024 + threadIdx.x;
    const float* src[3] = {a, b, c};
    o[i] = src[i >> 11][i & 2047];
}

// ---------------- RMSNorm ----------------
__global__ void rmsnorm_kernel(const float* __restrict__ x, const float* __restrict__ w,
                               __half* __restrict__ oh, float* __restrict__ of,
                               int* __restrict__ zcnt) {
    int s = blockIdx.x;
    if (zcnt && s == 0 && threadIdx.x < NE) zcnt[threadIdx.x] = 0;
    const float* xr = x + (long long)s * H;
    int tid = threadIdx.x;
    float ss = 0.f;
    for (int i = tid; i < H; i += 256) { float v = xr[i]; ss += v * v; }
    __shared__ float sh[8];
#pragma unroll
    for (int off = 16; off; off >>= 1) ss += __shfl_xor_sync(0xffffffffu, ss, off);
    if ((tid & 31) == 0) sh[tid >> 5] = ss;
    __syncthreads();
    ss = sh[tid & 7];
#pragma unroll
    for (int off = 4; off; off >>= 1) ss += __shfl_xor_sync(0xffffffffu, ss, off);
    float inv = rsqrtf(ss / (float)H + 1e-6f);
    for (int i = tid; i < H; i += 256) {
        float v = w[i] * xr[i] * inv;
        oh[(long long)s * H + i] = __float2half_rn(v);
        if (of) of[(long long)s * H + i] = v;
    }
}

// ---------------- router + top-k compaction ----------------
__global__ void router_kernel(const float* __restrict__ h2, const float* __restrict__ gw,
                              const float* __restrict__ sgate, float* __restrict__ rl,
                              float* __restrict__ sgl, int* __restrict__ cnt,
                              int* __restrict__ glist, int* __restrict__ slot,
                              float* __restrict__ wsl) {
    int s = blockIdx.x;
    int tid = threadIdx.x;
    const float* hr = h2 + (long long)s * H;
    float acc[9];
#pragma unroll
    for (int j = 0; j < 9; j++) acc[j] = 0.f;
    for (int i = tid; i < H; i += 256) {
        float hv = hr[i];
        const float* gr = gw + (long long)i * NE;
#pragma unroll
        for (int e = 0; e < NE; e++) acc[e] += hv * gr[e];
        acc[8] += hv * sgate[i];
    }
    __shared__ float sh[8][9];
    int warp = tid >> 5, lane = tid & 31;
#pragma unroll
    for (int j = 0; j < 9; j++) {
        float v = acc[j];
#pragma unroll
        for (int o = 16; o; o >>= 1) v += __shfl_xor_sync(0xffffffffu, v, o);
        if (lane == 0) sh[warp][j] = v;
    }
    __syncthreads();
    if (tid == 0) {
        float t[9];
#pragma unroll
        for (int j = 0; j < 9; j++) {
            float v = 0.f;
            for (int wi = 0; wi < 8; wi++) v += sh[wi][j];
            t[j] = v;
        }
        float mx = t[0];
        for (int e = 1; e < NE; e++) mx = fmaxf(mx, t[e]);
        float p[NE], sum = 0.f;
        for (int e = 0; e < NE; e++) { p[e] = expf(t[e] - mx); sum += p[e]; }
        for (int e = 0; e < NE; e++) p[e] /= sum;
        for (int kI = 0; kI < TOPK; kI++) {
            int bi = 0;
            float bv = p[0];
            for (int e = 1; e < NE; e++)
                if (p[e] > bv) { bv = p[e]; bi = e; }
            int pos = atomicAdd(&cnt[bi], 1);
            glist[bi * S + pos] = s;
            slot[s * TOPK + kI] = bi * S + pos;
            wsl[bi * S + pos] = bv;
            p[bi] = -1.f;
        }
        for (int e = 0; e < NE; e++) rl[s * NE + e] = t[e];
        sgl[s] = t[8];
    }
}

// ---------------- final combine ----------------
__global__ void final_kernel(const float* __restrict__ x2, const __half* __restrict__ eoh,
                             const int* __restrict__ slot,
                             const float* __restrict__ sm, const float* __restrict__ sgl,
                             float* __restrict__ out) {
    int i = blockIdx.x * 256 + threadIdx.x;
    int s = i >> 11, c = i & 2047;
    float mo = 0.f;
#pragma unroll
    for (int kI = 0; kI < TOPK; kI++)
        mo += __half2float(eoh[(long long)slot[s * TOPK + kI] * H + c]);
    float gg = 1.f / (1.f + expf(-sgl[s]));
    out[i] = x2[i] + mo + gg * sm[i];
}

// ---------------- host ----------------
extern "C" void kernel_launch(void* const* d_in, const int* in_sizes, int n_in,
                              void* d_out, int out_size) {
    const float* x = (const float*)d_in[0];
    const float* ln1 = (const float*)d_in[1];
    const float* ln2 = (const float*)d_in[2];
    const float* wq = (const float*)d_in[3];
    const float* bq = (const float*)d_in[4];
    const float* wk = (const float*)d_in[5];
    const float* bk = (const float*)d_in[6];
    const float* wv = (const float*)d_in[7];
    const float* bv = (const float*)d_in[8];
    const float* wo = (const float*)d_in[9];
    const float* gw = (const float*)d_in[10];
    const float* eg = (const float*)d_in[11];
    const float* eu = (const float*)d_in[12];
    const float* ed = (const float*)d_in[13];
    const float* sg = (const float*)d_in[14];
    const float* su = (const float*)d_in[15];
    const float* sd = (const float*)d_in[16];
    const float* sgate = (const float*)d_in[17];
    float* out = (float*)d_out;

    float *x2, *h2f, *sm, *sgl, *rls, *wsl, *bqkv;
    int *cnt, *glist, *slot;
    __half *h1h, *qkvh, *ath, *h2h, *uhh, *eoh, *ssh;
    __half *wqkvh, *woh, *egh, *euh, *edh, *sgw, *suw, *sdw;
    cudaGetSymbolAddress((void**)&x2, g_x2);
    cudaGetSymbolAddress((void**)&h2f, g_h2f);
    cudaGetSymbolAddress((void**)&sm, g_sm);
    cudaGetSymbolAddress((void**)&sgl, g_sgl);
    cudaGetSymbolAddress((void**)&rls, g_rl);
    cudaGetSymbolAddress((void**)&wsl, g_wsl);
    cudaGetSymbolAddress((void**)&bqkv, g_bqkv);
    cudaGetSymbolAddress((void**)&cnt, g_cnt);
    cudaGetSymbolAddress((void**)&glist, g_glist);
    cudaGetSymbolAddress((void**)&slot, g_slot);
    cudaGetSymbolAddress((void**)&h1h, g_h1h);
    cudaGetSymbolAddress((void**)&qkvh, g_qkvh);
    cudaGetSymbolAddress((void**)&ath, g_ath);
    cudaGetSymbolAddress((void**)&h2h, g_h2h);
    cudaGetSymbolAddress((void**)&uhh, g_uhh);
    cudaGetSymbolAddress((void**)&eoh, g_eoh);
    cudaGetSymbolAddress((void**)&ssh, g_ssh);
    cudaGetSymbolAddress((void**)&wqkvh, g_wqkvh);
    cudaGetSymbolAddress((void**)&woh, g_woh);
    cudaGetSymbolAddress((void**)&egh, g_egh);
    cudaGetSymbolAddress((void**)&euh, g_euh);
    cudaGetSymbolAddress((void**)&edh, g_edh);
    cudaGetSymbolAddress((void**)&sgw, g_sgw);
    cudaGetSymbolAddress((void**)&suw, g_suw);
    cudaGetSymbolAddress((void**)&sdw, g_sdw);

    __half* qh = qkvh;
    __half* kh = qkvh + (long long)S * H;
    __half* vh = qkvh + (long long)2 * S * H;

    cudaFuncSetAttribute(flash_kernel, cudaFuncAttributeMaxDynamicSharedMemorySize, FLASH_SMEM);
    cudaFuncSetAttribute(hgemm<1, true, 0, true, false>, cudaFuncAttributeMaxDynamicSharedMemorySize, SMEM_BASE);
    cudaFuncSetAttribute(hgemm<2, false, 0, false, false>, cudaFuncAttributeMaxDynamicSharedMemorySize, SMEM_BASE);
    cudaFuncSetAttribute(hgemm<0, true, 1, false, true>, cudaFuncAttributeMaxDynamicSharedMemorySize, SMEM_DUAL);
    cudaFuncSetAttribute(hgemm<4, true, 2, false, false>, cudaFuncAttributeMaxDynamicSharedMemorySize, SMEM_BASE);
    cudaFuncSetAttribute(hgemm<0, true, 0, false, true>, cudaFuncAttributeMaxDynamicSharedMemorySize, SMEM_DUAL);
    cudaFuncSetAttribute(hgemm<0, false, 0, false, false>, cudaFuncAttributeMaxDynamicSharedMemorySize, SMEM_BASE);

    static cudaStream_t s2 = 0, s3 = 0;
    static cudaEvent_t evFork = 0, evW0 = 0, evW = 0, evH2 = 0, evSh = 0, evN = 0;
    if (!s2) {
        cudaStreamCreateWithFlags(&s2, cudaStreamNonBlocking);
        cudaStreamCreateWithFlags(&s3, cudaStreamNonBlocking);
        cudaEventCreateWithFlags(&evFork, cudaEventDisableTiming);
        cudaEventCreateWithFlags(&evW0, cudaEventDisableTiming);
        cudaEventCreateWithFlags(&evW, cudaEventDisableTiming);
        cudaEventCreateWithFlags(&evH2, cudaEventDisableTiming);
        cudaEventCreateWithFlags(&evSh, cudaEventDisableTiming);
        cudaEventCreateWithFlags(&evN, cudaEventDisableTiming);
    }

    float* rl_dst = (out_size >= S * H + S * NE) ? (out + (size_t)S * H) : rls;

    // ---- fork conversion stream (QKV weights first) ----
    cudaEventRecord(evFork, 0);
    cudaStreamWaitEvent(s2, evFork, 0);
    bcopy_kernel<<<6, 1024, 0, s2>>>(bq, bk, bv, bqkv);
    f2h_kernel<<<2048, 256, 0, s2>>>(wq, wqkvh, (long long)H * H);
    f2h_kernel<<<2048, 256, 0, s2>>>(wk, wqkvh + (long long)H * H, (long long)H * H);
    f2h_kernel<<<2048, 256, 0, s2>>>(wv, wqkvh + (long long)2 * H * H, (long long)H * H);
    cudaEventRecord(evW0, s2);
    f2h_kernel<<<2048, 256, 0, s2>>>(wo, woh, (long long)H * H);
    f2h_kernel<<<4096, 256, 0, s2>>>(eg, egh, (long long)NE * H * IE);
    f2h_kernel<<<4096, 256, 0, s2>>>(eu, euh, (long long)NE * H * IE);
    f2h_kernel<<<4096, 256, 0, s2>>>(sg, sgw, (long long)H * IS);
    f2h_kernel<<<4096, 256, 0, s2>>>(su, suw, (long long)H * IS);
    f2h_kernel<<<4096, 256, 0, s2>>>(ed, edh, (long long)NE * IE * H);
    f2h_kernel<<<4096, 256, 0, s2>>>(sd, sdw, (long long)IS * H);
    cudaEventRecord(evW, s2);

    // ---- rmsnorm1 on s3 concurrent with f2h ----
    cudaStreamWaitEvent(s3, evFork, 0);
    rmsnorm_kernel<<<S, 256, 0, s3>>>(x, ln1, h1h, (float*)0, (int*)0);
    cudaEventRecord(evN, s3);

    // ---- main stream: attention path ----
    cudaStreamWaitEvent(0, evW0, 0);
    cudaStreamWaitEvent(0, evN, 0);
    hgemm<1, true, 0, true, false><<<dim3(16, 16, 3), 256, SMEM_BASE>>>(
        h1h, wqkvh, (const __half*)0, qkvh, bqkv, 0, 0,
        H, H, H, H, 0LL, (long long)H * H, (long long)S * H);
    flash_kernel<<<dim3(16, NH), 256, FLASH_SMEM>>>(qh, kh, vh, ath);
    hgemm<2, false, 0, false, false><<<dim3(16, 16, 1), 256, SMEM_BASE>>>(
        ath, woh, (const __half*)0, x2, x, 0, 0, H, H, H, H, 0, 0, 0);
    rmsnorm_kernel<<<S, 256>>>(x2, ln2, h2h, h2f, cnt);
    cudaEventRecord(evH2, 0);
    router_kernel<<<S, 256>>>(h2f, gw, sgate, rl_dst, sgl, cnt, glist, slot, wsl);

    // ---- stream s3: shared MLP branch (dual gate+up, then down) ----
    cudaStreamWaitEvent(s3, evH2, 0);
    cudaStreamWaitEvent(s3, evW, 0);
    hgemm<0, true, 0, false, true><<<dim3(IS / 128, 16, 1), 256, SMEM_DUAL, s3>>>(
        h2h, sgw, suw, ssh, (const float*)0, 0, 0, H, H, IS, IS, 0, 0, 0);
    hgemm<0, false, 0, false, false><<<dim3(16, 16, 1), 256, SMEM_BASE, s3>>>(
        ssh, sdw, (const __half*)0, sm, (const float*)0, 0, 0, IS, IS, H, H, 0, 0, 0);
    cudaEventRecord(evSh, s3);

    // ---- main stream: sparse MoE branch (dual gate+up, then weighted down) ----
    cudaStreamWaitEvent(0, evW, 0);
    hgemm<0, true, 1, false, true><<<dim3(IE / 128, 16, NE), 256, SMEM_DUAL>>>(
        h2h, egh, euh, uhh, (const float*)0, glist, cnt,
        H, H, IE, IE, 0LL, (long long)H * IE, (long long)S * IE);
    hgemm<4, true, 2, false, false><<<dim3(16, 16, NE), 256, SMEM_BASE>>>(
        uhh, edh, (const __half*)0, eoh, wsl, (const int*)0, cnt,
        IE, IE, H, H, (long long)S * IE, (long long)IE * H, (long long)S * H);

    // ---- join + combine ----
    cudaStreamWaitEvent(0, evSh, 0);
    final_kernel<<<(S * H) / 256, 256>>>(x2, eoh, slot, sm, sgl, out);
}